// round 12
// baseline (speedup 1.0000x reference)
#include <cuda_runtime.h>
#include <cuda_bf16.h>
#include <cstdint>

#define BB   2
#define NP   2048
#define KNB  16
#define EPSI 1e-5f
#define M4   (BB*NP)        // 4096
#define M8   (2*BB*NP)      // 8192

typedef __nv_bfloat16 bf;

// ======================= helpers =======================
__device__ __forceinline__ void split2(float x, bf& h, bf& l){
    h = __float2bfloat16(x);
    l = __float2bfloat16(x - __bfloat162float(h));
}
__device__ __forceinline__ uint32_t packbf(bf a, bf b){
    return ((uint32_t)__bfloat16_as_ushort(b) << 16) | (uint32_t)__bfloat16_as_ushort(a);
}
__device__ __forceinline__ uint32_t packsplit(float a, float b, uint32_t& lo){
    bf ha, la, hb, lb;
    split2(a, ha, la); split2(b, hb, lb);
    lo = packbf(la, lb);
    return packbf(ha, hb);
}

#define MMA16816(d, a, b) \
    asm volatile("mma.sync.aligned.m16n8k16.row.col.f32.bf16.bf16.f32 " \
        "{%0,%1,%2,%3}, {%4,%5,%6,%7}, {%8,%9}, {%0,%1,%2,%3};" \
        : "+f"((d)[0]), "+f"((d)[1]), "+f"((d)[2]), "+f"((d)[3]) \
        : "r"((a)[0]), "r"((a)[1]), "r"((a)[2]), "r"((a)[3]), \
          "r"((b)[0]), "r"((b)[1]))

#define LDSM4(r0, r1, r2, r3, a) \
    asm volatile("ldmatrix.sync.aligned.m8n8.x4.shared.b16 {%0,%1,%2,%3}, [%4];" \
        : "=r"(r0), "=r"(r1), "=r"(r2), "=r"(r3) : "r"(a))

#define CPA16(dst, src) \
    asm volatile("cp.async.cg.shared.global [%0], [%1], 16;" :: "r"(dst), "l"(src))
#define CP_COMMIT() asm volatile("cp.async.commit_group;" ::: "memory")
#define CP_WAIT1()  asm volatile("cp.async.wait_group 1;" ::: "memory")
#define CP_WAIT0()  asm volatile("cp.async.wait_group 0;" ::: "memory")

// ======================= device scratch =======================
__device__ __align__(16) float d_FE [M8*256];
__device__ int   d_KN [M8*KNB];
__device__ __align__(16) float d_PQ [M8*1024];
__device__ __align__(16) float d_MX [M8*512];
__device__ float d_STT[2*4*1024];
__device__ float d_BIAS[2*3*256];
__device__ __align__(16) bf d_AH [M8*1024];
__device__ __align__(16) bf d_AL [M8*1024];
__device__ __align__(16) bf d_W1H[2*512*256],  d_W1L[2*512*256];
__device__ __align__(16) bf d_W2H[2*1024*256], d_W2L[2*1024*256];
__device__ __align__(16) bf d_W3H[2*256*1024], d_W3L[2*256*1024];
__device__ __align__(16) bf d_WQH[2*256*256],  d_WQL[2*256*256];
__device__ __align__(16) bf d_WKVH[2*512*256], d_WKVL[2*512*256];
__device__ __align__(16) bf d_WOH[2*256*256],  d_WOL[2*256*256];
__device__ __align__(16) bf d_WM1H[2*512*512], d_WM1L[2*512*512];
__device__ __align__(16) bf d_WM2H[2*256*512], d_WM2L[2*256*512];
__device__ __align__(16) bf d_QHH[M4*256], d_QHL[M4*256];
__device__ __align__(16) bf d_KVH[M4*512], d_KVL[M4*512];
__device__ __align__(16) bf d_VTH[M4*256], d_VTL[M4*256];
__device__ __align__(16) bf d_OHH[M4*256], d_OHL[M4*256];

// ======================= transpose (fp32) =======================
__global__ void k_transpose(const float* __restrict__ in, float* __restrict__ out,
                            int R, int Cc)
{
    __shared__ float t[32][33];
    int b  = blockIdx.z;
    const float* ip = in  + (long)b * R * Cc;
    float*       op = out + (long)b * R * Cc;
    int c0 = blockIdx.x * 32, r0 = blockIdx.y * 32;
    for (int i = threadIdx.y; i < 32; i += 8)
        t[i][threadIdx.x] = ip[(long)(r0 + i) * Cc + c0 + threadIdx.x];
    __syncthreads();
    for (int i = threadIdx.y; i < 32; i += 8)
        op[(long)(c0 + i) * R + r0 + threadIdx.x] = t[threadIdx.x][i];
}

// ======================= kNN =======================
__global__ void __launch_bounds__(256) k_knn(const float* __restrict__ coords,
                                             int* __restrict__ knn)
{
    __shared__ float sx[NP], sy[NP], sz[NP], sd[NP];
    __shared__ float wv[8];
    __shared__ int   wi[8];
    int b = blockIdx.x / NP;
    int n = blockIdx.x % NP;
    const float* cb = coords + (long)b * 3 * NP;
    for (int j = threadIdx.x; j < NP; j += 256) {
        sx[j] = cb[j]; sy[j] = cb[NP + j]; sz[j] = cb[2 * NP + j];
    }
    __syncthreads();
    float xn = sx[n], yn = sy[n], zn = sz[n];
    float sqn = xn*xn + yn*yn + zn*zn;
    for (int j = threadIdx.x; j < NP; j += 256) {
        float x = sx[j], y = sy[j], z = sz[j];
        float d = sqn + (x*x + y*y + z*z) - 2.f * (xn*x + yn*y + zn*z);
        sd[j] = (j == n) ? 3.4e38f : d;
    }
    __syncthreads();
    int lane = threadIdx.x & 31, warp = threadIdx.x >> 5;
    for (int r = 0; r < KNB; r++) {
        float best = 3.0e38f; int bi = NP;
        for (int j = threadIdx.x; j < NP; j += 256) {
            float v = sd[j];
            if (v < best) { best = v; bi = j; }
        }
        #pragma unroll
        for (int off = 16; off; off >>= 1) {
            float ov = __shfl_down_sync(0xffffffffu, best, off);
            int   oi = __shfl_down_sync(0xffffffffu, bi,   off);
            if (ov < best || (ov == best && oi < bi)) { best = ov; bi = oi; }
        }
        if (lane == 0) { wv[warp] = best; wi[warp] = bi; }
        __syncthreads();
        if (threadIdx.x == 0) {
            float fb = wv[0]; int fi = wi[0];
            for (int w = 1; w < 8; w++)
                if (wv[w] < fb || (wv[w] == fb && wi[w] < fi)) { fb = wv[w]; fi = wi[w]; }
            knn[((long)b * NP + n) * KNB + r] = fi;
            sd[fi] = 3.4e38f;
        }
        __syncthreads();
    }
}

// ======================= HMMA GEMM (cp.async 2-stage + ldmatrix) ==============
template <int EPI, int MR, int NR>
__global__ void __launch_bounds__(256) mma_gemm(
    const bf* __restrict__ AH, const bf* __restrict__ AL, long lda,
    const bf* __restrict__ WH, const bf* __restrict__ WL, long ldw,
    const float* __restrict__ bias, const float* __restrict__ bias2,
    float* __restrict__ C, bf* __restrict__ OH, bf* __restrict__ OL,
    int ldc, int K)
{
    constexpr int MT    = MR / 32;
    constexpr int NW    = NR / 4;
    constexpr int NT    = NW / 8;
    constexpr int NBL   = NW / 16;
    constexpr int ATILE = MR * 80;
    constexpr int WTILE = NR * 80;
    constexpr int STAGE = 2 * (ATILE + WTILE);

    extern __shared__ __align__(16) char smem[];
    uint32_t sbase = (uint32_t)__cvta_generic_to_shared(smem);

    int tid = threadIdx.x, wid = tid >> 5, lane = tid & 31;
    int g = lane >> 2, tg = lane & 3;
    int wm = (wid >> 2) * (MR / 2);
    int wn = (wid & 3) * NW;
    int lr = tid >> 2;
    int lq = tid & 3;

    uint32_t aoff = (uint32_t)((wm + (lane & 7) + ((lane >> 3) & 1) * 8) * 80 + (lane >> 4) * 16);
    uint32_t boff = (uint32_t)((wn + (lane >> 4) * 8 + (lane & 7)) * 80 + ((lane >> 3) & 1) * 16);

    long m0 = (long)blockIdx.y * MR;
    int  n0 = blockIdx.x * NR;
    const bf* pAH = AH + m0 * lda;
    const bf* pAL = AL + m0 * lda;
    const bf* pWH = WH + (long)n0 * ldw;
    const bf* pWL = WL + (long)n0 * ldw;

    float acc[MT][NT][4];
    #pragma unroll
    for (int mt = 0; mt < MT; mt++)
        #pragma unroll
        for (int nt = 0; nt < NT; nt++)
            #pragma unroll
            for (int q = 0; q < 4; q++) acc[mt][nt][q] = 0.f;

    int nch = K >> 5;

    {
        uint32_t st = sbase;
        #pragma unroll
        for (int it = 0; it < MR / 64; it++) {
            int r = lr + it * 64;
            uint32_t d = st + r * 80 + lq * 16;
            CPA16(d,         pAH + (long)r * lda + lq * 8);
            CPA16(d + ATILE, pAL + (long)r * lda + lq * 8);
        }
        #pragma unroll
        for (int it = 0; it < NR / 64; it++) {
            int r = lr + it * 64;
            uint32_t d = st + 2 * ATILE + r * 80 + lq * 16;
            CPA16(d,         pWH + (long)r * ldw + lq * 8);
            CPA16(d + WTILE, pWL + (long)r * ldw + lq * 8);
        }
        CP_COMMIT();
    }

    for (int c = 0; c < nch; c++) {
        if (c + 1 < nch) {
            long k0 = (long)(c + 1) << 5;
            uint32_t st = sbase + ((c + 1) & 1) * STAGE;
            #pragma unroll
            for (int it = 0; it < MR / 64; it++) {
                int r = lr + it * 64;
                uint32_t d = st + r * 80 + lq * 16;
                CPA16(d,         pAH + (long)r * lda + k0 + lq * 8);
                CPA16(d + ATILE, pAL + (long)r * lda + k0 + lq * 8);
            }
            #pragma unroll
            for (int it = 0; it < NR / 64; it++) {
                int r = lr + it * 64;
                uint32_t d = st + 2 * ATILE + r * 80 + lq * 16;
                CPA16(d,         pWH + (long)r * ldw + k0 + lq * 8);
                CPA16(d + WTILE, pWL + (long)r * ldw + k0 + lq * 8);
            }
            CP_COMMIT();
            CP_WAIT1();
        } else {
            CP_WAIT0();
        }
        __syncthreads();

        uint32_t stA = sbase + (c & 1) * STAGE;
        uint32_t aA = stA + aoff;
        uint32_t bA = stA + 2 * ATILE + boff;

        #pragma unroll
        for (int ks = 0; ks < 2; ks++) {
            int kbB = ks * 32;
            uint32_t ah[MT][4], al[MT][4];
            #pragma unroll
            for (int mt = 0; mt < MT; mt++) {
                uint32_t a0 = aA + mt * (16 * 80) + kbB;
                LDSM4(ah[mt][0], ah[mt][1], ah[mt][2], ah[mt][3], a0);
                LDSM4(al[mt][0], al[mt][1], al[mt][2], al[mt][3], a0 + ATILE);
            }
            uint32_t bh[NT][2], bl[NT][2];
            #pragma unroll
            for (int np2 = 0; np2 < NBL; np2++) {
                uint32_t b0 = bA + np2 * (16 * 80) + kbB;
                LDSM4(bh[np2*2][0], bh[np2*2][1], bh[np2*2+1][0], bh[np2*2+1][1], b0);
                LDSM4(bl[np2*2][0], bl[np2*2][1], bl[np2*2+1][0], bl[np2*2+1][1], b0 + WTILE);
            }
            #pragma unroll
            for (int mt = 0; mt < MT; mt++)
                #pragma unroll
                for (int nt = 0; nt < NT; nt++) {
                    MMA16816(acc[mt][nt], ah[mt], bh[nt]);
                    MMA16816(acc[mt][nt], ah[mt], bl[nt]);
                    MMA16816(acc[mt][nt], al[mt], bh[nt]);
                }
        }
        __syncthreads();
    }

    #pragma unroll
    for (int mt = 0; mt < MT; mt++) {
        long row = m0 + wm + mt * 16 + g;
        #pragma unroll
        for (int nt = 0; nt < NT; nt++) {
            int col = n0 + wn + nt * 8 + tg * 2;
            float b0 = 0.f, b1 = 0.f;
            if (bias) {
                const float* bp = (bias2 && col >= 256) ? (bias2 - 256) : bias;
                b0 = __ldg(&bp[col]); b1 = __ldg(&bp[col + 1]);
            }
            float v0 = acc[mt][nt][0] + b0;
            float v1 = acc[mt][nt][1] + b1;
            float v2 = acc[mt][nt][2] + b0;
            float v3 = acc[mt][nt][3] + b1;
            if (EPI == 0) {
                *(float2*)(C + row * (long)ldc + col)       = make_float2(v0, v1);
                *(float2*)(C + (row + 8) * (long)ldc + col) = make_float2(v2, v3);
            } else {
                uint32_t lo0, lo1;
                uint32_t hi0 = packsplit(v0, v1, lo0);
                uint32_t hi1 = packsplit(v2, v3, lo1);
                *(uint32_t*)(OH + row * (long)ldc + col)       = hi0;
                *(uint32_t*)(OL + row * (long)ldc + col)       = lo0;
                *(uint32_t*)(OH + (row + 8) * (long)ldc + col) = hi1;
                *(uint32_t*)(OL + (row + 8) * (long)ldc + col) = lo1;
            }
        }
    }
}

#define SM_128_128 (2 * 2 * (128*80 + 128*80))
#define SM_64_128  (2 * 2 * (64*80  + 128*80))
#define SM_64_64   (2 * 2 * (64*80  + 64*80))

// ======================= fused flash attention (64-row q-blocks) ==============
// 4 warps / 128 threads, grid (32, 8) = 256 CTAs.
#define FQ_B (64*144)
#define FK_B (64*144)
#define FA_SMEM (2*FQ_B + 4*FK_B)   // 55296
__global__ void __launch_bounds__(128) k_flash(
    const bf* __restrict__ QH, const bf* __restrict__ QL,
    const bf* __restrict__ KVH, const bf* __restrict__ KVL,
    const bf* __restrict__ VH, const bf* __restrict__ VL,
    bf* __restrict__ OH, bf* __restrict__ OL)
{
    extern __shared__ __align__(16) char smem[];
    char* sQh = smem;
    char* sQl = smem + FQ_B;
    char* sKh = smem + 2 * FQ_B;
    char* sVh = sKh + 2 * FK_B;
    uint32_t sbase = (uint32_t)__cvta_generic_to_shared(smem);

    int tid = threadIdx.x, wid = tid >> 5, lane = tid & 31;
    int g = lane >> 2, tg = lane & 3;
    int z = blockIdx.y;
    int b = z >> 2, h = z & 3;
    long q0 = (long)blockIdx.x * 64;
    int wm = wid * 16;

    uint32_t aoff = (uint32_t)((wm + (lane & 7) + ((lane >> 3) & 1) * 8) * 144 + (lane >> 4) * 16);
    uint32_t boff = (uint32_t)(((lane >> 4) * 8 + (lane & 7)) * 144 + ((lane >> 3) & 1) * 16);
    uint32_t qA = sbase + aoff;
    uint32_t kA = sbase + 2 * FQ_B + boff;
    uint32_t vA = kA + 2 * FK_B;

    const bf* pQH = QH + ((long)b * NP + q0) * 256 + h * 64;
    const bf* pQL = QL + ((long)b * NP + q0) * 256 + h * 64;

    #pragma unroll
    for (int it = 0; it < 4; it++) {
        int i = tid + it * 128;
        int r = i >> 3, q = i & 7;
        *(uint4*)(sQh + r * 144 + q * 16) = *(const uint4*)(pQH + (long)r * 256 + q * 8);
        *(uint4*)(sQl + r * 144 + q * 16) = *(const uint4*)(pQL + (long)r * 256 + q * 8);
    }

    float m0 = -3.4e38f, m1 = -3.4e38f, l0 = 0.f, l1 = 0.f;
    float acc[8][4];
    #pragma unroll
    for (int nt = 0; nt < 8; nt++)
        #pragma unroll
        for (int q = 0; q < 4; q++) acc[nt][q] = 0.f;

    for (int c = 0; c < NP / 64; c++) {
        const bf* pKH = KVH + ((long)b * NP + c * 64) * 512 + h * 64;
        const bf* pKL = KVL + ((long)b * NP + c * 64) * 512 + h * 64;
        const bf* pVH = VH + (long)z * 64 * NP + c * 64;
        const bf* pVL = VL + (long)z * 64 * NP + c * 64;
        #pragma unroll
        for (int it = 0; it < 4; it++) {
            int i = tid + it * 128;
            int r = i >> 3, q = i & 7;
            *(uint4*)(sKh + r * 144 + q * 16)        = *(const uint4*)(pKH + (long)r * 512 + q * 8);
            *(uint4*)(sKh + FK_B + r * 144 + q * 16) = *(const uint4*)(pKL + (long)r * 512 + q * 8);
            *(uint4*)(sVh + r * 144 + q * 16)        = *(const uint4*)(pVH + (long)r * NP + q * 8);
            *(uint4*)(sVh + FK_B + r * 144 + q * 16) = *(const uint4*)(pVL + (long)r * NP + q * 8);
        }
        __syncthreads();

        float sacc[8][4];
        #pragma unroll
        for (int nt = 0; nt < 8; nt++)
            #pragma unroll
            for (int q = 0; q < 4; q++) sacc[nt][q] = 0.f;
        #pragma unroll
        for (int kk = 0; kk < 4; kk++) {
            int kbB = kk * 32;
            uint32_t aqh[4], aql[4];
            LDSM4(aqh[0], aqh[1], aqh[2], aqh[3], qA + kbB);
            LDSM4(aql[0], aql[1], aql[2], aql[3], qA + FQ_B + kbB);
            #pragma unroll
            for (int np2 = 0; np2 < 4; np2++) {
                uint32_t bh[2][2], bl[2][2];
                uint32_t b0 = kA + np2 * (16 * 144) + kbB;
                LDSM4(bh[0][0], bh[0][1], bh[1][0], bh[1][1], b0);
                LDSM4(bl[0][0], bl[0][1], bl[1][0], bl[1][1], b0 + FK_B);
                #pragma unroll
                for (int j = 0; j < 2; j++) {
                    MMA16816(sacc[np2*2+j], aqh, bh[j]);
                    MMA16816(sacc[np2*2+j], aqh, bl[j]);
                    MMA16816(sacc[np2*2+j], aql, bh[j]);
                }
            }
        }

        float rmax0 = -3.4e38f, rmax1 = -3.4e38f;
        #pragma unroll
        for (int nt = 0; nt < 8; nt++) {
            rmax0 = fmaxf(rmax0, fmaxf(sacc[nt][0], sacc[nt][1]));
            rmax1 = fmaxf(rmax1, fmaxf(sacc[nt][2], sacc[nt][3]));
        }
        rmax0 = fmaxf(rmax0, __shfl_xor_sync(0xffffffffu, rmax0, 1));
        rmax0 = fmaxf(rmax0, __shfl_xor_sync(0xffffffffu, rmax0, 2));
        rmax1 = fmaxf(rmax1, __shfl_xor_sync(0xffffffffu, rmax1, 1));
        rmax1 = fmaxf(rmax1, __shfl_xor_sync(0xffffffffu, rmax1, 2));
        float mn0 = fmaxf(m0, rmax0), mn1 = fmaxf(m1, rmax1);
        float al0 = __expf(m0 - mn0), al1 = __expf(m1 - mn1);
        m0 = mn0; m1 = mn1;

        float rs0 = 0.f, rs1 = 0.f;
        uint32_t pfh[4][4], pfl[4][4];
        #pragma unroll
        for (int nt = 0; nt < 8; nt++) {
            float p0 = __expf(sacc[nt][0] - mn0);
            float p1 = __expf(sacc[nt][1] - mn0);
            float p2 = __expf(sacc[nt][2] - mn1);
            float p3 = __expf(sacc[nt][3] - mn1);
            rs0 += p0 + p1; rs1 += p2 + p3;
            int kk = nt >> 1, base = (nt & 1) * 2;
            pfh[kk][base]     = packsplit(p0, p1, pfl[kk][base]);
            pfh[kk][base + 1] = packsplit(p2, p3, pfl[kk][base + 1]);
        }
        rs0 += __shfl_xor_sync(0xffffffffu, rs0, 1);
        rs0 += __shfl_xor_sync(0xffffffffu, rs0, 2);
        rs1 += __shfl_xor_sync(0xffffffffu, rs1, 1);
        rs1 += __shfl_xor_sync(0xffffffffu, rs1, 2);
        l0 = l0 * al0 + rs0; l1 = l1 * al1 + rs1;
        #pragma unroll
        for (int nt = 0; nt < 8; nt++) {
            acc[nt][0] *= al0; acc[nt][1] *= al0;
            acc[nt][2] *= al1; acc[nt][3] *= al1;
        }

        #pragma unroll
        for (int kk = 0; kk < 4; kk++) {
            int kbB = kk * 32;
            #pragma unroll
            for (int np2 = 0; np2 < 4; np2++) {
                uint32_t bh[2][2], bl[2][2];
                uint32_t b0 = vA + np2 * (16 * 144) + kbB;
                LDSM4(bh[0][0], bh[0][1], bh[1][0], bh[1][1], b0);
                LDSM4(bl[0][0], bl[0][1], bl[1][0], bl[1][1], b0 + FK_B);
                #pragma unroll
                for (int j = 0; j < 2; j++) {
                    MMA16816(acc[np2*2+j], pfh[kk], bh[j]);
                    MMA16816(acc[np2*2+j], pfh[kk], bl[j]);
                    MMA16816(acc[np2*2+j], pfl[kk], bh[j]);
                }
            }
        }
        __syncthreads();
    }

    float inv0 = 1.f / l0, inv1 = 1.f / l1;
    bf* pOH = OH + ((long)b * NP + q0 + wm) * 256 + h * 64;
    bf* pOL = OL + ((long)b * NP + q0 + wm) * 256 + h * 64;
    #pragma unroll
    for (int nt = 0; nt < 8; nt++) {
        int col = nt * 8 + tg * 2;
        uint32_t lo0, lo1;
        uint32_t hi0 = packsplit(acc[nt][0] * inv0, acc[nt][1] * inv0, lo0);
        uint32_t hi1 = packsplit(acc[nt][2] * inv1, acc[nt][3] * inv1, lo1);
        *(uint32_t*)(pOH + (long)g * 256 + col)       = hi0;
        *(uint32_t*)(pOL + (long)g * 256 + col)       = lo0;
        *(uint32_t*)(pOH + (long)(g + 8) * 256 + col) = hi1;
        *(uint32_t*)(pOL + (long)(g + 8) * 256 + col) = lo1;
    }
}

// ======================= fp32 -> bf16 hi/lo =======================
__global__ void k_cvt(const float* __restrict__ src, long ldi, int cols, long total,
                      bf* __restrict__ H, bf* __restrict__ L, long ldo)
{
    long i = ((long)blockIdx.x * blockDim.x + threadIdx.x) * 4;
    if (i >= total) return;
    long r = i / cols; int c = (int)(i - r * cols);
    float4 v = *(const float4*)(src + r * ldi + c);
    uint32_t lo0, lo1;
    uint32_t hi0 = packsplit(v.x, v.y, lo0);
    uint32_t hi1 = packsplit(v.z, v.w, lo1);
    *(uint2*)(H + r * ldo + c) = make_uint2(hi0, hi1);
    *(uint2*)(L + r * ldo + c) = make_uint2(lo0, lo1);
}

__global__ void k_prepw_b(const float* __restrict__ W, bf* __restrict__ H,
                          bf* __restrict__ L, int O, int Ci)
{
    long i = blockIdx.x * (long)blockDim.x + threadIdx.x;
    if (i >= (long)O * Ci) return;
    int o = (int)(i / Ci), c = (int)(i % Ci);
    float a  = W[(long)o * 2 * Ci + c];
    float bq = W[(long)o * 2 * Ci + Ci + c];
    bf h, l;
    split2(a - bq, h, l);
    H[(long)o * Ci + c] = h; L[(long)o * Ci + c] = l;
    split2(bq, h, l);
    H[((long)O + o) * Ci + c] = h; L[((long)O + o) * Ci + c] = l;
}

__global__ void k_prepw_perm(const float* __restrict__ W, float scale,
                             bf* __restrict__ H, bf* __restrict__ L, int roff,
                             const float* __restrict__ bin, float* __restrict__ bout)
{
    int i = blockIdx.x * blockDim.x + threadIdx.x;
    if (i >= 256 * 256) return;
    int o = i >> 8, c = i & 255;
    int op = (o & 3) * 64 + (o >> 2);
    bf h, l;
    split2(W[i] * scale, h, l);
    H[(long)(roff + op) * 256 + c] = h;
    L[(long)(roff + op) * 256 + c] = l;
    if (c == 0) bout[op] = bin[o] * scale;
}

__global__ void k_prepw_colperm(const float* __restrict__ W,
                                bf* __restrict__ H, bf* __restrict__ L)
{
    int i = blockIdx.x * blockDim.x + threadIdx.x;
    if (i >= 256 * 256) return;
    int o = i >> 8, oc = i & 255;
    int c = (oc & 63) * 4 + (oc >> 6);
    bf h, l;
    split2(W[o * 256 + c], h, l);
    H[i] = h; L[i] = l;
}

__global__ void k_vtrans(const bf* __restrict__ SH, const bf* __restrict__ SL,
                         bf* __restrict__ DH, bf* __restrict__ DL)
{
    __shared__ uint16_t th[32][34], tl[32][34];
    int b = blockIdx.z;
    int hc0 = blockIdx.x * 32;
    int n0  = blockIdx.y * 32;
    int tx = threadIdx.x, ty = threadIdx.y;
    for (int i = ty; i < 32; i += 8) {
        long src = ((long)b * NP + n0 + i) * 512 + 256 + hc0 + tx;
        th[i][tx] = ((const uint16_t*)SH)[src];
        tl[i][tx] = ((const uint16_t*)SL)[src];
    }
    __syncthreads();
    for (int i = ty; i < 32; i += 8) {
        int hc = hc0 + i;
        int h = hc >> 6, dd = hc & 63;
        long dst = (((long)b * 4 + h) * 64 + dd) * NP + n0 + tx;
        ((uint16_t*)DH)[dst] = th[tx][i];
        ((uint16_t*)DL)[dst] = tl[tx][i];
    }
}

// ======================= edge gather: max + stats =======================
__global__ void __launch_bounds__(256) k_edge(const float* __restrict__ PQ,
                                              const int* __restrict__ knn,
                                              float* __restrict__ mx,
                                              float* __restrict__ ssum,
                                              float* __restrict__ sssq,
                                              int Co)
{
    __shared__ long nbb[KNB];
    long bn = blockIdx.x;
    int  inst = (int)(bn / NP);
    if (threadIdx.x < KNB) {
        int nb = knn[bn * KNB + threadIdx.x];
        nbb[threadIdx.x] = ((long)inst * NP + nb) * (2 * Co) + Co;
    }
    __syncthreads();
    const float* Prow = PQ + bn * (2 * Co);
    for (int o = threadIdx.x; o < Co; o += 256) {
        float p = Prow[o];
        float mv = -3.4e38f, s = 0.f, ss = 0.f;
        #pragma unroll
        for (int k2 = 0; k2 < KNB; k2++) {
            float v = p + PQ[nbb[k2] + o];
            mv = fmaxf(mv, v); s += v; ss += v * v;
        }
        mx[bn * Co + o] = mv;
        atomicAdd(&ssum[inst * 1024 + o], s);
        atomicAdd(&sssq[inst * 1024 + o], ss);
    }
}

// ======================= per-channel stats =======================
__global__ void __launch_bounds__(256) k_colsum(const float* __restrict__ X, int ldx,
                                                float* __restrict__ ssum,
                                                float* __restrict__ sssq, int Co)
{
    int nch = NP / 128;
    int inst = blockIdx.x / nch;
    int ch   = blockIdx.x % nch;
    long r0 = (long)inst * NP + ch * 128;
    for (int o = threadIdx.x; o < Co; o += 256) {
        float s = 0.f, ss = 0.f;
        for (int r = 0; r < 128; r++) {
            float v = X[(r0 + r) * ldx + o];
            s += v; ss += v * v;
        }
        atomicAdd(&ssum[inst * 1024 + o], s);
        atomicAdd(&sssq[inst * 1024 + o], ss);
    }
}

// ======================= normalize + act -> fp32 =======================
__global__ void k_norm_act(const float* __restrict__ X, int ldx,
                           float* __restrict__ Y, int ldy,
                           const float* __restrict__ ssum,
                           const float* __restrict__ sssq,
                           int Co, long rows, float invcnt, int act)
{
    long i = blockIdx.x * (long)blockDim.x + threadIdx.x;
    if (i >= rows * Co) return;
    int  o  = (int)(i % Co);
    long rn = i / Co;
    int  inst = (int)(rn / NP);
    float mu  = ssum[inst * 1024 + o] * invcnt;
    float var = sssq[inst * 1024 + o] * invcnt - mu * mu;
    float v = (X[rn * ldx + o] - mu) * rsqrtf(var + EPSI);
    if (act == 1) v = (v >= 0.f) ? v : 0.2f * v;
    else          v = (v > 0.f)  ? v : 0.f;
    Y[rn * ldy + o] = v;
}

// ======================= normalize + act -> bf16 hi/lo =======================
__global__ void k_norm_act_split(const float* __restrict__ X, int ldx,
                                 bf* __restrict__ H, bf* __restrict__ L,
                                 int ldy, int offy,
                                 const float* __restrict__ ssum,
                                 const float* __restrict__ sssq,
                                 int Co, long rows, float invcnt, int act)
{
    long i = blockIdx.x * (long)blockDim.x + threadIdx.x;
    if (i >= rows * Co) return;
    int  o  = (int)(i % Co);
    long rn = i / Co;
    int  inst = (int)(rn / NP);
    float mu  = ssum[inst * 1024 + o] * invcnt;
    float var = sssq[inst * 1024 + o] * invcnt - mu * mu;
    float v = (X[rn * ldx + o] - mu) * rsqrtf(var + EPSI);
    if (act == 1) v = (v >= 0.f) ? v : 0.2f * v;
    else          v = (v > 0.f)  ? v : 0.f;
    bf h, l;
    split2(v, h, l);
    H[rn * ldy + offy + o] = h;
    L[rn * ldy + offy + o] = l;
}

// ======================= host =======================
template <int EPI>
static void gemm_any(const bf* AH, const bf* AL, long lda,
                     const bf* WH, const bf* WL, long ldw,
                     const float* bias, const float* bias2,
                     float* C, bf* OH, bf* OL, int ldc,
                     int M, int Nout, int K)
{
    long ctas = (long)(M / 128) * (Nout / 128);
    if (ctas >= 200) {
        dim3 g(Nout / 128, M / 128);
        mma_gemm<EPI, 128, 128><<<g, 256, SM_128_128>>>(AH, AL, lda, WH, WL, ldw,
            bias, bias2, C, OH, OL, ldc, K);
    } else if (ctas * 2 >= 200) {
        dim3 g(Nout / 128, M / 64);
        mma_gemm<EPI, 64, 128><<<g, 256, SM_64_128>>>(AH, AL, lda, WH, WL, ldw,
            bias, bias2, C, OH, OL, ldc, K);
    } else {
        dim3 g(Nout / 64, M / 64);
        mma_gemm<EPI, 64, 64><<<g, 256, SM_64_64>>>(AH, AL, lda, WH, WL, ldw,
            bias, bias2, C, OH, OL, ldc, K);
    }
}
static void gemm_f(const bf* AH, const bf* AL, long lda,
                   const bf* WH, const bf* WL, long ldw,
                   const float* bias, float* C, int ldc, int M, int Nout, int K)
{
    gemm_any<0>(AH, AL, lda, WH, WL, ldw, bias, nullptr, C, nullptr, nullptr, ldc, M, Nout, K);
}
static void gemm_s(const bf* AH, const bf* AL, long lda,
                   const bf* WH, const bf* WL, long ldw,
                   const float* bias, const float* bias2,
                   bf* OH, bf* OL, int ldc, int M, int Nout, int K)
{
    gemm_any<1>(AH, AL, lda, WH, WL, ldw, bias, bias2, nullptr, OH, OL, ldc, M, Nout, K);
}

#define GSA(sym, var, type) cudaGetSymbolAddress(&pv, sym); type* var = (type*)pv
#define CVTS(st, src, ldi, cols, total, H, L, ldo) \
    k_cvt<<<(int)(((total) / 4 + 255) / 256), 256, 0, st>>>(src, ldi, cols, total, H, L, ldo)
#define CVT(src, ldi, cols, total, H, L, ldo) CVTS(0, src, ldi, cols, total, H, L, ldo)

extern "C" void kernel_launch(void* const* d_in, const int* in_sizes, int n_in,
                              void* d_out, int out_size)
{
    const float* coords1 = (const float*)d_in[0];
    const float* coords2 = (const float*)d_in[2];
    const float* feats1  = (const float*)d_in[1];
    const float* feats2  = (const float*)d_in[3];
    const float* gW1 = (const float*)d_in[4];
    const float* gW2 = (const float*)d_in[5];
    const float* gW3 = (const float*)d_in[6];
    const float* Wq  = (const float*)d_in[7];  const float* bq  = (const float*)d_in[8];
    const float* Wk  = (const float*)d_in[9];  const float* bk  = (const float*)d_in[10];
    const float* Wv  = (const float*)d_in[11]; const float* bv  = (const float*)d_in[12];
    const float* Wo  = (const float*)d_in[13]; const float* bo  = (const float*)d_in[14];
    const float* Wm1 = (const float*)d_in[15]; const float* bm1 = (const float*)d_in[16];
    const float* Wm2 = (const float*)d_in[17]; const float* bm2 = (const float*)d_in[18];
    float* out = (float*)d_out;

    static int attr_set = 0;
    static cudaStream_t s2 = 0, s3 = 0, s4 = 0;
    static cudaEvent_t evf = 0, evk2 = 0, evk3 = 0, evG[2] = {0,0}, evA[2] = {0,0};
    if (!attr_set) {
        cudaFuncSetAttribute(mma_gemm<0,128,128>, cudaFuncAttributeMaxDynamicSharedMemorySize, SM_128_128);
        cudaFuncSetAttribute(mma_gemm<1,128,128>, cudaFuncAttributeMaxDynamicSharedMemorySize, SM_128_128);
        cudaFuncSetAttribute(mma_gemm<0,64,128>,  cudaFuncAttributeMaxDynamicSharedMemorySize, SM_64_128);
        cudaFuncSetAttribute(mma_gemm<1,64,128>,  cudaFuncAttributeMaxDynamicSharedMemorySize, SM_64_128);
        cudaFuncSetAttribute(mma_gemm<0,64,64>,   cudaFuncAttributeMaxDynamicSharedMemorySize, SM_64_64);
        cudaFuncSetAttribute(mma_gemm<1,64,64>,   cudaFuncAttributeMaxDynamicSharedMemorySize, SM_64_64);
        cudaFuncSetAttribute(k_flash, cudaFuncAttributeMaxDynamicSharedMemorySize, FA_SMEM);
        cudaStreamCreateWithFlags(&s2, cudaStreamNonBlocking);
        cudaStreamCreateWithFlags(&s3, cudaStreamNonBlocking);
        cudaStreamCreateWithFlags(&s4, cudaStreamNonBlocking);
        cudaEventCreateWithFlags(&evf, cudaEventDisableTiming);
        cudaEventCreateWithFlags(&evk2, cudaEventDisableTiming);
        cudaEventCreateWithFlags(&evk3, cudaEventDisableTiming);
        cudaEventCreateWithFlags(&evG[0], cudaEventDisableTiming);
        cudaEventCreateWithFlags(&evG[1], cudaEventDisableTiming);
        cudaEventCreateWithFlags(&evA[0], cudaEventDisableTiming);
        cudaEventCreateWithFlags(&evA[1], cudaEventDisableTiming);
        attr_set = 1;
    }

    void* pv;
    GSA(d_FE,  FEb, float);
    GSA(d_KN,  KNb, int);
    GSA(d_PQ,  PQp, float);
    GSA(d_MX,  MXp, float);
    GSA(d_STT, STp, float);
    GSA(d_BIAS, BP, float);
    GSA(d_AH,  AH, bf);    GSA(d_AL,  AL, bf);
    GSA(d_W1H, W1H, bf);   GSA(d_W1L, W1L, bf);
    GSA(d_W2H, W2H, bf);   GSA(d_W2L, W2L, bf);
    GSA(d_W3H, W3H, bf);   GSA(d_W3L, W3L, bf);
    GSA(d_WQH, WQH, bf);   GSA(d_WQL, WQL, bf);
    GSA(d_WKVH, WKVH, bf); GSA(d_WKVL, WKVL, bf);
    GSA(d_WOH, WOH, bf);   GSA(d_WOL, WOL, bf);
    GSA(d_WM1H, WM1H, bf); GSA(d_WM1L, WM1L, bf);
    GSA(d_WM2H, WM2H, bf); GSA(d_WM2L, WM2L, bf);
    GSA(d_QHH, QHH, bf);   GSA(d_QHL, QHL, bf);
    GSA(d_KVH, KVH, bf);   GSA(d_KVL, KVL, bf);
    GSA(d_VTH, VTH, bf);   GSA(d_VTL, VTL, bf);
    GSA(d_OHH, OHH, bf);   GSA(d_OHL, OHL, bf);
    float* SUM = STp;
    float* SSQ = STp + 4 * 1024;
    float* FE[2] = { FEb, FEb + (long)M4 * 256 };
    bf* F1H = AH;               bf* F1L = AL;
    bf* F2H = AH + (long)M4 * 512;
    bf* F2L = AL + (long)M4 * 512;

    const int EWB = 256;
    dim3 tb(32, 8);

    cudaEventRecord(evf, 0);
    cudaStreamWaitEvent(s2, evf, 0);
    cudaStreamWaitEvent(s3, evf, 0);
    cudaStreamWaitEvent(s4, evf, 0);
    k_knn<<<BB * NP, 256, 0, s3>>>(coords1, KNb);
    k_knn<<<BB * NP, 256, 0, s4>>>(coords2, KNb + (long)M4 * KNB);
    cudaEventRecord(evk2, s3);
    cudaEventRecord(evk3, s4);

    for (int i = 0; i < 2; i++) {
        long o1 = (long)i * 512 * 256, o2 = (long)i * 1024 * 256, o3 = (long)i * 256 * 1024;
        k_prepw_b<<<(256 * 256 + 255) / 256, 256, 0, s2>>>(gW1 + (long)i * 256 * 512,
                                                           W1H + o1, W1L + o1, 256, 256);
        k_prepw_b<<<(512 * 256 + 255) / 256, 256, 0, s2>>>(gW2 + (long)i * 512 * 512,
                                                           W2H + o2, W2L + o2, 512, 256);
        CVTS(s2, gW3 + (long)i * 256 * 1024, 1024, 1024, (long)256 * 1024,
             W3H + o3, W3L + o3, 1024);
        cudaEventRecord(evG[i], s2);
    }
    for (int i = 0; i < 2; i++) {
        long oq = (long)i * 65536, okv = (long)i * 512 * 256;
        long om1 = (long)i * 262144, om2 = (long)i * 131072;
        float* BQP = BP + i * 768;
        float* BKP = BQP + 256;
        float* BVP = BQP + 512;
        k_prepw_perm<<<256, 256, 0, s2>>>(Wq + oq, 0.125f, WQH + oq, WQL + oq, 0,
                                          bq + (long)i * 256, BQP);
        k_prepw_perm<<<256, 256, 0, s2>>>(Wk + oq, 1.f, WKVH + okv, WKVL + okv, 0,
                                          bk + (long)i * 256, BKP);
        k_prepw_perm<<<256, 256, 0, s2>>>(Wv + oq, 1.f, WKVH + okv, WKVL + okv, 256,
                                          bv + (long)i * 256, BVP);
        k_prepw_colperm<<<256, 256, 0, s2>>>(Wo + oq, WOH + oq, WOL + oq);
        CVTS(s2, Wm1 + om1, 512, 512, (long)262144, WM1H + om1, WM1L + om1, 512);
        CVTS(s2, Wm2 + om2, 512, 512, (long)131072, WM2H + om2, WM2L + om2, 512);
        cudaEventRecord(evA[i], s2);
    }

    k_transpose<<<dim3(NP / 32, 256 / 32, BB), tb>>>(feats1, FE[0], 256, NP);
    k_transpose<<<dim3(NP / 32, 256 / 32, BB), tb>>>(feats2, FE[1], 256, NP);

    const long R8 = M8, R4 = M4;
    int joined = 0;

    for (int li = 0; li < 4; li++) {
        int i = li / 2;
        if ((li & 1) == 0) {
            // ---------------- GCN layer i (both clouds batched) ----------------
            long o1 = (long)i * 512 * 256, o2 = (long)i * 1024 * 256, o3 = (long)i * 256 * 1024;
            cudaStreamWaitEvent(0, evG[i], 0);
            CVT(FEb, 256, 256, R8 * 256, AH, AL, 1024);
            gemm_f(AH, AL, 1024, W1H + o1, W1L + o1, 256, nullptr, PQp, 512, (int)R8, 512, 256);
            cudaMemsetAsync(STp, 0, sizeof(float) * 2 * 4 * 1024, 0);
            if (!joined) {
                cudaStreamWaitEvent(0, evk2, 0);
                cudaStreamWaitEvent(0, evk3, 0);
                joined = 1;
            }
            k_edge<<<(int)R8, 256>>>(PQp, KNb, MXp, SUM, SSQ, 256);
            k_norm_act_split<<<(int)((R8 * 256 + EWB - 1) / EWB), EWB>>>(
                MXp, 256, AH, AL, 1024, 256, SUM, SSQ, 256, R8, 1.f / 32768.f, 1);
            gemm_f(AH + 256, AL + 256, 1024, W2H + o2, W2L + o2, 256, nullptr,
                   PQp, 1024, (int)R8, 1024, 256);
            cudaMemsetAsync(STp, 0, sizeof(float) * 2 * 4 * 1024, 0);
            k_edge<<<(int)R8, 256>>>(PQp, KNb, MXp, SUM, SSQ, 512);
            k_norm_act_split<<<(int)((R8 * 512 + EWB - 1) / EWB), EWB>>>(
                MXp, 512, AH, AL, 1024, 512, SUM, SSQ, 512, R8, 1.f / 32768.f, 1);
            gemm_f(AH, AL, 1024, W3H + o3, W3L + o3, 1024, nullptr, MXp, 256, (int)R8, 256, 1024);
            cudaMemsetAsync(STp, 0, sizeof(float) * 2 * 4 * 1024, 0);
            k_colsum<<<(int)(R8 / 128), 256>>>(MXp, 256, SUM, SSQ, 256);
            k_norm_act<<<(int)((R8 * 256 + EWB - 1) / EWB), EWB>>>(
                MXp, 256, FEb, 256, SUM, SSQ, 256, R8, 1.f / (float)NP, 1);
        } else {
            // ---------------- cross-attention layer i ----------------
            long oq = (long)i * 65536, okv = (long)i * 512 * 256;
            long om1 = (long)i * 262144, om2 = (long)i * 131072;
            float* BQP = BP + i * 768;
            float* BKP = BQP + 256;
            float* BVP = BQP + 512;
            cudaStreamWaitEvent(0, evA[i], 0);
            for (int a = 0; a < 2; a++) {
                const float* f1p = FE[a];
                const float* f2p = FE[1 - a];
                CVT(f1p, 256, 256, R4 * 256, F1H, F1L, 512);
                gemm_s(F1H, F1L, 512, WQH + oq, WQL + oq, 256, BQP, nullptr,
                       QHH, QHL, 256, (int)R4, 256, 256);
                CVT(f2p, 256, 256, R4 * 256, F2H, F2L, 256);
                gemm_s(F2H, F2L, 256, WKVH + okv, WKVL + okv, 256, BKP, BVP,
                       KVH, KVL, 512, (int)R4, 512, 256);
                k_vtrans<<<dim3(8, NP / 32, BB), tb>>>(KVH, KVL, VTH, VTL);
                k_flash<<<dim3(32, 8), 128, FA_SMEM>>>(QHH, QHL, KVH, KVL, VTH, VTL, OHH, OHL);
                gemm_s(OHH, OHL, 256, WOH + oq, WOL + oq, 256, bo + (long)i * 256, nullptr,
                       F1H + 256, F1L + 256, 512, (int)R4, 256, 256);
                gemm_f(F1H, F1L, 512, WM1H + om1, WM1L + om1, 512, bm1 + (long)i * 512,
                       PQp, 512, (int)R4, 512, 512);
                cudaMemsetAsync(STp, 0, sizeof(float) * 2 * 4 * 1024, 0);
                k_colsum<<<(int)(R4 / 128), 256>>>(PQp, 512, SUM, SSQ, 512);
                k_norm_act_split<<<(int)((R4 * 512 + EWB - 1) / EWB), EWB>>>(
                    PQp, 512, F1H, F1L, 512, 0, SUM, SSQ, 512, R4, 1.f / (float)NP, 2);
                gemm_f(F1H, F1L, 512, WM2H + om2, WM2L + om2, 512, bm2 + (long)i * 256,
                       FE[a], 256, (int)R4, 256, 512);
            }
        }
    }

    k_transpose<<<dim3(256 / 32, NP / 32, BB), tb>>>(FE[0], out, NP, 256);
    k_transpose<<<dim3(256 / 32, NP / 32, BB), tb>>>(FE[1], out + (long)M4 * 256, NP, 256);
}

// round 14
// speedup vs baseline: 1.0434x; 1.0434x over previous
#include <cuda_runtime.h>
#include <cuda_bf16.h>
#include <cstdint>

#define BB   2
#define NP   2048
#define KNB  16
#define EPSI 1e-5f
#define M4   (BB*NP)        // 4096
#define M8   (2*BB*NP)      // 8192

typedef __nv_bfloat16 bf;

// ======================= helpers =======================
__device__ __forceinline__ void split2(float x, bf& h, bf& l){
    h = __float2bfloat16(x);
    l = __float2bfloat16(x - __bfloat162float(h));
}
__device__ __forceinline__ uint32_t packbf(bf a, bf b){
    return ((uint32_t)__bfloat16_as_ushort(b) << 16) | (uint32_t)__bfloat16_as_ushort(a);
}
__device__ __forceinline__ uint32_t packsplit(float a, float b, uint32_t& lo){
    bf ha, la, hb, lb;
    split2(a, ha, la); split2(b, hb, lb);
    lo = packbf(la, lb);
    return packbf(ha, hb);
}

#define MMA16816(d, a, b) \
    asm volatile("mma.sync.aligned.m16n8k16.row.col.f32.bf16.bf16.f32 " \
        "{%0,%1,%2,%3}, {%4,%5,%6,%7}, {%8,%9}, {%0,%1,%2,%3};" \
        : "+f"((d)[0]), "+f"((d)[1]), "+f"((d)[2]), "+f"((d)[3]) \
        : "r"((a)[0]), "r"((a)[1]), "r"((a)[2]), "r"((a)[3]), \
          "r"((b)[0]), "r"((b)[1]))

#define LDSM4(r0, r1, r2, r3, a) \
    asm volatile("ldmatrix.sync.aligned.m8n8.x4.shared.b16 {%0,%1,%2,%3}, [%4];" \
        : "=r"(r0), "=r"(r1), "=r"(r2), "=r"(r3) : "r"(a))

#define CPA16(dst, src) \
    asm volatile("cp.async.cg.shared.global [%0], [%1], 16;" :: "r"(dst), "l"(src))
#define CP_COMMIT() asm volatile("cp.async.commit_group;" ::: "memory")
#define CP_WAIT1()  asm volatile("cp.async.wait_group 1;" ::: "memory")
#define CP_WAIT0()  asm volatile("cp.async.wait_group 0;" ::: "memory")

// ======================= device scratch =======================
__device__ __align__(16) float d_FE [M8*256];
__device__ int   d_KN [M8*KNB];
__device__ __align__(16) float d_PQ [M8*1024];
__device__ __align__(16) float d_MX [M8*512];
__device__ float d_STT[2*4*1024];
__device__ float d_BIAS[2*3*256];
__device__ __align__(16) bf d_AH [M8*1024];
__device__ __align__(16) bf d_AL [M8*1024];
__device__ __align__(16) bf d_W1H[2*512*256],  d_W1L[2*512*256];
__device__ __align__(16) bf d_W2H[2*1024*256], d_W2L[2*1024*256];
__device__ __align__(16) bf d_W3H[2*256*1024], d_W3L[2*256*1024];
__device__ __align__(16) bf d_WQH[2*256*256],  d_WQL[2*256*256];
__device__ __align__(16) bf d_WKVH[2*512*256], d_WKVL[2*512*256];
__device__ __align__(16) bf d_WOH[2*256*256],  d_WOL[2*256*256];
__device__ __align__(16) bf d_WM1H[2*512*512], d_WM1L[2*512*512];
__device__ __align__(16) bf d_WM2H[2*256*512], d_WM2L[2*256*512];
__device__ __align__(16) bf d_QHH[M4*256], d_QHL[M4*256];
__device__ __align__(16) bf d_KVH[M4*512], d_KVL[M4*512];
__device__ __align__(16) bf d_VTH[M4*256], d_VTL[M4*256];
__device__ __align__(16) bf d_OHH[M4*256], d_OHL[M4*256];
__device__ __align__(16) float d_OP[2L*8*NP*64];   // split-KV partial O
__device__ __align__(16) float d_ML[2L*8*NP*2];    // split-KV partial (m,l)

// ======================= transpose (fp32) =======================
__global__ void k_transpose(const float* __restrict__ in, float* __restrict__ out,
                            int R, int Cc)
{
    __shared__ float t[32][33];
    int b  = blockIdx.z;
    const float* ip = in  + (long)b * R * Cc;
    float*       op = out + (long)b * R * Cc;
    int c0 = blockIdx.x * 32, r0 = blockIdx.y * 32;
    for (int i = threadIdx.y; i < 32; i += 8)
        t[i][threadIdx.x] = ip[(long)(r0 + i) * Cc + c0 + threadIdx.x];
    __syncthreads();
    for (int i = threadIdx.y; i < 32; i += 8)
        op[(long)(c0 + i) * R + r0 + threadIdx.x] = t[threadIdx.x][i];
}

// ======================= kNN =======================
__global__ void __launch_bounds__(256) k_knn(const float* __restrict__ coords,
                                             int* __restrict__ knn)
{
    __shared__ float sx[NP], sy[NP], sz[NP], sd[NP];
    __shared__ float wv[8];
    __shared__ int   wi[8];
    int b = blockIdx.x / NP;
    int n = blockIdx.x % NP;
    const float* cb = coords + (long)b * 3 * NP;
    for (int j = threadIdx.x; j < NP; j += 256) {
        sx[j] = cb[j]; sy[j] = cb[NP + j]; sz[j] = cb[2 * NP + j];
    }
    __syncthreads();
    float xn = sx[n], yn = sy[n], zn = sz[n];
    float sqn = xn*xn + yn*yn + zn*zn;
    for (int j = threadIdx.x; j < NP; j += 256) {
        float x = sx[j], y = sy[j], z = sz[j];
        float d = sqn + (x*x + y*y + z*z) - 2.f * (xn*x + yn*y + zn*z);
        sd[j] = (j == n) ? 3.4e38f : d;
    }
    __syncthreads();
    int lane = threadIdx.x & 31, warp = threadIdx.x >> 5;
    for (int r = 0; r < KNB; r++) {
        float best = 3.0e38f; int bi = NP;
        for (int j = threadIdx.x; j < NP; j += 256) {
            float v = sd[j];
            if (v < best) { best = v; bi = j; }
        }
        #pragma unroll
        for (int off = 16; off; off >>= 1) {
            float ov = __shfl_down_sync(0xffffffffu, best, off);
            int   oi = __shfl_down_sync(0xffffffffu, bi,   off);
            if (ov < best || (ov == best && oi < bi)) { best = ov; bi = oi; }
        }
        if (lane == 0) { wv[warp] = best; wi[warp] = bi; }
        __syncthreads();
        if (threadIdx.x == 0) {
            float fb = wv[0]; int fi = wi[0];
            for (int w = 1; w < 8; w++)
                if (wv[w] < fb || (wv[w] == fb && wi[w] < fi)) { fb = wv[w]; fi = wi[w]; }
            knn[((long)b * NP + n) * KNB + r] = fi;
            sd[fi] = 3.4e38f;
        }
        __syncthreads();
    }
}

// ======================= HMMA GEMM (cp.async 2-stage + ldmatrix) ==============
template <int EPI, int MR, int NR>
__global__ void __launch_bounds__(256) mma_gemm(
    const bf* __restrict__ AH, const bf* __restrict__ AL, long lda,
    const bf* __restrict__ WH, const bf* __restrict__ WL, long ldw,
    const float* __restrict__ bias, const float* __restrict__ bias2,
    float* __restrict__ C, bf* __restrict__ OH, bf* __restrict__ OL,
    int ldc, int K)
{
    constexpr int MT    = MR / 32;
    constexpr int NW    = NR / 4;
    constexpr int NT    = NW / 8;
    constexpr int NBL   = NW / 16;
    constexpr int ATILE = MR * 80;
    constexpr int WTILE = NR * 80;
    constexpr int STAGE = 2 * (ATILE + WTILE);

    extern __shared__ __align__(16) char smem[];
    uint32_t sbase = (uint32_t)__cvta_generic_to_shared(smem);

    int tid = threadIdx.x, wid = tid >> 5, lane = tid & 31;
    int g = lane >> 2, tg = lane & 3;
    int wm = (wid >> 2) * (MR / 2);
    int wn = (wid & 3) * NW;
    int lr = tid >> 2;
    int lq = tid & 3;

    uint32_t aoff = (uint32_t)((wm + (lane & 7) + ((lane >> 3) & 1) * 8) * 80 + (lane >> 4) * 16);
    uint32_t boff = (uint32_t)((wn + (lane >> 4) * 8 + (lane & 7)) * 80 + ((lane >> 3) & 1) * 16);

    long m0 = (long)blockIdx.y * MR;
    int  n0 = blockIdx.x * NR;
    const bf* pAH = AH + m0 * lda;
    const bf* pAL = AL + m0 * lda;
    const bf* pWH = WH + (long)n0 * ldw;
    const bf* pWL = WL + (long)n0 * ldw;

    float acc[MT][NT][4];
    #pragma unroll
    for (int mt = 0; mt < MT; mt++)
        #pragma unroll
        for (int nt = 0; nt < NT; nt++)
            #pragma unroll
            for (int q = 0; q < 4; q++) acc[mt][nt][q] = 0.f;

    int nch = K >> 5;

    {
        uint32_t st = sbase;
        #pragma unroll
        for (int it = 0; it < MR / 64; it++) {
            int r = lr + it * 64;
            uint32_t d = st + r * 80 + lq * 16;
            CPA16(d,         pAH + (long)r * lda + lq * 8);
            CPA16(d + ATILE, pAL + (long)r * lda + lq * 8);
        }
        #pragma unroll
        for (int it = 0; it < NR / 64; it++) {
            int r = lr + it * 64;
            uint32_t d = st + 2 * ATILE + r * 80 + lq * 16;
            CPA16(d,         pWH + (long)r * ldw + lq * 8);
            CPA16(d + WTILE, pWL + (long)r * ldw + lq * 8);
        }
        CP_COMMIT();
    }

    for (int c = 0; c < nch; c++) {
        if (c + 1 < nch) {
            long k0 = (long)(c + 1) << 5;
            uint32_t st = sbase + ((c + 1) & 1) * STAGE;
            #pragma unroll
            for (int it = 0; it < MR / 64; it++) {
                int r = lr + it * 64;
                uint32_t d = st + r * 80 + lq * 16;
                CPA16(d,         pAH + (long)r * lda + k0 + lq * 8);
                CPA16(d + ATILE, pAL + (long)r * lda + k0 + lq * 8);
            }
            #pragma unroll
            for (int it = 0; it < NR / 64; it++) {
                int r = lr + it * 64;
                uint32_t d = st + 2 * ATILE + r * 80 + lq * 16;
                CPA16(d,         pWH + (long)r * ldw + k0 + lq * 8);
                CPA16(d + WTILE, pWL + (long)r * ldw + k0 + lq * 8);
            }
            CP_COMMIT();
            CP_WAIT1();
        } else {
            CP_WAIT0();
        }
        __syncthreads();

        uint32_t stA = sbase + (c & 1) * STAGE;
        uint32_t aA = stA + aoff;
        uint32_t bA = stA + 2 * ATILE + boff;

        #pragma unroll
        for (int ks = 0; ks < 2; ks++) {
            int kbB = ks * 32;
            uint32_t ah[MT][4], al[MT][4];
            #pragma unroll
            for (int mt = 0; mt < MT; mt++) {
                uint32_t a0 = aA + mt * (16 * 80) + kbB;
                LDSM4(ah[mt][0], ah[mt][1], ah[mt][2], ah[mt][3], a0);
                LDSM4(al[mt][0], al[mt][1], al[mt][2], al[mt][3], a0 + ATILE);
            }
            uint32_t bh[NT][2], bl[NT][2];
            #pragma unroll
            for (int np2 = 0; np2 < NBL; np2++) {
                uint32_t b0 = bA + np2 * (16 * 80) + kbB;
                LDSM4(bh[np2*2][0], bh[np2*2][1], bh[np2*2+1][0], bh[np2*2+1][1], b0);
                LDSM4(bl[np2*2][0], bl[np2*2][1], bl[np2*2+1][0], bl[np2*2+1][1], b0 + WTILE);
            }
            #pragma unroll
            for (int mt = 0; mt < MT; mt++)
                #pragma unroll
                for (int nt = 0; nt < NT; nt++) {
                    MMA16816(acc[mt][nt], ah[mt], bh[nt]);
                    MMA16816(acc[mt][nt], ah[mt], bl[nt]);
                    MMA16816(acc[mt][nt], al[mt], bh[nt]);
                }
        }
        __syncthreads();
    }

    #pragma unroll
    for (int mt = 0; mt < MT; mt++) {
        long row = m0 + wm + mt * 16 + g;
        #pragma unroll
        for (int nt = 0; nt < NT; nt++) {
            int col = n0 + wn + nt * 8 + tg * 2;
            float b0 = 0.f, b1 = 0.f;
            if (bias) {
                const float* bp = (bias2 && col >= 256) ? (bias2 - 256) : bias;
                b0 = __ldg(&bp[col]); b1 = __ldg(&bp[col + 1]);
            }
            float v0 = acc[mt][nt][0] + b0;
            float v1 = acc[mt][nt][1] + b1;
            float v2 = acc[mt][nt][2] + b0;
            float v3 = acc[mt][nt][3] + b1;
            if (EPI == 0) {
                *(float2*)(C + row * (long)ldc + col)       = make_float2(v0, v1);
                *(float2*)(C + (row + 8) * (long)ldc + col) = make_float2(v2, v3);
            } else {
                uint32_t lo0, lo1;
                uint32_t hi0 = packsplit(v0, v1, lo0);
                uint32_t hi1 = packsplit(v2, v3, lo1);
                *(uint32_t*)(OH + row * (long)ldc + col)       = hi0;
                *(uint32_t*)(OL + row * (long)ldc + col)       = lo0;
                *(uint32_t*)(OH + (row + 8) * (long)ldc + col) = hi1;
                *(uint32_t*)(OL + (row + 8) * (long)ldc + col) = lo1;
            }
        }
    }
}

#define SM_128_128 (2 * 2 * (128*80 + 128*80))
#define SM_64_128  (2 * 2 * (64*80  + 128*80))
#define SM_64_64   (2 * 2 * (64*80  + 64*80))

// ======================= fused flash attention (split-KV) =======================
// 128-row q-blocks, 256 threads, grid (16, 8, 2): blockIdx.z picks a KV half.
// Emits unnormalized partial O (fp32) + per-row (m, l); k_fmerge combines.
#define FQ_B (128*144)
#define FK_B (64*144)
#define FA_SMEM (2*FQ_B + 4*FK_B)
__global__ void __launch_bounds__(256) k_flash(
    const bf* __restrict__ QH, const bf* __restrict__ QL,
    const bf* __restrict__ KVH, const bf* __restrict__ KVL,
    const bf* __restrict__ VH, const bf* __restrict__ VL,
    float* __restrict__ OP, float* __restrict__ ML)
{
    extern __shared__ __align__(16) char smem[];
    char* sQh = smem;
    char* sQl = smem + FQ_B;
    char* sKh = smem + 2 * FQ_B;
    char* sVh = sKh + 2 * FK_B;
    uint32_t sbase = (uint32_t)__cvta_generic_to_shared(smem);

    int tid = threadIdx.x, wid = tid >> 5, lane = tid & 31;
    int g = lane >> 2, tg = lane & 3;
    int z = blockIdx.y;
    int b = z >> 2, h = z & 3;
    long q0 = (long)blockIdx.x * 128;
    int wm = wid * 16;
    int part = blockIdx.z;
    int c0 = part * (NP / 128);        // 16 chunks per half
    int c1 = c0 + (NP / 128);

    uint32_t aoff = (uint32_t)((wm + (lane & 7) + ((lane >> 3) & 1) * 8) * 144 + (lane >> 4) * 16);
    uint32_t boff = (uint32_t)(((lane >> 4) * 8 + (lane & 7)) * 144 + ((lane >> 3) & 1) * 16);
    uint32_t qA = sbase + aoff;
    uint32_t kA = sbase + 2 * FQ_B + boff;
    uint32_t vA = kA + 2 * FK_B;

    const bf* pQH = QH + ((long)b * NP + q0) * 256 + h * 64;
    const bf* pQL = QL + ((long)b * NP + q0) * 256 + h * 64;

    #pragma unroll
    for (int it = 0; it < 4; it++) {
        int i = tid + it * 256;
        int r = i >> 3, q = i & 7;
        *(uint4*)(sQh + r * 144 + q * 16) = *(const uint4*)(pQH + (long)r * 256 + q * 8);
        *(uint4*)(sQl + r * 144 + q * 16) = *(const uint4*)(pQL + (long)r * 256 + q * 8);
    }

    float m0 = -3.4e38f, m1 = -3.4e38f, l0 = 0.f, l1 = 0.f;
    float acc[8][4];
    #pragma unroll
    for (int nt = 0; nt < 8; nt++)
        #pragma unroll
        for (int q = 0; q < 4; q++) acc[nt][q] = 0.f;

    for (int c = c0; c < c1; c++) {
        const bf* pKH = KVH + ((long)b * NP + c * 64) * 512 + h * 64;
        const bf* pKL = KVL + ((long)b * NP + c * 64) * 512 + h * 64;
        const bf* pVH = VH + (long)z * 64 * NP + c * 64;
        const bf* pVL = VL + (long)z * 64 * NP + c * 64;
        #pragma unroll
        for (int it = 0; it < 2; it++) {
            int i = tid + it * 256;
            int r = i >> 3, q = i & 7;
            *(uint4*)(sKh + r * 144 + q * 16)        = *(const uint4*)(pKH + (long)r * 512 + q * 8);
            *(uint4*)(sKh + FK_B + r * 144 + q * 16) = *(const uint4*)(pKL + (long)r * 512 + q * 8);
            *(uint4*)(sVh + r * 144 + q * 16)        = *(const uint4*)(pVH + (long)r * NP + q * 8);
            *(uint4*)(sVh + FK_B + r * 144 + q * 16) = *(const uint4*)(pVL + (long)r * NP + q * 8);
        }
        __syncthreads();

        float sacc[8][4];
        #pragma unroll
        for (int nt = 0; nt < 8; nt++)
            #pragma unroll
            for (int q = 0; q < 4; q++) sacc[nt][q] = 0.f;
        #pragma unroll
        for (int kk = 0; kk < 4; kk++) {
            int kbB = kk * 32;
            uint32_t aqh[4], aql[4];
            LDSM4(aqh[0], aqh[1], aqh[2], aqh[3], qA + kbB);
            LDSM4(aql[0], aql[1], aql[2], aql[3], qA + FQ_B + kbB);
            #pragma unroll
            for (int np2 = 0; np2 < 4; np2++) {
                uint32_t bh[2][2], bl[2][2];
                uint32_t b0 = kA + np2 * (16 * 144) + kbB;
                LDSM4(bh[0][0], bh[0][1], bh[1][0], bh[1][1], b0);
                LDSM4(bl[0][0], bl[0][1], bl[1][0], bl[1][1], b0 + FK_B);
                #pragma unroll
                for (int j = 0; j < 2; j++) {
                    MMA16816(sacc[np2*2+j], aqh, bh[j]);
                    MMA16816(sacc[np2*2+j], aqh, bl[j]);
                    MMA16816(sacc[np2*2+j], aql, bh[j]);
                }
            }
        }

        float rmax0 = -3.4e38f, rmax1 = -3.4e38f;
        #pragma unroll
        for (int nt = 0; nt < 8; nt++) {
            rmax0 = fmaxf(rmax0, fmaxf(sacc[nt][0], sacc[nt][1]));
            rmax1 = fmaxf(rmax1, fmaxf(sacc[nt][2], sacc[nt][3]));
        }
        rmax0 = fmaxf(rmax0, __shfl_xor_sync(0xffffffffu, rmax0, 1));
        rmax0 = fmaxf(rmax0, __shfl_xor_sync(0xffffffffu, rmax0, 2));
        rmax1 = fmaxf(rmax1, __shfl_xor_sync(0xffffffffu, rmax1, 1));
        rmax1 = fmaxf(rmax1, __shfl_xor_sync(0xffffffffu, rmax1, 2));
        float mn0 = fmaxf(m0, rmax0), mn1 = fmaxf(m1, rmax1);
        float al0 = __expf(m0 - mn0), al1 = __expf(m1 - mn1);
        m0 = mn0; m1 = mn1;

        float rs0 = 0.f, rs1 = 0.f;
        uint32_t pfh[4][4], pfl[4][4];
        #pragma unroll
        for (int nt = 0; nt < 8; nt++) {
            float p0 = __expf(sacc[nt][0] - mn0);
            float p1 = __expf(sacc[nt][1] - mn0);
            float p2 = __expf(sacc[nt][2] - mn1);
            float p3 = __expf(sacc[nt][3] - mn1);
            rs0 += p0 + p1; rs1 += p2 + p3;
            int kk = nt >> 1, base = (nt & 1) * 2;
            pfh[kk][base]     = packsplit(p0, p1, pfl[kk][base]);
            pfh[kk][base + 1] = packsplit(p2, p3, pfl[kk][base + 1]);
        }
        rs0 += __shfl_xor_sync(0xffffffffu, rs0, 1);
        rs0 += __shfl_xor_sync(0xffffffffu, rs0, 2);
        rs1 += __shfl_xor_sync(0xffffffffu, rs1, 1);
        rs1 += __shfl_xor_sync(0xffffffffu, rs1, 2);
        l0 = l0 * al0 + rs0; l1 = l1 * al1 + rs1;
        #pragma unroll
        for (int nt = 0; nt < 8; nt++) {
            acc[nt][0] *= al0; acc[nt][1] *= al0;
            acc[nt][2] *= al1; acc[nt][3] *= al1;
        }

        #pragma unroll
        for (int kk = 0; kk < 4; kk++) {
            int kbB = kk * 32;
            #pragma unroll
            for (int np2 = 0; np2 < 4; np2++) {
                uint32_t bh[2][2], bl[2][2];
                uint32_t b0 = vA + np2 * (16 * 144) + kbB;
                LDSM4(bh[0][0], bh[0][1], bh[1][0], bh[1][1], b0);
                LDSM4(bl[0][0], bl[0][1], bl[1][0], bl[1][1], b0 + FK_B);
                #pragma unroll
                for (int j = 0; j < 2; j++) {
                    MMA16816(acc[np2*2+j], pfh[kk], bh[j]);
                    MMA16816(acc[np2*2+j], pfh[kk], bl[j]);
                    MMA16816(acc[np2*2+j], pfl[kk], bh[j]);
                }
            }
        }
        __syncthreads();
    }

    // write unnormalized partial + (m, l)
    long rbase = ((long)part * 8 + z) * NP + q0 + wm;
    float* pO = OP + rbase * 64;
    #pragma unroll
    for (int nt = 0; nt < 8; nt++) {
        int col = nt * 8 + tg * 2;
        *(float2*)(pO + (long)g * 64 + col)       = make_float2(acc[nt][0], acc[nt][1]);
        *(float2*)(pO + (long)(g + 8) * 64 + col) = make_float2(acc[nt][2], acc[nt][3]);
    }
    if (tg == 0) {
        ML[(rbase + g) * 2]         = m0;
        ML[(rbase + g) * 2 + 1]     = l0;
        ML[(rbase + g + 8) * 2]     = m1;
        ML[(rbase + g + 8) * 2 + 1] = l1;
    }
}

// merge two KV-half partials -> bf16 hi/lo (Wo-input layout)
__global__ void __launch_bounds__(256) k_fmerge(
    const float* __restrict__ OP, const float* __restrict__ ML,
    bf* __restrict__ OH, bf* __restrict__ OL)
{
    long i = (long)blockIdx.x * blockDim.x + threadIdx.x;   // 8*NP*32
    if (i >= (long)8 * NP * 32) return;
    int  c2 = (int)(i & 31) * 2;
    long zn = i >> 5;                    // z*NP + n
    int  n  = (int)(zn & (NP - 1));
    int  z  = (int)(zn >> 11);
    float m0 = ML[zn * 2],                     l0 = ML[zn * 2 + 1];
    float m1 = ML[((long)8 * NP + zn) * 2],    l1 = ML[((long)8 * NP + zn) * 2 + 1];
    float m  = fmaxf(m0, m1);
    float a0 = __expf(m0 - m), a1 = __expf(m1 - m);
    float inv = 1.f / (l0 * a0 + l1 * a1);
    long o0 = zn * 64 + c2;
    float2 v0 = *(const float2*)(OP + o0);
    float2 v1 = *(const float2*)(OP + (long)8 * NP * 64 + o0);
    float x = (v0.x * a0 + v1.x * a1) * inv;
    float y = (v0.y * a0 + v1.y * a1) * inv;
    uint32_t lo;
    uint32_t hi = packsplit(x, y, lo);
    int b = z >> 2, h = z & 3;
    long od = ((long)b * NP + n) * 256 + h * 64 + c2;
    *(uint32_t*)(OH + od) = hi;
    *(uint32_t*)(OL + od) = lo;
}

// ======================= fp32 -> bf16 hi/lo =======================
__global__ void k_cvt(const float* __restrict__ src, long ldi, int cols, long total,
                      bf* __restrict__ H, bf* __restrict__ L, long ldo)
{
    long i = ((long)blockIdx.x * blockDim.x + threadIdx.x) * 4;
    if (i >= total) return;
    long r = i / cols; int c = (int)(i - r * cols);
    float4 v = *(const float4*)(src + r * ldi + c);
    uint32_t lo0, lo1;
    uint32_t hi0 = packsplit(v.x, v.y, lo0);
    uint32_t hi1 = packsplit(v.z, v.w, lo1);
    *(uint2*)(H + r * ldo + c) = make_uint2(hi0, hi1);
    *(uint2*)(L + r * ldo + c) = make_uint2(lo0, lo1);
}

__global__ void k_prepw_b(const float* __restrict__ W, bf* __restrict__ H,
                          bf* __restrict__ L, int O, int Ci)
{
    long i = blockIdx.x * (long)blockDim.x + threadIdx.x;
    if (i >= (long)O * Ci) return;
    int o = (int)(i / Ci), c = (int)(i % Ci);
    float a  = W[(long)o * 2 * Ci + c];
    float bq = W[(long)o * 2 * Ci + Ci + c];
    bf h, l;
    split2(a - bq, h, l);
    H[(long)o * Ci + c] = h; L[(long)o * Ci + c] = l;
    split2(bq, h, l);
    H[((long)O + o) * Ci + c] = h; L[((long)O + o) * Ci + c] = l;
}

__global__ void k_prepw_perm(const float* __restrict__ W, float scale,
                             bf* __restrict__ H, bf* __restrict__ L, int roff,
                             const float* __restrict__ bin, float* __restrict__ bout)
{
    int i = blockIdx.x * blockDim.x + threadIdx.x;
    if (i >= 256 * 256) return;
    int o = i >> 8, c = i & 255;
    int op = (o & 3) * 64 + (o >> 2);
    bf h, l;
    split2(W[i] * scale, h, l);
    H[(long)(roff + op) * 256 + c] = h;
    L[(long)(roff + op) * 256 + c] = l;
    if (c == 0) bout[op] = bin[o] * scale;
}

__global__ void k_prepw_colperm(const float* __restrict__ W,
                                bf* __restrict__ H, bf* __restrict__ L)
{
    int i = blockIdx.x * blockDim.x + threadIdx.x;
    if (i >= 256 * 256) return;
    int o = i >> 8, oc = i & 255;
    int c = (oc & 63) * 4 + (oc >> 6);
    bf h, l;
    split2(W[o * 256 + c], h, l);
    H[i] = h; L[i] = l;
}

__global__ void k_vtrans(const bf* __restrict__ SH, const bf* __restrict__ SL,
                         bf* __restrict__ DH, bf* __restrict__ DL)
{
    __shared__ uint16_t th[32][34], tl[32][34];
    int b = blockIdx.z;
    int hc0 = blockIdx.x * 32;
    int n0  = blockIdx.y * 32;
    int tx = threadIdx.x, ty = threadIdx.y;
    for (int i = ty; i < 32; i += 8) {
        long src = ((long)b * NP + n0 + i) * 512 + 256 + hc0 + tx;
        th[i][tx] = ((const uint16_t*)SH)[src];
        tl[i][tx] = ((const uint16_t*)SL)[src];
    }
    __syncthreads();
    for (int i = ty; i < 32; i += 8) {
        int hc = hc0 + i;
        int h = hc >> 6, dd = hc & 63;
        long dst = (((long)b * 4 + h) * 64 + dd) * NP + n0 + tx;
        ((uint16_t*)DH)[dst] = th[tx][i];
        ((uint16_t*)DL)[dst] = tl[tx][i];
    }
}

// ======================= edge gather: max + stats =======================
__global__ void __launch_bounds__(256) k_edge(const float* __restrict__ PQ,
                                              const int* __restrict__ knn,
                                              float* __restrict__ mx,
                                              float* __restrict__ ssum,
                                              float* __restrict__ sssq,
                                              int Co)
{
    __shared__ long nbb[KNB];
    long bn = blockIdx.x;
    int  inst = (int)(bn / NP);
    if (threadIdx.x < KNB) {
        int nb = knn[bn * KNB + threadIdx.x];
        nbb[threadIdx.x] = ((long)inst * NP + nb) * (2 * Co) + Co;
    }
    __syncthreads();
    const float* Prow = PQ + bn * (2 * Co);
    for (int o = threadIdx.x; o < Co; o += 256) {
        float p = Prow[o];
        float mv = -3.4e38f, s = 0.f, ss = 0.f;
        #pragma unroll
        for (int k2 = 0; k2 < KNB; k2++) {
            float v = p + PQ[nbb[k2] + o];
            mv = fmaxf(mv, v); s += v; ss += v * v;
        }
        mx[bn * Co + o] = mv;
        atomicAdd(&ssum[inst * 1024 + o], s);
        atomicAdd(&sssq[inst * 1024 + o], ss);
    }
}

// ======================= per-channel stats =======================
__global__ void __launch_bounds__(256) k_colsum(const float* __restrict__ X, int ldx,
                                                float* __restrict__ ssum,
                                                float* __restrict__ sssq, int Co)
{
    int nch = NP / 128;
    int inst = blockIdx.x / nch;
    int ch   = blockIdx.x % nch;
    long r0 = (long)inst * NP + ch * 128;
    for (int o = threadIdx.x; o < Co; o += 256) {
        float s = 0.f, ss = 0.f;
        for (int r = 0; r < 128; r++) {
            float v = X[(r0 + r) * ldx + o];
            s += v; ss += v * v;
        }
        atomicAdd(&ssum[inst * 1024 + o], s);
        atomicAdd(&sssq[inst * 1024 + o], ss);
    }
}

// ======================= normalize + act -> fp32 =======================
__global__ void k_norm_act(const float* __restrict__ X, int ldx,
                           float* __restrict__ Y, int ldy,
                           const float* __restrict__ ssum,
                           const float* __restrict__ sssq,
                           int Co, long rows, float invcnt, int act)
{
    long i = blockIdx.x * (long)blockDim.x + threadIdx.x;
    if (i >= rows * Co) return;
    int  o  = (int)(i % Co);
    long rn = i / Co;
    int  inst = (int)(rn / NP);
    float mu  = ssum[inst * 1024 + o] * invcnt;
    float var = sssq[inst * 1024 + o] * invcnt - mu * mu;
    float v = (X[rn * ldx + o] - mu) * rsqrtf(var + EPSI);
    if (act == 1) v = (v >= 0.f) ? v : 0.2f * v;
    else          v = (v > 0.f)  ? v : 0.f;
    Y[rn * ldy + o] = v;
}

// ======================= normalize + act -> bf16 hi/lo =======================
__global__ void k_norm_act_split(const float* __restrict__ X, int ldx,
                                 bf* __restrict__ H, bf* __restrict__ L,
                                 int ldy, int offy,
                                 const float* __restrict__ ssum,
                                 const float* __restrict__ sssq,
                                 int Co, long rows, float invcnt, int act)
{
    long i = blockIdx.x * (long)blockDim.x + threadIdx.x;
    if (i >= rows * Co) return;
    int  o  = (int)(i % Co);
    long rn = i / Co;
    int  inst = (int)(rn / NP);
    float mu  = ssum[inst * 1024 + o] * invcnt;
    float var = sssq[inst * 1024 + o] * invcnt - mu * mu;
    float v = (X[rn * ldx + o] - mu) * rsqrtf(var + EPSI);
    if (act == 1) v = (v >= 0.f) ? v : 0.2f * v;
    else          v = (v > 0.f)  ? v : 0.f;
    bf h, l;
    split2(v, h, l);
    H[rn * ldy + offy + o] = h;
    L[rn * ldy + offy + o] = l;
}

// ======================= host =======================
template <int EPI>
static void gemm_any(const bf* AH, const bf* AL, long lda,
                     const bf* WH, const bf* WL, long ldw,
                     const float* bias, const float* bias2,
                     float* C, bf* OH, bf* OL, int ldc,
                     int M, int Nout, int K)
{
    long ctas = (long)(M / 128) * (Nout / 128);
    if (ctas >= 200) {
        dim3 g(Nout / 128, M / 128);
        mma_gemm<EPI, 128, 128><<<g, 256, SM_128_128>>>(AH, AL, lda, WH, WL, ldw,
            bias, bias2, C, OH, OL, ldc, K);
    } else if (ctas * 2 >= 200) {
        dim3 g(Nout / 128, M / 64);
        mma_gemm<EPI, 64, 128><<<g, 256, SM_64_128>>>(AH, AL, lda, WH, WL, ldw,
            bias, bias2, C, OH, OL, ldc, K);
    } else {
        dim3 g(Nout / 64, M / 64);
        mma_gemm<EPI, 64, 64><<<g, 256, SM_64_64>>>(AH, AL, lda, WH, WL, ldw,
            bias, bias2, C, OH, OL, ldc, K);
    }
}
static void gemm_f(const bf* AH, const bf* AL, long lda,
                   const bf* WH, const bf* WL, long ldw,
                   const float* bias, float* C, int ldc, int M, int Nout, int K)
{
    gemm_any<0>(AH, AL, lda, WH, WL, ldw, bias, nullptr, C, nullptr, nullptr, ldc, M, Nout, K);
}
static void gemm_s(const bf* AH, const bf* AL, long lda,
                   const bf* WH, const bf* WL, long ldw,
                   const float* bias, const float* bias2,
                   bf* OH, bf* OL, int ldc, int M, int Nout, int K)
{
    gemm_any<1>(AH, AL, lda, WH, WL, ldw, bias, bias2, nullptr, OH, OL, ldc, M, Nout, K);
}

#define GSA(sym, var, type) cudaGetSymbolAddress(&pv, sym); type* var = (type*)pv
#define CVTS(st, src, ldi, cols, total, H, L, ldo) \
    k_cvt<<<(int)(((total) / 4 + 255) / 256), 256, 0, st>>>(src, ldi, cols, total, H, L, ldo)
#define CVT(src, ldi, cols, total, H, L, ldo) CVTS(0, src, ldi, cols, total, H, L, ldo)

extern "C" void kernel_launch(void* const* d_in, const int* in_sizes, int n_in,
                              void* d_out, int out_size)
{
    const float* coords1 = (const float*)d_in[0];
    const float* coords2 = (const float*)d_in[2];
    const float* feats1  = (const float*)d_in[1];
    const float* feats2  = (const float*)d_in[3];
    const float* gW1 = (const float*)d_in[4];
    const float* gW2 = (const float*)d_in[5];
    const float* gW3 = (const float*)d_in[6];
    const float* Wq  = (const float*)d_in[7];  const float* bq  = (const float*)d_in[8];
    const float* Wk  = (const float*)d_in[9];  const float* bk  = (const float*)d_in[10];
    const float* Wv  = (const float*)d_in[11]; const float* bv  = (const float*)d_in[12];
    const float* Wo  = (const float*)d_in[13]; const float* bo  = (const float*)d_in[14];
    const float* Wm1 = (const float*)d_in[15]; const float* bm1 = (const float*)d_in[16];
    const float* Wm2 = (const float*)d_in[17]; const float* bm2 = (const float*)d_in[18];
    float* out = (float*)d_out;

    static int attr_set = 0;
    static cudaStream_t s2 = 0, s3 = 0, s4 = 0;
    static cudaEvent_t evf = 0, evk2 = 0, evk3 = 0, evG[2] = {0,0}, evA[2] = {0,0};
    if (!attr_set) {
        cudaFuncSetAttribute(mma_gemm<0,128,128>, cudaFuncAttributeMaxDynamicSharedMemorySize, SM_128_128);
        cudaFuncSetAttribute(mma_gemm<1,128,128>, cudaFuncAttributeMaxDynamicSharedMemorySize, SM_128_128);
        cudaFuncSetAttribute(mma_gemm<0,64,128>,  cudaFuncAttributeMaxDynamicSharedMemorySize, SM_64_128);
        cudaFuncSetAttribute(mma_gemm<1,64,128>,  cudaFuncAttributeMaxDynamicSharedMemorySize, SM_64_128);
        cudaFuncSetAttribute(mma_gemm<0,64,64>,   cudaFuncAttributeMaxDynamicSharedMemorySize, SM_64_64);
        cudaFuncSetAttribute(mma_gemm<1,64,64>,   cudaFuncAttributeMaxDynamicSharedMemorySize, SM_64_64);
        cudaFuncSetAttribute(k_flash, cudaFuncAttributeMaxDynamicSharedMemorySize, FA_SMEM);
        cudaStreamCreateWithFlags(&s2, cudaStreamNonBlocking);
        cudaStreamCreateWithFlags(&s3, cudaStreamNonBlocking);
        cudaStreamCreateWithFlags(&s4, cudaStreamNonBlocking);
        cudaEventCreateWithFlags(&evf, cudaEventDisableTiming);
        cudaEventCreateWithFlags(&evk2, cudaEventDisableTiming);
        cudaEventCreateWithFlags(&evk3, cudaEventDisableTiming);
        cudaEventCreateWithFlags(&evG[0], cudaEventDisableTiming);
        cudaEventCreateWithFlags(&evG[1], cudaEventDisableTiming);
        cudaEventCreateWithFlags(&evA[0], cudaEventDisableTiming);
        cudaEventCreateWithFlags(&evA[1], cudaEventDisableTiming);
        attr_set = 1;
    }

    void* pv;
    GSA(d_FE,  FEb, float);
    GSA(d_KN,  KNb, int);
    GSA(d_PQ,  PQp, float);
    GSA(d_MX,  MXp, float);
    GSA(d_STT, STp, float);
    GSA(d_BIAS, BP, float);
    GSA(d_OP,  OPp, float);
    GSA(d_ML,  MLp, float);
    GSA(d_AH,  AH, bf);    GSA(d_AL,  AL, bf);
    GSA(d_W1H, W1H, bf);   GSA(d_W1L, W1L, bf);
    GSA(d_W2H, W2H, bf);   GSA(d_W2L, W2L, bf);
    GSA(d_W3H, W3H, bf);   GSA(d_W3L, W3L, bf);
    GSA(d_WQH, WQH, bf);   GSA(d_WQL, WQL, bf);
    GSA(d_WKVH, WKVH, bf); GSA(d_WKVL, WKVL, bf);
    GSA(d_WOH, WOH, bf);   GSA(d_WOL, WOL, bf);
    GSA(d_WM1H, WM1H, bf); GSA(d_WM1L, WM1L, bf);
    GSA(d_WM2H, WM2H, bf); GSA(d_WM2L, WM2L, bf);
    GSA(d_QHH, QHH, bf);   GSA(d_QHL, QHL, bf);
    GSA(d_KVH, KVH, bf);   GSA(d_KVL, KVL, bf);
    GSA(d_VTH, VTH, bf);   GSA(d_VTL, VTL, bf);
    GSA(d_OHH, OHH, bf);   GSA(d_OHL, OHL, bf);
    float* SUM = STp;
    float* SSQ = STp + 4 * 1024;
    float* FE[2] = { FEb, FEb + (long)M4 * 256 };
    bf* F1H = AH;               bf* F1L = AL;
    bf* F2H = AH + (long)M4 * 512;
    bf* F2L = AL + (long)M4 * 512;

    const int EWB = 256;
    dim3 tb(32, 8);

    cudaEventRecord(evf, 0);
    cudaStreamWaitEvent(s2, evf, 0);
    cudaStreamWaitEvent(s3, evf, 0);
    cudaStreamWaitEvent(s4, evf, 0);
    k_knn<<<BB * NP, 256, 0, s3>>>(coords1, KNb);
    k_knn<<<BB * NP, 256, 0, s4>>>(coords2, KNb + (long)M4 * KNB);
    cudaEventRecord(evk2, s3);
    cudaEventRecord(evk3, s4);

    for (int i = 0; i < 2; i++) {
        long o1 = (long)i * 512 * 256, o2 = (long)i * 1024 * 256, o3 = (long)i * 256 * 1024;
        k_prepw_b<<<(256 * 256 + 255) / 256, 256, 0, s2>>>(gW1 + (long)i * 256 * 512,
                                                           W1H + o1, W1L + o1, 256, 256);
        k_prepw_b<<<(512 * 256 + 255) / 256, 256, 0, s2>>>(gW2 + (long)i * 512 * 512,
                                                           W2H + o2, W2L + o2, 512, 256);
        CVTS(s2, gW3 + (long)i * 256 * 1024, 1024, 1024, (long)256 * 1024,
             W3H + o3, W3L + o3, 1024);
        cudaEventRecord(evG[i], s2);
    }
    for (int i = 0; i < 2; i++) {
        long oq = (long)i * 65536, okv = (long)i * 512 * 256;
        long om1 = (long)i * 262144, om2 = (long)i * 131072;
        float* BQP = BP + i * 768;
        float* BKP = BQP + 256;
        float* BVP = BQP + 512;
        k_prepw_perm<<<256, 256, 0, s2>>>(Wq + oq, 0.125f, WQH + oq, WQL + oq, 0,
                                          bq + (long)i * 256, BQP);
        k_prepw_perm<<<256, 256, 0, s2>>>(Wk + oq, 1.f, WKVH + okv, WKVL + okv, 0,
                                          bk + (long)i * 256, BKP);
        k_prepw_perm<<<256, 256, 0, s2>>>(Wv + oq, 1.f, WKVH + okv, WKVL + okv, 256,
                                          bv + (long)i * 256, BVP);
        k_prepw_colperm<<<256, 256, 0, s2>>>(Wo + oq, WOH + oq, WOL + oq);
        CVTS(s2, Wm1 + om1, 512, 512, (long)262144, WM1H + om1, WM1L + om1, 512);
        CVTS(s2, Wm2 + om2, 512, 512, (long)131072, WM2H + om2, WM2L + om2, 512);
        cudaEventRecord(evA[i], s2);
    }

    k_transpose<<<dim3(NP / 32, 256 / 32, BB), tb>>>(feats1, FE[0], 256, NP);
    k_transpose<<<dim3(NP / 32, 256 / 32, BB), tb>>>(feats2, FE[1], 256, NP);

    const long R8 = M8, R4 = M4;
    int joined = 0;

    for (int li = 0; li < 4; li++) {
        int i = li / 2;
        if ((li & 1) == 0) {
            // ---------------- GCN layer i (both clouds batched) ----------------
            long o1 = (long)i * 512 * 256, o2 = (long)i * 1024 * 256, o3 = (long)i * 256 * 1024;
            cudaStreamWaitEvent(0, evG[i], 0);
            CVT(FEb, 256, 256, R8 * 256, AH, AL, 1024);
            gemm_f(AH, AL, 1024, W1H + o1, W1L + o1, 256, nullptr, PQp, 512, (int)R8, 512, 256);
            cudaMemsetAsync(STp, 0, sizeof(float) * 2 * 4 * 1024, 0);
            if (!joined) {
                cudaStreamWaitEvent(0, evk2, 0);
                cudaStreamWaitEvent(0, evk3, 0);
                joined = 1;
            }
            k_edge<<<(int)R8, 256>>>(PQp, KNb, MXp, SUM, SSQ, 256);
            k_norm_act_split<<<(int)((R8 * 256 + EWB - 1) / EWB), EWB>>>(
                MXp, 256, AH, AL, 1024, 256, SUM, SSQ, 256, R8, 1.f / 32768.f, 1);
            gemm_f(AH + 256, AL + 256, 1024, W2H + o2, W2L + o2, 256, nullptr,
                   PQp, 1024, (int)R8, 1024, 256);
            cudaMemsetAsync(STp, 0, sizeof(float) * 2 * 4 * 1024, 0);
            k_edge<<<(int)R8, 256>>>(PQp, KNb, MXp, SUM, SSQ, 512);
            k_norm_act_split<<<(int)((R8 * 512 + EWB - 1) / EWB), EWB>>>(
                MXp, 512, AH, AL, 1024, 512, SUM, SSQ, 512, R8, 1.f / 32768.f, 1);
            gemm_f(AH, AL, 1024, W3H + o3, W3L + o3, 1024, nullptr, MXp, 256, (int)R8, 256, 1024);
            cudaMemsetAsync(STp, 0, sizeof(float) * 2 * 4 * 1024, 0);
            k_colsum<<<(int)(R8 / 128), 256>>>(MXp, 256, SUM, SSQ, 256);
            k_norm_act<<<(int)((R8 * 256 + EWB - 1) / EWB), EWB>>>(
                MXp, 256, FEb, 256, SUM, SSQ, 256, R8, 1.f / (float)NP, 1);
        } else {
            // ---------------- cross-attention layer i ----------------
            long oq = (long)i * 65536, okv = (long)i * 512 * 256;
            long om1 = (long)i * 262144, om2 = (long)i * 131072;
            float* BQP = BP + i * 768;
            float* BKP = BQP + 256;
            float* BVP = BQP + 512;
            cudaStreamWaitEvent(0, evA[i], 0);
            for (int a = 0; a < 2; a++) {
                const float* f1p = FE[a];
                const float* f2p = FE[1 - a];
                CVT(f1p, 256, 256, R4 * 256, F1H, F1L, 512);
                gemm_s(F1H, F1L, 512, WQH + oq, WQL + oq, 256, BQP, nullptr,
                       QHH, QHL, 256, (int)R4, 256, 256);
                CVT(f2p, 256, 256, R4 * 256, F2H, F2L, 256);
                gemm_s(F2H, F2L, 256, WKVH + okv, WKVL + okv, 256, BKP, BVP,
                       KVH, KVL, 512, (int)R4, 512, 256);
                k_vtrans<<<dim3(8, NP / 32, BB), tb>>>(KVH, KVL, VTH, VTL);
                k_flash<<<dim3(16, 8, 2), 256, FA_SMEM>>>(QHH, QHL, KVH, KVL, VTH, VTL, OPp, MLp);
                k_fmerge<<<(int)((8L * NP * 32 + 255) / 256), 256>>>(OPp, MLp, OHH, OHL);
                gemm_s(OHH, OHL, 256, WOH + oq, WOL + oq, 256, bo + (long)i * 256, nullptr,
                       F1H + 256, F1L + 256, 512, (int)R4, 256, 256);
                gemm_f(F1H, F1L, 512, WM1H + om1, WM1L + om1, 512, bm1 + (long)i * 512,
                       PQp, 512, (int)R4, 512, 512);
                cudaMemsetAsync(STp, 0, sizeof(float) * 2 * 4 * 1024, 0);
                k_colsum<<<(int)(R4 / 128), 256>>>(PQp, 512, SUM, SSQ, 512);
                k_norm_act_split<<<(int)((R4 * 512 + EWB - 1) / EWB), EWB>>>(
                    PQp, 512, F1H, F1L, 512, 0, SUM, SSQ, 512, R4, 1.f / (float)NP, 2);
                gemm_f(F1H, F1L, 512, WM2H + om2, WM2L + om2, 512, bm2 + (long)i * 256,
                       FE[a], 256, (int)R4, 256, 512);
            }
        }
    }

    k_transpose<<<dim3(256 / 32, NP / 32, BB), tb>>>(FE[0], out, NP, 256);
    k_transpose<<<dim3(256 / 32, NP / 32, BB), tb>>>(FE[1], out + (long)M4 * 256, NP, 256);
}

// round 15
// speedup vs baseline: 1.0688x; 1.0244x over previous
#include <cuda_runtime.h>
#include <cuda_bf16.h>
#include <cstdint>

#define BB   2
#define NP   2048
#define KNB  16
#define EPSI 1e-5f
#define M4   (BB*NP)        // 4096
#define M8   (2*BB*NP)      // 8192

typedef __nv_bfloat16 bf;

// ======================= helpers =======================
__device__ __forceinline__ void split2(float x, bf& h, bf& l){
    h = __float2bfloat16(x);
    l = __float2bfloat16(x - __bfloat162float(h));
}
__device__ __forceinline__ uint32_t packbf(bf a, bf b){
    return ((uint32_t)__bfloat16_as_ushort(b) << 16) | (uint32_t)__bfloat16_as_ushort(a);
}
__device__ __forceinline__ uint32_t packsplit(float a, float b, uint32_t& lo){
    bf ha, la, hb, lb;
    split2(a, ha, la); split2(b, hb, lb);
    lo = packbf(la, lb);
    return packbf(ha, hb);
}

#define MMA16816(d, a, b) \
    asm volatile("mma.sync.aligned.m16n8k16.row.col.f32.bf16.bf16.f32 " \
        "{%0,%1,%2,%3}, {%4,%5,%6,%7}, {%8,%9}, {%0,%1,%2,%3};" \
        : "+f"((d)[0]), "+f"((d)[1]), "+f"((d)[2]), "+f"((d)[3]) \
        : "r"((a)[0]), "r"((a)[1]), "r"((a)[2]), "r"((a)[3]), \
          "r"((b)[0]), "r"((b)[1]))

#define LDSM4(r0, r1, r2, r3, a) \
    asm volatile("ldmatrix.sync.aligned.m8n8.x4.shared.b16 {%0,%1,%2,%3}, [%4];" \
        : "=r"(r0), "=r"(r1), "=r"(r2), "=r"(r3) : "r"(a))

#define CPA16(dst, src) \
    asm volatile("cp.async.cg.shared.global [%0], [%1], 16;" :: "r"(dst), "l"(src))
#define CP_COMMIT() asm volatile("cp.async.commit_group;" ::: "memory")
#define CP_WAIT1()  asm volatile("cp.async.wait_group 1;" ::: "memory")
#define CP_WAIT0()  asm volatile("cp.async.wait_group 0;" ::: "memory")

// ======================= device scratch =======================
__device__ __align__(16) float d_FE [M8*256];
__device__ int   d_KN [M8*KNB];
__device__ __align__(16) float d_PQ [M8*1024];
__device__ __align__(16) float d_MX [M8*512];
__device__ float d_STT[2*4*1024];
__device__ float d_BIAS[2*3*256];
__device__ __align__(16) bf d_AH [M8*1024];
__device__ __align__(16) bf d_AL [M8*1024];
__device__ __align__(16) bf d_W1H[2*512*256],  d_W1L[2*512*256];
__device__ __align__(16) bf d_W2H[2*1024*256], d_W2L[2*1024*256];
__device__ __align__(16) bf d_W3H[2*256*1024], d_W3L[2*256*1024];
__device__ __align__(16) bf d_WQH[2*256*256],  d_WQL[2*256*256];
__device__ __align__(16) bf d_WKVH[2*512*256], d_WKVL[2*512*256];
__device__ __align__(16) bf d_WOH[2*256*256],  d_WOL[2*256*256];
__device__ __align__(16) bf d_WM1H[2*512*512], d_WM1L[2*512*512];
__device__ __align__(16) bf d_WM2H[2*256*512], d_WM2L[2*256*512];
__device__ __align__(16) bf d_QHH[M4*256], d_QHL[M4*256];
__device__ __align__(16) bf d_KVH[M4*512], d_KVL[M4*512];
__device__ __align__(16) bf d_VTH[M4*256], d_VTL[M4*256];
__device__ __align__(16) bf d_OHH[M4*256], d_OHL[M4*256];
__device__ __align__(16) float d_OP[2L*8*NP*64];   // split-KV partial O
__device__ __align__(16) float d_ML[2L*8*NP*2];    // split-KV partial (m,l)

// ======================= transpose (fp32) =======================
__global__ void k_transpose(const float* __restrict__ in, float* __restrict__ out,
                            int R, int Cc)
{
    __shared__ float t[32][33];
    int b  = blockIdx.z;
    const float* ip = in  + (long)b * R * Cc;
    float*       op = out + (long)b * R * Cc;
    int c0 = blockIdx.x * 32, r0 = blockIdx.y * 32;
    for (int i = threadIdx.y; i < 32; i += 8)
        t[i][threadIdx.x] = ip[(long)(r0 + i) * Cc + c0 + threadIdx.x];
    __syncthreads();
    for (int i = threadIdx.y; i < 32; i += 8)
        op[(long)(c0 + i) * R + r0 + threadIdx.x] = t[threadIdx.x][i];
}

// ======================= kNN =======================
__global__ void __launch_bounds__(256) k_knn(const float* __restrict__ coords,
                                             int* __restrict__ knn)
{
    __shared__ float sx[NP], sy[NP], sz[NP], sd[NP];
    __shared__ float wv[8];
    __shared__ int   wi[8];
    int b = blockIdx.x / NP;
    int n = blockIdx.x % NP;
    const float* cb = coords + (long)b * 3 * NP;
    for (int j = threadIdx.x; j < NP; j += 256) {
        sx[j] = cb[j]; sy[j] = cb[NP + j]; sz[j] = cb[2 * NP + j];
    }
    __syncthreads();
    float xn = sx[n], yn = sy[n], zn = sz[n];
    float sqn = xn*xn + yn*yn + zn*zn;
    for (int j = threadIdx.x; j < NP; j += 256) {
        float x = sx[j], y = sy[j], z = sz[j];
        float d = sqn + (x*x + y*y + z*z) - 2.f * (xn*x + yn*y + zn*z);
        sd[j] = (j == n) ? 3.4e38f : d;
    }
    __syncthreads();
    int lane = threadIdx.x & 31, warp = threadIdx.x >> 5;
    for (int r = 0; r < KNB; r++) {
        float best = 3.0e38f; int bi = NP;
        for (int j = threadIdx.x; j < NP; j += 256) {
            float v = sd[j];
            if (v < best) { best = v; bi = j; }
        }
        #pragma unroll
        for (int off = 16; off; off >>= 1) {
            float ov = __shfl_down_sync(0xffffffffu, best, off);
            int   oi = __shfl_down_sync(0xffffffffu, bi,   off);
            if (ov < best || (ov == best && oi < bi)) { best = ov; bi = oi; }
        }
        if (lane == 0) { wv[warp] = best; wi[warp] = bi; }
        __syncthreads();
        if (threadIdx.x == 0) {
            float fb = wv[0]; int fi = wi[0];
            for (int w = 1; w < 8; w++)
                if (wv[w] < fb || (wv[w] == fb && wi[w] < fi)) { fb = wv[w]; fi = wi[w]; }
            knn[((long)b * NP + n) * KNB + r] = fi;
            sd[fi] = 3.4e38f;
        }
        __syncthreads();
    }
}

// ======================= HMMA GEMM (cp.async 2-stage + ldmatrix) ==============
// EPI 0: fp32 C. EPI 1: split bf16 hi/lo. EPI 2: fp32 C + fused column stats.
template <int EPI, int MR, int NR>
__global__ void __launch_bounds__(256) mma_gemm(
    const bf* __restrict__ AH, const bf* __restrict__ AL, long lda,
    const bf* __restrict__ WH, const bf* __restrict__ WL, long ldw,
    const float* __restrict__ bias, const float* __restrict__ bias2,
    float* __restrict__ C, bf* __restrict__ OH, bf* __restrict__ OL,
    float* __restrict__ gsum, float* __restrict__ gsq,
    int ldc, int K)
{
    constexpr int MT    = MR / 32;
    constexpr int NW    = NR / 4;
    constexpr int NT    = NW / 8;
    constexpr int NBL   = NW / 16;
    constexpr int ATILE = MR * 80;
    constexpr int WTILE = NR * 80;
    constexpr int STAGE = 2 * (ATILE + WTILE);

    extern __shared__ __align__(16) char smem[];
    uint32_t sbase = (uint32_t)__cvta_generic_to_shared(smem);

    int tid = threadIdx.x, wid = tid >> 5, lane = tid & 31;
    int g = lane >> 2, tg = lane & 3;
    int wm = (wid >> 2) * (MR / 2);
    int wn = (wid & 3) * NW;
    int lr = tid >> 2;
    int lq = tid & 3;

    uint32_t aoff = (uint32_t)((wm + (lane & 7) + ((lane >> 3) & 1) * 8) * 80 + (lane >> 4) * 16);
    uint32_t boff = (uint32_t)((wn + (lane >> 4) * 8 + (lane & 7)) * 80 + ((lane >> 3) & 1) * 16);

    long m0 = (long)blockIdx.y * MR;
    int  n0 = blockIdx.x * NR;
    const bf* pAH = AH + m0 * lda;
    const bf* pAL = AL + m0 * lda;
    const bf* pWH = WH + (long)n0 * ldw;
    const bf* pWL = WL + (long)n0 * ldw;

    float acc[MT][NT][4];
    #pragma unroll
    for (int mt = 0; mt < MT; mt++)
        #pragma unroll
        for (int nt = 0; nt < NT; nt++)
            #pragma unroll
            for (int q = 0; q < 4; q++) acc[mt][nt][q] = 0.f;

    int nch = K >> 5;

    {
        uint32_t st = sbase;
        #pragma unroll
        for (int it = 0; it < MR / 64; it++) {
            int r = lr + it * 64;
            uint32_t d = st + r * 80 + lq * 16;
            CPA16(d,         pAH + (long)r * lda + lq * 8);
            CPA16(d + ATILE, pAL + (long)r * lda + lq * 8);
        }
        #pragma unroll
        for (int it = 0; it < NR / 64; it++) {
            int r = lr + it * 64;
            uint32_t d = st + 2 * ATILE + r * 80 + lq * 16;
            CPA16(d,         pWH + (long)r * ldw + lq * 8);
            CPA16(d + WTILE, pWL + (long)r * ldw + lq * 8);
        }
        CP_COMMIT();
    }

    for (int c = 0; c < nch; c++) {
        if (c + 1 < nch) {
            long k0 = (long)(c + 1) << 5;
            uint32_t st = sbase + ((c + 1) & 1) * STAGE;
            #pragma unroll
            for (int it = 0; it < MR / 64; it++) {
                int r = lr + it * 64;
                uint32_t d = st + r * 80 + lq * 16;
                CPA16(d,         pAH + (long)r * lda + k0 + lq * 8);
                CPA16(d + ATILE, pAL + (long)r * lda + k0 + lq * 8);
            }
            #pragma unroll
            for (int it = 0; it < NR / 64; it++) {
                int r = lr + it * 64;
                uint32_t d = st + 2 * ATILE + r * 80 + lq * 16;
                CPA16(d,         pWH + (long)r * ldw + k0 + lq * 8);
                CPA16(d + WTILE, pWL + (long)r * ldw + k0 + lq * 8);
            }
            CP_COMMIT();
            CP_WAIT1();
        } else {
            CP_WAIT0();
        }
        __syncthreads();

        uint32_t stA = sbase + (c & 1) * STAGE;
        uint32_t aA = stA + aoff;
        uint32_t bA = stA + 2 * ATILE + boff;

        #pragma unroll
        for (int ks = 0; ks < 2; ks++) {
            int kbB = ks * 32;
            uint32_t ah[MT][4], al[MT][4];
            #pragma unroll
            for (int mt = 0; mt < MT; mt++) {
                uint32_t a0 = aA + mt * (16 * 80) + kbB;
                LDSM4(ah[mt][0], ah[mt][1], ah[mt][2], ah[mt][3], a0);
                LDSM4(al[mt][0], al[mt][1], al[mt][2], al[mt][3], a0 + ATILE);
            }
            uint32_t bh[NT][2], bl[NT][2];
            #pragma unroll
            for (int np2 = 0; np2 < NBL; np2++) {
                uint32_t b0 = bA + np2 * (16 * 80) + kbB;
                LDSM4(bh[np2*2][0], bh[np2*2][1], bh[np2*2+1][0], bh[np2*2+1][1], b0);
                LDSM4(bl[np2*2][0], bl[np2*2][1], bl[np2*2+1][0], bl[np2*2+1][1], b0 + WTILE);
            }
            #pragma unroll
            for (int mt = 0; mt < MT; mt++)
                #pragma unroll
                for (int nt = 0; nt < NT; nt++) {
                    MMA16816(acc[mt][nt], ah[mt], bh[nt]);
                    MMA16816(acc[mt][nt], ah[mt], bl[nt]);
                    MMA16816(acc[mt][nt], al[mt], bh[nt]);
                }
        }
        __syncthreads();
    }

    float csum[NT][2], csq[NT][2];
    if (EPI == 2) {
        #pragma unroll
        for (int nt = 0; nt < NT; nt++) {
            csum[nt][0] = 0.f; csum[nt][1] = 0.f;
            csq[nt][0] = 0.f;  csq[nt][1] = 0.f;
        }
    }

    #pragma unroll
    for (int mt = 0; mt < MT; mt++) {
        long row = m0 + wm + mt * 16 + g;
        #pragma unroll
        for (int nt = 0; nt < NT; nt++) {
            int col = n0 + wn + nt * 8 + tg * 2;
            float b0 = 0.f, b1 = 0.f;
            if (bias) {
                const float* bp = (bias2 && col >= 256) ? (bias2 - 256) : bias;
                b0 = __ldg(&bp[col]); b1 = __ldg(&bp[col + 1]);
            }
            float v0 = acc[mt][nt][0] + b0;
            float v1 = acc[mt][nt][1] + b1;
            float v2 = acc[mt][nt][2] + b0;
            float v3 = acc[mt][nt][3] + b1;
            if (EPI == 1) {
                uint32_t lo0, lo1;
                uint32_t hi0 = packsplit(v0, v1, lo0);
                uint32_t hi1 = packsplit(v2, v3, lo1);
                *(uint32_t*)(OH + row * (long)ldc + col)       = hi0;
                *(uint32_t*)(OL + row * (long)ldc + col)       = lo0;
                *(uint32_t*)(OH + (row + 8) * (long)ldc + col) = hi1;
                *(uint32_t*)(OL + (row + 8) * (long)ldc + col) = lo1;
            } else {
                *(float2*)(C + row * (long)ldc + col)       = make_float2(v0, v1);
                *(float2*)(C + (row + 8) * (long)ldc + col) = make_float2(v2, v3);
                if (EPI == 2) {
                    csum[nt][0] += v0 + v2; csq[nt][0] += v0 * v0 + v2 * v2;
                    csum[nt][1] += v1 + v3; csq[nt][1] += v1 * v1 + v3 * v3;
                }
            }
        }
    }

    if (EPI == 2) {
        int inst = (int)(m0 / NP);
        float* sb = gsum + inst * 1024;
        float* qb = gsq  + inst * 1024;
        #pragma unroll
        for (int nt = 0; nt < NT; nt++) {
            #pragma unroll
            for (int j = 0; j < 2; j++) {
                float s = csum[nt][j], q = csq[nt][j];
                s += __shfl_xor_sync(0xffffffffu, s, 4);
                s += __shfl_xor_sync(0xffffffffu, s, 8);
                s += __shfl_xor_sync(0xffffffffu, s, 16);
                q += __shfl_xor_sync(0xffffffffu, q, 4);
                q += __shfl_xor_sync(0xffffffffu, q, 8);
                q += __shfl_xor_sync(0xffffffffu, q, 16);
                if (g == 0) {
                    int col = n0 + wn + nt * 8 + tg * 2 + j;
                    atomicAdd(&sb[col], s);
                    atomicAdd(&qb[col], q);
                }
            }
        }
    }
}

#define SM_128_128 (2 * 2 * (128*80 + 128*80))
#define SM_64_128  (2 * 2 * (64*80  + 128*80))
#define SM_64_64   (2 * 2 * (64*80  + 64*80))

// ======================= fused flash attention (split-KV) =======================
#define FQ_B (128*144)
#define FK_B (64*144)
#define FA_SMEM (2*FQ_B + 4*FK_B)
__global__ void __launch_bounds__(256) k_flash(
    const bf* __restrict__ QH, const bf* __restrict__ QL,
    const bf* __restrict__ KVH, const bf* __restrict__ KVL,
    const bf* __restrict__ VH, const bf* __restrict__ VL,
    float* __restrict__ OP, float* __restrict__ ML)
{
    extern __shared__ __align__(16) char smem[];
    char* sQh = smem;
    char* sQl = smem + FQ_B;
    char* sKh = smem + 2 * FQ_B;
    char* sVh = sKh + 2 * FK_B;
    uint32_t sbase = (uint32_t)__cvta_generic_to_shared(smem);

    int tid = threadIdx.x, wid = tid >> 5, lane = tid & 31;
    int g = lane >> 2, tg = lane & 3;
    int z = blockIdx.y;
    int b = z >> 2, h = z & 3;
    long q0 = (long)blockIdx.x * 128;
    int wm = wid * 16;
    int part = blockIdx.z;
    int c0 = part * (NP / 128);
    int c1 = c0 + (NP / 128);

    uint32_t aoff = (uint32_t)((wm + (lane & 7) + ((lane >> 3) & 1) * 8) * 144 + (lane >> 4) * 16);
    uint32_t boff = (uint32_t)(((lane >> 4) * 8 + (lane & 7)) * 144 + ((lane >> 3) & 1) * 16);
    uint32_t qA = sbase + aoff;
    uint32_t kA = sbase + 2 * FQ_B + boff;
    uint32_t vA = kA + 2 * FK_B;

    const bf* pQH = QH + ((long)b * NP + q0) * 256 + h * 64;
    const bf* pQL = QL + ((long)b * NP + q0) * 256 + h * 64;

    #pragma unroll
    for (int it = 0; it < 4; it++) {
        int i = tid + it * 256;
        int r = i >> 3, q = i & 7;
        *(uint4*)(sQh + r * 144 + q * 16) = *(const uint4*)(pQH + (long)r * 256 + q * 8);
        *(uint4*)(sQl + r * 144 + q * 16) = *(const uint4*)(pQL + (long)r * 256 + q * 8);
    }

    float m0 = -3.4e38f, m1 = -3.4e38f, l0 = 0.f, l1 = 0.f;
    float acc[8][4];
    #pragma unroll
    for (int nt = 0; nt < 8; nt++)
        #pragma unroll
        for (int q = 0; q < 4; q++) acc[nt][q] = 0.f;

    for (int c = c0; c < c1; c++) {
        const bf* pKH = KVH + ((long)b * NP + c * 64) * 512 + h * 64;
        const bf* pKL = KVL + ((long)b * NP + c * 64) * 512 + h * 64;
        const bf* pVH = VH + (long)z * 64 * NP + c * 64;
        const bf* pVL = VL + (long)z * 64 * NP + c * 64;
        #pragma unroll
        for (int it = 0; it < 2; it++) {
            int i = tid + it * 256;
            int r = i >> 3, q = i & 7;
            *(uint4*)(sKh + r * 144 + q * 16)        = *(const uint4*)(pKH + (long)r * 512 + q * 8);
            *(uint4*)(sKh + FK_B + r * 144 + q * 16) = *(const uint4*)(pKL + (long)r * 512 + q * 8);
            *(uint4*)(sVh + r * 144 + q * 16)        = *(const uint4*)(pVH + (long)r * NP + q * 8);
            *(uint4*)(sVh + FK_B + r * 144 + q * 16) = *(const uint4*)(pVL + (long)r * NP + q * 8);
        }
        __syncthreads();

        float sacc[8][4];
        #pragma unroll
        for (int nt = 0; nt < 8; nt++)
            #pragma unroll
            for (int q = 0; q < 4; q++) sacc[nt][q] = 0.f;
        #pragma unroll
        for (int kk = 0; kk < 4; kk++) {
            int kbB = kk * 32;
            uint32_t aqh[4], aql[4];
            LDSM4(aqh[0], aqh[1], aqh[2], aqh[3], qA + kbB);
            LDSM4(aql[0], aql[1], aql[2], aql[3], qA + FQ_B + kbB);
            #pragma unroll
            for (int np2 = 0; np2 < 4; np2++) {
                uint32_t bh[2][2], bl[2][2];
                uint32_t b0 = kA + np2 * (16 * 144) + kbB;
                LDSM4(bh[0][0], bh[0][1], bh[1][0], bh[1][1], b0);
                LDSM4(bl[0][0], bl[0][1], bl[1][0], bl[1][1], b0 + FK_B);
                #pragma unroll
                for (int j = 0; j < 2; j++) {
                    MMA16816(sacc[np2*2+j], aqh, bh[j]);
                    MMA16816(sacc[np2*2+j], aqh, bl[j]);
                    MMA16816(sacc[np2*2+j], aql, bh[j]);
                }
            }
        }

        float rmax0 = -3.4e38f, rmax1 = -3.4e38f;
        #pragma unroll
        for (int nt = 0; nt < 8; nt++) {
            rmax0 = fmaxf(rmax0, fmaxf(sacc[nt][0], sacc[nt][1]));
            rmax1 = fmaxf(rmax1, fmaxf(sacc[nt][2], sacc[nt][3]));
        }
        rmax0 = fmaxf(rmax0, __shfl_xor_sync(0xffffffffu, rmax0, 1));
        rmax0 = fmaxf(rmax0, __shfl_xor_sync(0xffffffffu, rmax0, 2));
        rmax1 = fmaxf(rmax1, __shfl_xor_sync(0xffffffffu, rmax1, 1));
        rmax1 = fmaxf(rmax1, __shfl_xor_sync(0xffffffffu, rmax1, 2));
        float mn0 = fmaxf(m0, rmax0), mn1 = fmaxf(m1, rmax1);
        float al0 = __expf(m0 - mn0), al1 = __expf(m1 - mn1);
        m0 = mn0; m1 = mn1;

        float rs0 = 0.f, rs1 = 0.f;
        uint32_t pfh[4][4], pfl[4][4];
        #pragma unroll
        for (int nt = 0; nt < 8; nt++) {
            float p0 = __expf(sacc[nt][0] - mn0);
            float p1 = __expf(sacc[nt][1] - mn0);
            float p2 = __expf(sacc[nt][2] - mn1);
            float p3 = __expf(sacc[nt][3] - mn1);
            rs0 += p0 + p1; rs1 += p2 + p3;
            int kk = nt >> 1, base = (nt & 1) * 2;
            pfh[kk][base]     = packsplit(p0, p1, pfl[kk][base]);
            pfh[kk][base + 1] = packsplit(p2, p3, pfl[kk][base + 1]);
        }
        rs0 += __shfl_xor_sync(0xffffffffu, rs0, 1);
        rs0 += __shfl_xor_sync(0xffffffffu, rs0, 2);
        rs1 += __shfl_xor_sync(0xffffffffu, rs1, 1);
        rs1 += __shfl_xor_sync(0xffffffffu, rs1, 2);
        l0 = l0 * al0 + rs0; l1 = l1 * al1 + rs1;
        #pragma unroll
        for (int nt = 0; nt < 8; nt++) {
            acc[nt][0] *= al0; acc[nt][1] *= al0;
            acc[nt][2] *= al1; acc[nt][3] *= al1;
        }

        #pragma unroll
        for (int kk = 0; kk < 4; kk++) {
            int kbB = kk * 32;
            #pragma unroll
            for (int np2 = 0; np2 < 4; np2++) {
                uint32_t bh[2][2], bl[2][2];
                uint32_t b0 = vA + np2 * (16 * 144) + kbB;
                LDSM4(bh[0][0], bh[0][1], bh[1][0], bh[1][1], b0);
                LDSM4(bl[0][0], bl[0][1], bl[1][0], bl[1][1], b0 + FK_B);
                #pragma unroll
                for (int j = 0; j < 2; j++) {
                    MMA16816(acc[np2*2+j], pfh[kk], bh[j]);
                    MMA16816(acc[np2*2+j], pfh[kk], bl[j]);
                    MMA16816(acc[np2*2+j], pfl[kk], bh[j]);
                }
            }
        }
        __syncthreads();
    }

    long rbase = ((long)part * 8 + z) * NP + q0 + wm;
    float* pO = OP + rbase * 64;
    #pragma unroll
    for (int nt = 0; nt < 8; nt++) {
        int col = nt * 8 + tg * 2;
        *(float2*)(pO + (long)g * 64 + col)       = make_float2(acc[nt][0], acc[nt][1]);
        *(float2*)(pO + (long)(g + 8) * 64 + col) = make_float2(acc[nt][2], acc[nt][3]);
    }
    if (tg == 0) {
        ML[(rbase + g) * 2]         = m0;
        ML[(rbase + g) * 2 + 1]     = l0;
        ML[(rbase + g + 8) * 2]     = m1;
        ML[(rbase + g + 8) * 2 + 1] = l1;
    }
}

// merge two KV-half partials -> bf16 hi/lo (Wo-input layout)
__global__ void __launch_bounds__(256) k_fmerge(
    const float* __restrict__ OP, const float* __restrict__ ML,
    bf* __restrict__ OH, bf* __restrict__ OL)
{
    long i = (long)blockIdx.x * blockDim.x + threadIdx.x;
    if (i >= (long)8 * NP * 32) return;
    int  c2 = (int)(i & 31) * 2;
    long zn = i >> 5;
    int  n  = (int)(zn & (NP - 1));
    int  z  = (int)(zn >> 11);
    float m0 = ML[zn * 2],                     l0 = ML[zn * 2 + 1];
    float m1 = ML[((long)8 * NP + zn) * 2],    l1 = ML[((long)8 * NP + zn) * 2 + 1];
    float m  = fmaxf(m0, m1);
    float a0 = __expf(m0 - m), a1 = __expf(m1 - m);
    float inv = 1.f / (l0 * a0 + l1 * a1);
    long o0 = zn * 64 + c2;
    float2 v0 = *(const float2*)(OP + o0);
    float2 v1 = *(const float2*)(OP + (long)8 * NP * 64 + o0);
    float x = (v0.x * a0 + v1.x * a1) * inv;
    float y = (v0.y * a0 + v1.y * a1) * inv;
    uint32_t lo;
    uint32_t hi = packsplit(x, y, lo);
    int b = z >> 2, h = z & 3;
    long od = ((long)b * NP + n) * 256 + h * 64 + c2;
    *(uint32_t*)(OH + od) = hi;
    *(uint32_t*)(OL + od) = lo;
}

// ======================= fp32 -> bf16 hi/lo =======================
__global__ void k_cvt(const float* __restrict__ src, long ldi, int cols, long total,
                      bf* __restrict__ H, bf* __restrict__ L, long ldo)
{
    long i = ((long)blockIdx.x * blockDim.x + threadIdx.x) * 4;
    if (i >= total) return;
    long r = i / cols; int c = (int)(i - r * cols);
    float4 v = *(const float4*)(src + r * ldi + c);
    uint32_t lo0, lo1;
    uint32_t hi0 = packsplit(v.x, v.y, lo0);
    uint32_t hi1 = packsplit(v.z, v.w, lo1);
    *(uint2*)(H + r * ldo + c) = make_uint2(hi0, hi1);
    *(uint2*)(L + r * ldo + c) = make_uint2(lo0, lo1);
}

__global__ void k_prepw_b(const float* __restrict__ W, bf* __restrict__ H,
                          bf* __restrict__ L, int O, int Ci)
{
    long i = blockIdx.x * (long)blockDim.x + threadIdx.x;
    if (i >= (long)O * Ci) return;
    int o = (int)(i / Ci), c = (int)(i % Ci);
    float a  = W[(long)o * 2 * Ci + c];
    float bq = W[(long)o * 2 * Ci + Ci + c];
    bf h, l;
    split2(a - bq, h, l);
    H[(long)o * Ci + c] = h; L[(long)o * Ci + c] = l;
    split2(bq, h, l);
    H[((long)O + o) * Ci + c] = h; L[((long)O + o) * Ci + c] = l;
}

__global__ void k_prepw_perm(const float* __restrict__ W, float scale,
                             bf* __restrict__ H, bf* __restrict__ L, int roff,
                             const float* __restrict__ bin, float* __restrict__ bout)
{
    int i = blockIdx.x * blockDim.x + threadIdx.x;
    if (i >= 256 * 256) return;
    int o = i >> 8, c = i & 255;
    int op = (o & 3) * 64 + (o >> 2);
    bf h, l;
    split2(W[i] * scale, h, l);
    H[(long)(roff + op) * 256 + c] = h;
    L[(long)(roff + op) * 256 + c] = l;
    if (c == 0) bout[op] = bin[o] * scale;
}

__global__ void k_prepw_colperm(const float* __restrict__ W,
                                bf* __restrict__ H, bf* __restrict__ L)
{
    int i = blockIdx.x * blockDim.x + threadIdx.x;
    if (i >= 256 * 256) return;
    int o = i >> 8, oc = i & 255;
    int c = (oc & 63) * 4 + (oc >> 6);
    bf h, l;
    split2(W[o * 256 + c], h, l);
    H[i] = h; L[i] = l;
}

__global__ void k_vtrans(const bf* __restrict__ SH, const bf* __restrict__ SL,
                         bf* __restrict__ DH, bf* __restrict__ DL)
{
    __shared__ uint16_t th[32][34], tl[32][34];
    int b = blockIdx.z;
    int hc0 = blockIdx.x * 32;
    int n0  = blockIdx.y * 32;
    int tx = threadIdx.x, ty = threadIdx.y;
    for (int i = ty; i < 32; i += 8) {
        long src = ((long)b * NP + n0 + i) * 512 + 256 + hc0 + tx;
        th[i][tx] = ((const uint16_t*)SH)[src];
        tl[i][tx] = ((const uint16_t*)SL)[src];
    }
    __syncthreads();
    for (int i = ty; i < 32; i += 8) {
        int hc = hc0 + i;
        int h = hc >> 6, dd = hc & 63;
        long dst = (((long)b * 4 + h) * 64 + dd) * NP + n0 + tx;
        ((uint16_t*)DH)[dst] = th[tx][i];
        ((uint16_t*)DL)[dst] = tl[tx][i];
    }
}

// ======================= edge gather: max + stats =======================
__global__ void __launch_bounds__(256) k_edge(const float* __restrict__ PQ,
                                              const int* __restrict__ knn,
                                              float* __restrict__ mx,
                                              float* __restrict__ ssum,
                                              float* __restrict__ sssq,
                                              int Co)
{
    __shared__ long nbb[KNB];
    long bn = blockIdx.x;
    int  inst = (int)(bn / NP);
    if (threadIdx.x < KNB) {
        int nb = knn[bn * KNB + threadIdx.x];
        nbb[threadIdx.x] = ((long)inst * NP + nb) * (2 * Co) + Co;
    }
    __syncthreads();
    const float* Prow = PQ + bn * (2 * Co);
    for (int o = threadIdx.x; o < Co; o += 256) {
        float p = Prow[o];
        float mv = -3.4e38f, s = 0.f, ss = 0.f;
        #pragma unroll
        for (int k2 = 0; k2 < KNB; k2++) {
            float v = p + PQ[nbb[k2] + o];
            mv = fmaxf(mv, v); s += v; ss += v * v;
        }
        mx[bn * Co + o] = mv;
        atomicAdd(&ssum[inst * 1024 + o], s);
        atomicAdd(&sssq[inst * 1024 + o], ss);
    }
}

// ======================= normalize + act -> fp32 =======================
__global__ void k_norm_act(const float* __restrict__ X, int ldx,
                           float* __restrict__ Y, int ldy,
                           const float* __restrict__ ssum,
                           const float* __restrict__ sssq,
                           int Co, long rows, float invcnt, int act)
{
    long i = blockIdx.x * (long)blockDim.x + threadIdx.x;
    if (i >= rows * Co) return;
    int  o  = (int)(i % Co);
    long rn = i / Co;
    int  inst = (int)(rn / NP);
    float mu  = ssum[inst * 1024 + o] * invcnt;
    float var = sssq[inst * 1024 + o] * invcnt - mu * mu;
    float v = (X[rn * ldx + o] - mu) * rsqrtf(var + EPSI);
    if (act == 1) v = (v >= 0.f) ? v : 0.2f * v;
    else          v = (v > 0.f)  ? v : 0.f;
    Y[rn * ldy + o] = v;
}

// ======================= normalize + act -> bf16 hi/lo =======================
__global__ void k_norm_act_split(const float* __restrict__ X, int ldx,
                                 bf* __restrict__ H, bf* __restrict__ L,
                                 int ldy, int offy,
                                 const float* __restrict__ ssum,
                                 const float* __restrict__ sssq,
                                 int Co, long rows, float invcnt, int act)
{
    long i = blockIdx.x * (long)blockDim.x + threadIdx.x;
    if (i >= rows * Co) return;
    int  o  = (int)(i % Co);
    long rn = i / Co;
    int  inst = (int)(rn / NP);
    float mu  = ssum[inst * 1024 + o] * invcnt;
    float var = sssq[inst * 1024 + o] * invcnt - mu * mu;
    float v = (X[rn * ldx + o] - mu) * rsqrtf(var + EPSI);
    if (act == 1) v = (v >= 0.f) ? v : 0.2f * v;
    else          v = (v > 0.f)  ? v : 0.f;
    bf h, l;
    split2(v, h, l);
    H[rn * ldy + offy + o] = h;
    L[rn * ldy + offy + o] = l;
}

// ======================= host =======================
template <int EPI>
static void gemm_any(const bf* AH, const bf* AL, long lda,
                     const bf* WH, const bf* WL, long ldw,
                     const float* bias, const float* bias2,
                     float* C, bf* OH, bf* OL,
                     float* gsum, float* gsq, int ldc,
                     int M, int Nout, int K)
{
    long ctas = (long)(M / 128) * (Nout / 128);
    if (ctas >= 200) {
        dim3 g(Nout / 128, M / 128);
        mma_gemm<EPI, 128, 128><<<g, 256, SM_128_128>>>(AH, AL, lda, WH, WL, ldw,
            bias, bias2, C, OH, OL, gsum, gsq, ldc, K);
    } else if (ctas * 2 >= 200) {
        dim3 g(Nout / 128, M / 64);
        mma_gemm<EPI, 64, 128><<<g, 256, SM_64_128>>>(AH, AL, lda, WH, WL, ldw,
            bias, bias2, C, OH, OL, gsum, gsq, ldc, K);
    } else {
        dim3 g(Nout / 64, M / 64);
        mma_gemm<EPI, 64, 64><<<g, 256, SM_64_64>>>(AH, AL, lda, WH, WL, ldw,
            bias, bias2, C, OH, OL, gsum, gsq, ldc, K);
    }
}
static void gemm_f(const bf* AH, const bf* AL, long lda,
                   const bf* WH, const bf* WL, long ldw,
                   const float* bias, float* C, int ldc, int M, int Nout, int K)
{
    gemm_any<0>(AH, AL, lda, WH, WL, ldw, bias, nullptr, C, nullptr, nullptr,
                nullptr, nullptr, ldc, M, Nout, K);
}
static void gemm_fs(const bf* AH, const bf* AL, long lda,
                    const bf* WH, const bf* WL, long ldw,
                    const float* bias, float* C, float* gsum, float* gsq,
                    int ldc, int M, int Nout, int K)
{
    gemm_any<2>(AH, AL, lda, WH, WL, ldw, bias, nullptr, C, nullptr, nullptr,
                gsum, gsq, ldc, M, Nout, K);
}
static void gemm_s(const bf* AH, const bf* AL, long lda,
                   const bf* WH, const bf* WL, long ldw,
                   const float* bias, const float* bias2,
                   bf* OH, bf* OL, int ldc, int M, int Nout, int K)
{
    gemm_any<1>(AH, AL, lda, WH, WL, ldw, bias, bias2, nullptr, OH, OL,
                nullptr, nullptr, ldc, M, Nout, K);
}

#define GSA(sym, var, type) cudaGetSymbolAddress(&pv, sym); type* var = (type*)pv
#define CVTS(st, src, ldi, cols, total, H, L, ldo) \
    k_cvt<<<(int)(((total) / 4 + 255) / 256), 256, 0, st>>>(src, ldi, cols, total, H, L, ldo)
#define CVT(src, ldi, cols, total, H, L, ldo) CVTS(0, src, ldi, cols, total, H, L, ldo)

extern "C" void kernel_launch(void* const* d_in, const int* in_sizes, int n_in,
                              void* d_out, int out_size)
{
    const float* coords1 = (const float*)d_in[0];
    const float* coords2 = (const float*)d_in[2];
    const float* feats1  = (const float*)d_in[1];
    const float* feats2  = (const float*)d_in[3];
    const float* gW1 = (const float*)d_in[4];
    const float* gW2 = (const float*)d_in[5];
    const float* gW3 = (const float*)d_in[6];
    const float* Wq  = (const float*)d_in[7];  const float* bq  = (const float*)d_in[8];
    const float* Wk  = (const float*)d_in[9];  const float* bk  = (const float*)d_in[10];
    const float* Wv  = (const float*)d_in[11]; const float* bv  = (const float*)d_in[12];
    const float* Wo  = (const float*)d_in[13]; const float* bo  = (const float*)d_in[14];
    const float* Wm1 = (const float*)d_in[15]; const float* bm1 = (const float*)d_in[16];
    const float* Wm2 = (const float*)d_in[17]; const float* bm2 = (const float*)d_in[18];
    float* out = (float*)d_out;

    static int attr_set = 0;
    static cudaStream_t s2 = 0, s3 = 0, s4 = 0;
    static cudaEvent_t evf = 0, evk2 = 0, evk3 = 0, evG[2] = {0,0}, evA[2] = {0,0};
    if (!attr_set) {
        cudaFuncSetAttribute(mma_gemm<0,128,128>, cudaFuncAttributeMaxDynamicSharedMemorySize, SM_128_128);
        cudaFuncSetAttribute(mma_gemm<1,128,128>, cudaFuncAttributeMaxDynamicSharedMemorySize, SM_128_128);
        cudaFuncSetAttribute(mma_gemm<2,128,128>, cudaFuncAttributeMaxDynamicSharedMemorySize, SM_128_128);
        cudaFuncSetAttribute(mma_gemm<0,64,128>,  cudaFuncAttributeMaxDynamicSharedMemorySize, SM_64_128);
        cudaFuncSetAttribute(mma_gemm<1,64,128>,  cudaFuncAttributeMaxDynamicSharedMemorySize, SM_64_128);
        cudaFuncSetAttribute(mma_gemm<2,64,128>,  cudaFuncAttributeMaxDynamicSharedMemorySize, SM_64_128);
        cudaFuncSetAttribute(mma_gemm<0,64,64>,   cudaFuncAttributeMaxDynamicSharedMemorySize, SM_64_64);
        cudaFuncSetAttribute(mma_gemm<1,64,64>,   cudaFuncAttributeMaxDynamicSharedMemorySize, SM_64_64);
        cudaFuncSetAttribute(mma_gemm<2,64,64>,   cudaFuncAttributeMaxDynamicSharedMemorySize, SM_64_64);
        cudaFuncSetAttribute(k_flash, cudaFuncAttributeMaxDynamicSharedMemorySize, FA_SMEM);
        cudaStreamCreateWithFlags(&s2, cudaStreamNonBlocking);
        cudaStreamCreateWithFlags(&s3, cudaStreamNonBlocking);
        cudaStreamCreateWithFlags(&s4, cudaStreamNonBlocking);
        cudaEventCreateWithFlags(&evf, cudaEventDisableTiming);
        cudaEventCreateWithFlags(&evk2, cudaEventDisableTiming);
        cudaEventCreateWithFlags(&evk3, cudaEventDisableTiming);
        cudaEventCreateWithFlags(&evG[0], cudaEventDisableTiming);
        cudaEventCreateWithFlags(&evG[1], cudaEventDisableTiming);
        cudaEventCreateWithFlags(&evA[0], cudaEventDisableTiming);
        cudaEventCreateWithFlags(&evA[1], cudaEventDisableTiming);
        attr_set = 1;
    }

    void* pv;
    GSA(d_FE,  FEb, float);
    GSA(d_KN,  KNb, int);
    GSA(d_PQ,  PQp, float);
    GSA(d_MX,  MXp, float);
    GSA(d_STT, STp, float);
    GSA(d_BIAS, BP, float);
    GSA(d_OP,  OPp, float);
    GSA(d_ML,  MLp, float);
    GSA(d_AH,  AH, bf);    GSA(d_AL,  AL, bf);
    GSA(d_W1H, W1H, bf);   GSA(d_W1L, W1L, bf);
    GSA(d_W2H, W2H, bf);   GSA(d_W2L, W2L, bf);
    GSA(d_W3H, W3H, bf);   GSA(d_W3L, W3L, bf);
    GSA(d_WQH, WQH, bf);   GSA(d_WQL, WQL, bf);
    GSA(d_WKVH, WKVH, bf); GSA(d_WKVL, WKVL, bf);
    GSA(d_WOH, WOH, bf);   GSA(d_WOL, WOL, bf);
    GSA(d_WM1H, WM1H, bf); GSA(d_WM1L, WM1L, bf);
    GSA(d_WM2H, WM2H, bf); GSA(d_WM2L, WM2L, bf);
    GSA(d_QHH, QHH, bf);   GSA(d_QHL, QHL, bf);
    GSA(d_KVH, KVH, bf);   GSA(d_KVL, KVL, bf);
    GSA(d_VTH, VTH, bf);   GSA(d_VTL, VTL, bf);
    GSA(d_OHH, OHH, bf);   GSA(d_OHL, OHL, bf);
    float* SUM = STp;
    float* SSQ = STp + 4 * 1024;
    float* FE[2] = { FEb, FEb + (long)M4 * 256 };
    bf* F1H = AH;               bf* F1L = AL;
    bf* F2H = AH + (long)M4 * 512;
    bf* F2L = AL + (long)M4 * 512;

    const int EWB = 256;
    dim3 tb(32, 8);

    cudaEventRecord(evf, 0);
    cudaStreamWaitEvent(s2, evf, 0);
    cudaStreamWaitEvent(s3, evf, 0);
    cudaStreamWaitEvent(s4, evf, 0);
    k_knn<<<BB * NP, 256, 0, s3>>>(coords1, KNb);
    k_knn<<<BB * NP, 256, 0, s4>>>(coords2, KNb + (long)M4 * KNB);
    cudaEventRecord(evk2, s3);
    cudaEventRecord(evk3, s4);

    for (int i = 0; i < 2; i++) {
        long o1 = (long)i * 512 * 256, o2 = (long)i * 1024 * 256, o3 = (long)i * 256 * 1024;
        k_prepw_b<<<(256 * 256 + 255) / 256, 256, 0, s2>>>(gW1 + (long)i * 256 * 512,
                                                           W1H + o1, W1L + o1, 256, 256);
        k_prepw_b<<<(512 * 256 + 255) / 256, 256, 0, s2>>>(gW2 + (long)i * 512 * 512,
                                                           W2H + o2, W2L + o2, 512, 256);
        CVTS(s2, gW3 + (long)i * 256 * 1024, 1024, 1024, (long)256 * 1024,
             W3H + o3, W3L + o3, 1024);
        cudaEventRecord(evG[i], s2);
    }
    for (int i = 0; i < 2; i++) {
        long oq = (long)i * 65536, okv = (long)i * 512 * 256;
        long om1 = (long)i * 262144, om2 = (long)i * 131072;
        float* BQP = BP + i * 768;
        float* BKP = BQP + 256;
        float* BVP = BQP + 512;
        k_prepw_perm<<<256, 256, 0, s2>>>(Wq + oq, 0.125f, WQH + oq, WQL + oq, 0,
                                          bq + (long)i * 256, BQP);
        k_prepw_perm<<<256, 256, 0, s2>>>(Wk + oq, 1.f, WKVH + okv, WKVL + okv, 0,
                                          bk + (long)i * 256, BKP);
        k_prepw_perm<<<256, 256, 0, s2>>>(Wv + oq, 1.f, WKVH + okv, WKVL + okv, 256,
                                          bv + (long)i * 256, BVP);
        k_prepw_colperm<<<256, 256, 0, s2>>>(Wo + oq, WOH + oq, WOL + oq);
        CVTS(s2, Wm1 + om1, 512, 512, (long)262144, WM1H + om1, WM1L + om1, 512);
        CVTS(s2, Wm2 + om2, 512, 512, (long)131072, WM2H + om2, WM2L + om2, 512);
        cudaEventRecord(evA[i], s2);
    }

    k_transpose<<<dim3(NP / 32, 256 / 32, BB), tb>>>(feats1, FE[0], 256, NP);
    k_transpose<<<dim3(NP / 32, 256 / 32, BB), tb>>>(feats2, FE[1], 256, NP);

    const long R8 = M8, R4 = M4;
    int joined = 0;

    for (int li = 0; li < 4; li++) {
        int i = li / 2;
        if ((li & 1) == 0) {
            // ---------------- GCN layer i (both clouds batched) ----------------
            long o1 = (long)i * 512 * 256, o2 = (long)i * 1024 * 256, o3 = (long)i * 256 * 1024;
            cudaStreamWaitEvent(0, evG[i], 0);
            CVT(FEb, 256, 256, R8 * 256, AH, AL, 1024);
            gemm_f(AH, AL, 1024, W1H + o1, W1L + o1, 256, nullptr, PQp, 512, (int)R8, 512, 256);
            cudaMemsetAsync(STp, 0, sizeof(float) * 2 * 4 * 1024, 0);
            if (!joined) {
                cudaStreamWaitEvent(0, evk2, 0);
                cudaStreamWaitEvent(0, evk3, 0);
                joined = 1;
            }
            k_edge<<<(int)R8, 256>>>(PQp, KNb, MXp, SUM, SSQ, 256);
            k_norm_act_split<<<(int)((R8 * 256 + EWB - 1) / EWB), EWB>>>(
                MXp, 256, AH, AL, 1024, 256, SUM, SSQ, 256, R8, 1.f / 32768.f, 1);
            gemm_f(AH + 256, AL + 256, 1024, W2H + o2, W2L + o2, 256, nullptr,
                   PQp, 1024, (int)R8, 1024, 256);
            cudaMemsetAsync(STp, 0, sizeof(float) * 2 * 4 * 1024, 0);
            k_edge<<<(int)R8, 256>>>(PQp, KNb, MXp, SUM, SSQ, 512);
            k_norm_act_split<<<(int)((R8 * 512 + EWB - 1) / EWB), EWB>>>(
                MXp, 512, AH, AL, 1024, 512, SUM, SSQ, 512, R8, 1.f / 32768.f, 1);
            cudaMemsetAsync(STp, 0, sizeof(float) * 2 * 4 * 1024, 0);
            gemm_fs(AH, AL, 1024, W3H + o3, W3L + o3, 1024, nullptr,
                    MXp, SUM, SSQ, 256, (int)R8, 256, 1024);
            k_norm_act<<<(int)((R8 * 256 + EWB - 1) / EWB), EWB>>>(
                MXp, 256, FEb, 256, SUM, SSQ, 256, R8, 1.f / (float)NP, 1);
        } else {
            // ---------------- cross-attention layer i ----------------
            long oq = (long)i * 65536, okv = (long)i * 512 * 256;
            long om1 = (long)i * 262144, om2 = (long)i * 131072;
            float* BQP = BP + i * 768;
            float* BKP = BQP + 256;
            float* BVP = BQP + 512;
            cudaStreamWaitEvent(0, evA[i], 0);
            for (int a = 0; a < 2; a++) {
                const float* f1p = FE[a];
                const float* f2p = FE[1 - a];
                CVT(f1p, 256, 256, R4 * 256, F1H, F1L, 512);
                gemm_s(F1H, F1L, 512, WQH + oq, WQL + oq, 256, BQP, nullptr,
                       QHH, QHL, 256, (int)R4, 256, 256);
                CVT(f2p, 256, 256, R4 * 256, F2H, F2L, 256);
                gemm_s(F2H, F2L, 256, WKVH + okv, WKVL + okv, 256, BKP, BVP,
                       KVH, KVL, 512, (int)R4, 512, 256);
                k_vtrans<<<dim3(8, NP / 32, BB), tb>>>(KVH, KVL, VTH, VTL);
                k_flash<<<dim3(16, 8, 2), 256, FA_SMEM>>>(QHH, QHL, KVH, KVL, VTH, VTL, OPp, MLp);
                k_fmerge<<<(int)((8L * NP * 32 + 255) / 256), 256>>>(OPp, MLp, OHH, OHL);
                gemm_s(OHH, OHL, 256, WOH + oq, WOL + oq, 256, bo + (long)i * 256, nullptr,
                       F1H + 256, F1L + 256, 512, (int)R4, 256, 256);
                cudaMemsetAsync(STp, 0, sizeof(float) * 2 * 4 * 1024, 0);
                gemm_fs(F1H, F1L, 512, WM1H + om1, WM1L + om1, 512, bm1 + (long)i * 512,
                        PQp, SUM, SSQ, 512, (int)R4, 512, 512);
                k_norm_act_split<<<(int)((R4 * 512 + EWB - 1) / EWB), EWB>>>(
                    PQp, 512, F1H, F1L, 512, 0, SUM, SSQ, 512, R4, 1.f / (float)NP, 2);
                gemm_f(F1H, F1L, 512, WM2H + om2, WM2L + om2, 512, bm2 + (long)i * 256,
                       FE[a], 256, (int)R4, 256, 512);
            }
        }
    }

    k_transpose<<<dim3(256 / 32, NP / 32, BB), tb>>>(FE[0], out, NP, 256);
    k_transpose<<<dim3(256 / 32, NP / 32, BB), tb>>>(FE[1], out + (long)M4 * 256, NP, 256);
}

// round 16
// speedup vs baseline: 1.0748x; 1.0056x over previous
#include <cuda_runtime.h>
#include <cuda_bf16.h>
#include <cstdint>

#define BB   2
#define NP   2048
#define KNB  16
#define EPSI 1e-5f
#define M4   (BB*NP)        // 4096
#define M8   (2*BB*NP)      // 8192

typedef __nv_bfloat16 bf;

// ======================= helpers =======================
__device__ __forceinline__ void split2(float x, bf& h, bf& l){
    h = __float2bfloat16(x);
    l = __float2bfloat16(x - __bfloat162float(h));
}
__device__ __forceinline__ uint32_t packbf(bf a, bf b){
    return ((uint32_t)__bfloat16_as_ushort(b) << 16) | (uint32_t)__bfloat16_as_ushort(a);
}
__device__ __forceinline__ uint32_t packsplit(float a, float b, uint32_t& lo){
    bf ha, la, hb, lb;
    split2(a, ha, la); split2(b, hb, lb);
    lo = packbf(la, lb);
    return packbf(ha, hb);
}

#define MMA16816(d, a, b) \
    asm volatile("mma.sync.aligned.m16n8k16.row.col.f32.bf16.bf16.f32 " \
        "{%0,%1,%2,%3}, {%4,%5,%6,%7}, {%8,%9}, {%0,%1,%2,%3};" \
        : "+f"((d)[0]), "+f"((d)[1]), "+f"((d)[2]), "+f"((d)[3]) \
        : "r"((a)[0]), "r"((a)[1]), "r"((a)[2]), "r"((a)[3]), \
          "r"((b)[0]), "r"((b)[1]))

#define LDSM4(r0, r1, r2, r3, a) \
    asm volatile("ldmatrix.sync.aligned.m8n8.x4.shared.b16 {%0,%1,%2,%3}, [%4];" \
        : "=r"(r0), "=r"(r1), "=r"(r2), "=r"(r3) : "r"(a))

#define CPA16(dst, src) \
    asm volatile("cp.async.cg.shared.global [%0], [%1], 16;" :: "r"(dst), "l"(src))
#define CP_COMMIT() asm volatile("cp.async.commit_group;" ::: "memory")
#define CP_WAIT1()  asm volatile("cp.async.wait_group 1;" ::: "memory")
#define CP_WAIT0()  asm volatile("cp.async.wait_group 0;" ::: "memory")

// ======================= device scratch =======================
__device__ __align__(16) float d_FE [M8*256];
__device__ int   d_KN [M8*KNB];
__device__ __align__(16) float d_PQ [M8*1024];
__device__ __align__(16) float d_MX [M8*512];
__device__ float d_STT[2*4*1024];
__device__ float d_BIAS[2*3*256];
__device__ __align__(16) bf d_AH [M8*1024];
__device__ __align__(16) bf d_AL [M8*1024];
__device__ __align__(16) bf d_FSH[M8*256], d_FSL[M8*256];    // split copy of FE
__device__ __align__(16) bf d_W1H[2*512*256],  d_W1L[2*512*256];
__device__ __align__(16) bf d_W2H[2*1024*256], d_W2L[2*1024*256];
__device__ __align__(16) bf d_W3H[2*256*1024], d_W3L[2*256*1024];
__device__ __align__(16) bf d_WQH[2*256*256],  d_WQL[2*256*256];
__device__ __align__(16) bf d_WKVH[2*512*256], d_WKVL[2*512*256];
__device__ __align__(16) bf d_WOH[2*256*256],  d_WOL[2*256*256];
__device__ __align__(16) bf d_WM1H[2*512*512], d_WM1L[2*512*512];
__device__ __align__(16) bf d_WM2H[2*256*512], d_WM2L[2*256*512];
__device__ __align__(16) bf d_QHH[M4*256], d_QHL[M4*256];
__device__ __align__(16) bf d_KVH[M4*512], d_KVL[M4*512];
__device__ __align__(16) bf d_VTH[M4*256], d_VTL[M4*256];
__device__ __align__(16) bf d_OHH[M4*256], d_OHL[M4*256];
__device__ __align__(16) float d_OP[2L*8*NP*64];   // split-KV partial O
__device__ __align__(16) float d_ML[2L*8*NP*2];    // split-KV partial (m,l)

// ======================= transpose (fp32) =======================
__global__ void k_transpose(const float* __restrict__ in, float* __restrict__ out,
                            int R, int Cc)
{
    __shared__ float t[32][33];
    int b  = blockIdx.z;
    const float* ip = in  + (long)b * R * Cc;
    float*       op = out + (long)b * R * Cc;
    int c0 = blockIdx.x * 32, r0 = blockIdx.y * 32;
    for (int i = threadIdx.y; i < 32; i += 8)
        t[i][threadIdx.x] = ip[(long)(r0 + i) * Cc + c0 + threadIdx.x];
    __syncthreads();
    for (int i = threadIdx.y; i < 32; i += 8)
        op[(long)(c0 + i) * R + r0 + threadIdx.x] = t[threadIdx.x][i];
}

// ======================= kNN =======================
__global__ void __launch_bounds__(256) k_knn(const float* __restrict__ coords,
                                             int* __restrict__ knn)
{
    __shared__ float sx[NP], sy[NP], sz[NP], sd[NP];
    __shared__ float wv[8];
    __shared__ int   wi[8];
    int b = blockIdx.x / NP;
    int n = blockIdx.x % NP;
    const float* cb = coords + (long)b * 3 * NP;
    for (int j = threadIdx.x; j < NP; j += 256) {
        sx[j] = cb[j]; sy[j] = cb[NP + j]; sz[j] = cb[2 * NP + j];
    }
    __syncthreads();
    float xn = sx[n], yn = sy[n], zn = sz[n];
    float sqn = xn*xn + yn*yn + zn*zn;
    for (int j = threadIdx.x; j < NP; j += 256) {
        float x = sx[j], y = sy[j], z = sz[j];
        float d = sqn + (x*x + y*y + z*z) - 2.f * (xn*x + yn*y + zn*z);
        sd[j] = (j == n) ? 3.4e38f : d;
    }
    __syncthreads();
    int lane = threadIdx.x & 31, warp = threadIdx.x >> 5;
    for (int r = 0; r < KNB; r++) {
        float best = 3.0e38f; int bi = NP;
        for (int j = threadIdx.x; j < NP; j += 256) {
            float v = sd[j];
            if (v < best) { best = v; bi = j; }
        }
        #pragma unroll
        for (int off = 16; off; off >>= 1) {
            float ov = __shfl_down_sync(0xffffffffu, best, off);
            int   oi = __shfl_down_sync(0xffffffffu, bi,   off);
            if (ov < best || (ov == best && oi < bi)) { best = ov; bi = oi; }
        }
        if (lane == 0) { wv[warp] = best; wi[warp] = bi; }
        __syncthreads();
        if (threadIdx.x == 0) {
            float fb = wv[0]; int fi = wi[0];
            for (int w = 1; w < 8; w++)
                if (wv[w] < fb || (wv[w] == fb && wi[w] < fi)) { fb = wv[w]; fi = wi[w]; }
            knn[((long)b * NP + n) * KNB + r] = fi;
            sd[fi] = 3.4e38f;
        }
        __syncthreads();
    }
}

// ======================= HMMA GEMM (cp.async 2-stage + ldmatrix) ==============
// EPI 0: fp32 C. EPI 1: split bf16 hi/lo. EPI 2: fp32 C + column stats.
// EPI 3: fp32 C + split bf16 hi/lo.
// Dual-A: chunks with k0 >= K1 read from A2 (same lda).
template <int EPI, int MR, int NR>
__global__ void __launch_bounds__(256) mma_gemm(
    const bf* __restrict__ AH, const bf* __restrict__ AL,
    const bf* __restrict__ A2H, const bf* __restrict__ A2L, int K1, long lda,
    const bf* __restrict__ WH, const bf* __restrict__ WL, long ldw,
    const float* __restrict__ bias, const float* __restrict__ bias2,
    float* __restrict__ C, bf* __restrict__ OH, bf* __restrict__ OL,
    float* __restrict__ gsum, float* __restrict__ gsq,
    int ldc, int K)
{
    constexpr int MT    = MR / 32;
    constexpr int NW    = NR / 4;
    constexpr int NT    = NW / 8;
    constexpr int NBL   = NW / 16;
    constexpr int ATILE = MR * 80;
    constexpr int WTILE = NR * 80;
    constexpr int STAGE = 2 * (ATILE + WTILE);

    extern __shared__ __align__(16) char smem[];
    uint32_t sbase = (uint32_t)__cvta_generic_to_shared(smem);

    int tid = threadIdx.x, wid = tid >> 5, lane = tid & 31;
    int g = lane >> 2, tg = lane & 3;
    int wm = (wid >> 2) * (MR / 2);
    int wn = (wid & 3) * NW;
    int lr = tid >> 2;
    int lq = tid & 3;

    uint32_t aoff = (uint32_t)((wm + (lane & 7) + ((lane >> 3) & 1) * 8) * 80 + (lane >> 4) * 16);
    uint32_t boff = (uint32_t)((wn + (lane >> 4) * 8 + (lane & 7)) * 80 + ((lane >> 3) & 1) * 16);

    long m0 = (long)blockIdx.y * MR;
    int  n0 = blockIdx.x * NR;
    const bf* pAH  = AH + m0 * lda;
    const bf* pAL  = AL + m0 * lda;
    const bf* pA2H = A2H ? A2H + m0 * lda : nullptr;
    const bf* pA2L = A2L ? A2L + m0 * lda : nullptr;
    const bf* pWH  = WH + (long)n0 * ldw;
    const bf* pWL  = WL + (long)n0 * ldw;

    float acc[MT][NT][4];
    #pragma unroll
    for (int mt = 0; mt < MT; mt++)
        #pragma unroll
        for (int nt = 0; nt < NT; nt++)
            #pragma unroll
            for (int q = 0; q < 4; q++) acc[mt][nt][q] = 0.f;

    int nch = K >> 5;

    {
        const bf* sH = pAH; const bf* sL = pAL; long kk0 = 0;
        if (0 >= K1) { sH = pA2H; sL = pA2L; }
        uint32_t st = sbase;
        #pragma unroll
        for (int it = 0; it < MR / 64; it++) {
            int r = lr + it * 64;
            uint32_t d = st + r * 80 + lq * 16;
            CPA16(d,         sH + (long)r * lda + kk0 + lq * 8);
            CPA16(d + ATILE, sL + (long)r * lda + kk0 + lq * 8);
        }
        #pragma unroll
        for (int it = 0; it < NR / 64; it++) {
            int r = lr + it * 64;
            uint32_t d = st + 2 * ATILE + r * 80 + lq * 16;
            CPA16(d,         pWH + (long)r * ldw + lq * 8);
            CPA16(d + WTILE, pWL + (long)r * ldw + lq * 8);
        }
        CP_COMMIT();
    }

    for (int c = 0; c < nch; c++) {
        if (c + 1 < nch) {
            long k0 = (long)(c + 1) << 5;
            const bf* sH = pAH; const bf* sL = pAL; long kk0 = k0;
            if (k0 >= K1) { sH = pA2H; sL = pA2L; kk0 = k0 - K1; }
            uint32_t st = sbase + ((c + 1) & 1) * STAGE;
            #pragma unroll
            for (int it = 0; it < MR / 64; it++) {
                int r = lr + it * 64;
                uint32_t d = st + r * 80 + lq * 16;
                CPA16(d,         sH + (long)r * lda + kk0 + lq * 8);
                CPA16(d + ATILE, sL + (long)r * lda + kk0 + lq * 8);
            }
            #pragma unroll
            for (int it = 0; it < NR / 64; it++) {
                int r = lr + it * 64;
                uint32_t d = st + 2 * ATILE + r * 80 + lq * 16;
                CPA16(d,         pWH + (long)r * ldw + k0 + lq * 8);
                CPA16(d + WTILE, pWL + (long)r * ldw + k0 + lq * 8);
            }
            CP_COMMIT();
            CP_WAIT1();
        } else {
            CP_WAIT0();
        }
        __syncthreads();

        uint32_t stA = sbase + (c & 1) * STAGE;
        uint32_t aA = stA + aoff;
        uint32_t bA = stA + 2 * ATILE + boff;

        #pragma unroll
        for (int ks = 0; ks < 2; ks++) {
            int kbB = ks * 32;
            uint32_t ah[MT][4], al[MT][4];
            #pragma unroll
            for (int mt = 0; mt < MT; mt++) {
                uint32_t a0 = aA + mt * (16 * 80) + kbB;
                LDSM4(ah[mt][0], ah[mt][1], ah[mt][2], ah[mt][3], a0);
                LDSM4(al[mt][0], al[mt][1], al[mt][2], al[mt][3], a0 + ATILE);
            }
            uint32_t bh[NT][2], bl[NT][2];
            #pragma unroll
            for (int np2 = 0; np2 < NBL; np2++) {
                uint32_t b0 = bA + np2 * (16 * 80) + kbB;
                LDSM4(bh[np2*2][0], bh[np2*2][1], bh[np2*2+1][0], bh[np2*2+1][1], b0);
                LDSM4(bl[np2*2][0], bl[np2*2][1], bl[np2*2+1][0], bl[np2*2+1][1], b0 + WTILE);
            }
            #pragma unroll
            for (int mt = 0; mt < MT; mt++)
                #pragma unroll
                for (int nt = 0; nt < NT; nt++) {
                    MMA16816(acc[mt][nt], ah[mt], bh[nt]);
                    MMA16816(acc[mt][nt], ah[mt], bl[nt]);
                    MMA16816(acc[mt][nt], al[mt], bh[nt]);
                }
        }
        __syncthreads();
    }

    float csum[NT][2], csq[NT][2];
    if (EPI == 2) {
        #pragma unroll
        for (int nt = 0; nt < NT; nt++) {
            csum[nt][0] = 0.f; csum[nt][1] = 0.f;
            csq[nt][0] = 0.f;  csq[nt][1] = 0.f;
        }
    }

    #pragma unroll
    for (int mt = 0; mt < MT; mt++) {
        long row = m0 + wm + mt * 16 + g;
        #pragma unroll
        for (int nt = 0; nt < NT; nt++) {
            int col = n0 + wn + nt * 8 + tg * 2;
            float b0 = 0.f, b1 = 0.f;
            if (bias) {
                const float* bp = (bias2 && col >= 256) ? (bias2 - 256) : bias;
                b0 = __ldg(&bp[col]); b1 = __ldg(&bp[col + 1]);
            }
            float v0 = acc[mt][nt][0] + b0;
            float v1 = acc[mt][nt][1] + b1;
            float v2 = acc[mt][nt][2] + b0;
            float v3 = acc[mt][nt][3] + b1;
            if (EPI == 1 || EPI == 3) {
                uint32_t lo0, lo1;
                uint32_t hi0 = packsplit(v0, v1, lo0);
                uint32_t hi1 = packsplit(v2, v3, lo1);
                *(uint32_t*)(OH + row * (long)ldc + col)       = hi0;
                *(uint32_t*)(OL + row * (long)ldc + col)       = lo0;
                *(uint32_t*)(OH + (row + 8) * (long)ldc + col) = hi1;
                *(uint32_t*)(OL + (row + 8) * (long)ldc + col) = lo1;
            }
            if (EPI != 1) {
                *(float2*)(C + row * (long)ldc + col)       = make_float2(v0, v1);
                *(float2*)(C + (row + 8) * (long)ldc + col) = make_float2(v2, v3);
                if (EPI == 2) {
                    csum[nt][0] += v0 + v2; csq[nt][0] += v0 * v0 + v2 * v2;
                    csum[nt][1] += v1 + v3; csq[nt][1] += v1 * v1 + v3 * v3;
                }
            }
        }
    }

    if (EPI == 2) {
        int inst = (int)(m0 / NP);
        float* sb = gsum + inst * 1024;
        float* qb = gsq  + inst * 1024;
        #pragma unroll
        for (int nt = 0; nt < NT; nt++) {
            #pragma unroll
            for (int j = 0; j < 2; j++) {
                float s = csum[nt][j], q = csq[nt][j];
                s += __shfl_xor_sync(0xffffffffu, s, 4);
                s += __shfl_xor_sync(0xffffffffu, s, 8);
                s += __shfl_xor_sync(0xffffffffu, s, 16);
                q += __shfl_xor_sync(0xffffffffu, q, 4);
                q += __shfl_xor_sync(0xffffffffu, q, 8);
                q += __shfl_xor_sync(0xffffffffu, q, 16);
                if (g == 0) {
                    int col = n0 + wn + nt * 8 + tg * 2 + j;
                    atomicAdd(&sb[col], s);
                    atomicAdd(&qb[col], q);
                }
            }
        }
    }
}

#define SM_128_128 (2 * 2 * (128*80 + 128*80))
#define SM_64_128  (2 * 2 * (64*80  + 128*80))
#define SM_64_64   (2 * 2 * (64*80  + 64*80))

// ======================= fused flash attention (split-KV) =======================
#define FQ_B (128*144)
#define FK_B (64*144)
#define FA_SMEM (2*FQ_B + 4*FK_B)
__global__ void __launch_bounds__(256) k_flash(
    const bf* __restrict__ QH, const bf* __restrict__ QL,
    const bf* __restrict__ KVH, const bf* __restrict__ KVL,
    const bf* __restrict__ VH, const bf* __restrict__ VL,
    float* __restrict__ OP, float* __restrict__ ML)
{
    extern __shared__ __align__(16) char smem[];
    char* sQh = smem;
    char* sQl = smem + FQ_B;
    char* sKh = smem + 2 * FQ_B;
    char* sVh = sKh + 2 * FK_B;
    uint32_t sbase = (uint32_t)__cvta_generic_to_shared(smem);

    int tid = threadIdx.x, wid = tid >> 5, lane = tid & 31;
    int g = lane >> 2, tg = lane & 3;
    int z = blockIdx.y;
    int b = z >> 2, h = z & 3;
    long q0 = (long)blockIdx.x * 128;
    int wm = wid * 16;
    int part = blockIdx.z;
    int c0 = part * (NP / 128);
    int c1 = c0 + (NP / 128);

    uint32_t aoff = (uint32_t)((wm + (lane & 7) + ((lane >> 3) & 1) * 8) * 144 + (lane >> 4) * 16);
    uint32_t boff = (uint32_t)(((lane >> 4) * 8 + (lane & 7)) * 144 + ((lane >> 3) & 1) * 16);
    uint32_t qA = sbase + aoff;
    uint32_t kA = sbase + 2 * FQ_B + boff;
    uint32_t vA = kA + 2 * FK_B;

    const bf* pQH = QH + ((long)b * NP + q0) * 256 + h * 64;
    const bf* pQL = QL + ((long)b * NP + q0) * 256 + h * 64;

    #pragma unroll
    for (int it = 0; it < 4; it++) {
        int i = tid + it * 256;
        int r = i >> 3, q = i & 7;
        *(uint4*)(sQh + r * 144 + q * 16) = *(const uint4*)(pQH + (long)r * 256 + q * 8);
        *(uint4*)(sQl + r * 144 + q * 16) = *(const uint4*)(pQL + (long)r * 256 + q * 8);
    }

    float m0 = -3.4e38f, m1 = -3.4e38f, l0 = 0.f, l1 = 0.f;
    float acc[8][4];
    #pragma unroll
    for (int nt = 0; nt < 8; nt++)
        #pragma unroll
        for (int q = 0; q < 4; q++) acc[nt][q] = 0.f;

    for (int c = c0; c < c1; c++) {
        const bf* pKH = KVH + ((long)b * NP + c * 64) * 512 + h * 64;
        const bf* pKL = KVL + ((long)b * NP + c * 64) * 512 + h * 64;
        const bf* pVH = VH + (long)z * 64 * NP + c * 64;
        const bf* pVL = VL + (long)z * 64 * NP + c * 64;
        #pragma unroll
        for (int it = 0; it < 2; it++) {
            int i = tid + it * 256;
            int r = i >> 3, q = i & 7;
            *(uint4*)(sKh + r * 144 + q * 16)        = *(const uint4*)(pKH + (long)r * 512 + q * 8);
            *(uint4*)(sKh + FK_B + r * 144 + q * 16) = *(const uint4*)(pKL + (long)r * 512 + q * 8);
            *(uint4*)(sVh + r * 144 + q * 16)        = *(const uint4*)(pVH + (long)r * NP + q * 8);
            *(uint4*)(sVh + FK_B + r * 144 + q * 16) = *(const uint4*)(pVL + (long)r * NP + q * 8);
        }
        __syncthreads();

        float sacc[8][4];
        #pragma unroll
        for (int nt = 0; nt < 8; nt++)
            #pragma unroll
            for (int q = 0; q < 4; q++) sacc[nt][q] = 0.f;
        #pragma unroll
        for (int kk = 0; kk < 4; kk++) {
            int kbB = kk * 32;
            uint32_t aqh[4], aql[4];
            LDSM4(aqh[0], aqh[1], aqh[2], aqh[3], qA + kbB);
            LDSM4(aql[0], aql[1], aql[2], aql[3], qA + FQ_B + kbB);
            #pragma unroll
            for (int np2 = 0; np2 < 4; np2++) {
                uint32_t bh[2][2], bl[2][2];
                uint32_t b0 = kA + np2 * (16 * 144) + kbB;
                LDSM4(bh[0][0], bh[0][1], bh[1][0], bh[1][1], b0);
                LDSM4(bl[0][0], bl[0][1], bl[1][0], bl[1][1], b0 + FK_B);
                #pragma unroll
                for (int j = 0; j < 2; j++) {
                    MMA16816(sacc[np2*2+j], aqh, bh[j]);
                    MMA16816(sacc[np2*2+j], aqh, bl[j]);
                    MMA16816(sacc[np2*2+j], aql, bh[j]);
                }
            }
        }

        float rmax0 = -3.4e38f, rmax1 = -3.4e38f;
        #pragma unroll
        for (int nt = 0; nt < 8; nt++) {
            rmax0 = fmaxf(rmax0, fmaxf(sacc[nt][0], sacc[nt][1]));
            rmax1 = fmaxf(rmax1, fmaxf(sacc[nt][2], sacc[nt][3]));
        }
        rmax0 = fmaxf(rmax0, __shfl_xor_sync(0xffffffffu, rmax0, 1));
        rmax0 = fmaxf(rmax0, __shfl_xor_sync(0xffffffffu, rmax0, 2));
        rmax1 = fmaxf(rmax1, __shfl_xor_sync(0xffffffffu, rmax1, 1));
        rmax1 = fmaxf(rmax1, __shfl_xor_sync(0xffffffffu, rmax1, 2));
        float mn0 = fmaxf(m0, rmax0), mn1 = fmaxf(m1, rmax1);
        float al0 = __expf(m0 - mn0), al1 = __expf(m1 - mn1);
        m0 = mn0; m1 = mn1;

        float rs0 = 0.f, rs1 = 0.f;
        uint32_t pfh[4][4], pfl[4][4];
        #pragma unroll
        for (int nt = 0; nt < 8; nt++) {
            float p0 = __expf(sacc[nt][0] - mn0);
            float p1 = __expf(sacc[nt][1] - mn0);
            float p2 = __expf(sacc[nt][2] - mn1);
            float p3 = __expf(sacc[nt][3] - mn1);
            rs0 += p0 + p1; rs1 += p2 + p3;
            int kk = nt >> 1, base = (nt & 1) * 2;
            pfh[kk][base]     = packsplit(p0, p1, pfl[kk][base]);
            pfh[kk][base + 1] = packsplit(p2, p3, pfl[kk][base + 1]);
        }
        rs0 += __shfl_xor_sync(0xffffffffu, rs0, 1);
        rs0 += __shfl_xor_sync(0xffffffffu, rs0, 2);
        rs1 += __shfl_xor_sync(0xffffffffu, rs1, 1);
        rs1 += __shfl_xor_sync(0xffffffffu, rs1, 2);
        l0 = l0 * al0 + rs0; l1 = l1 * al1 + rs1;
        #pragma unroll
        for (int nt = 0; nt < 8; nt++) {
            acc[nt][0] *= al0; acc[nt][1] *= al0;
            acc[nt][2] *= al1; acc[nt][3] *= al1;
        }

        #pragma unroll
        for (int kk = 0; kk < 4; kk++) {
            int kbB = kk * 32;
            #pragma unroll
            for (int np2 = 0; np2 < 4; np2++) {
                uint32_t bh[2][2], bl[2][2];
                uint32_t b0 = vA + np2 * (16 * 144) + kbB;
                LDSM4(bh[0][0], bh[0][1], bh[1][0], bh[1][1], b0);
                LDSM4(bl[0][0], bl[0][1], bl[1][0], bl[1][1], b0 + FK_B);
                #pragma unroll
                for (int j = 0; j < 2; j++) {
                    MMA16816(acc[np2*2+j], pfh[kk], bh[j]);
                    MMA16816(acc[np2*2+j], pfh[kk], bl[j]);
                    MMA16816(acc[np2*2+j], pfl[kk], bh[j]);
                }
            }
        }
        __syncthreads();
    }

    long rbase = ((long)part * 8 + z) * NP + q0 + wm;
    float* pO = OP + rbase * 64;
    #pragma unroll
    for (int nt = 0; nt < 8; nt++) {
        int col = nt * 8 + tg * 2;
        *(float2*)(pO + (long)g * 64 + col)       = make_float2(acc[nt][0], acc[nt][1]);
        *(float2*)(pO + (long)(g + 8) * 64 + col) = make_float2(acc[nt][2], acc[nt][3]);
    }
    if (tg == 0) {
        ML[(rbase + g) * 2]         = m0;
        ML[(rbase + g) * 2 + 1]     = l0;
        ML[(rbase + g + 8) * 2]     = m1;
        ML[(rbase + g + 8) * 2 + 1] = l1;
    }
}

// merge two KV-half partials -> bf16 hi/lo (Wo-input layout)
__global__ void __launch_bounds__(256) k_fmerge(
    const float* __restrict__ OP, const float* __restrict__ ML,
    bf* __restrict__ OH, bf* __restrict__ OL)
{
    long i = (long)blockIdx.x * blockDim.x + threadIdx.x;
    if (i >= (long)8 * NP * 32) return;
    int  c2 = (int)(i & 31) * 2;
    long zn = i >> 5;
    int  n  = (int)(zn & (NP - 1));
    int  z  = (int)(zn >> 11);
    float m0 = ML[zn * 2],                     l0 = ML[zn * 2 + 1];
    float m1 = ML[((long)8 * NP + zn) * 2],    l1 = ML[((long)8 * NP + zn) * 2 + 1];
    float m  = fmaxf(m0, m1);
    float a0 = __expf(m0 - m), a1 = __expf(m1 - m);
    float inv = 1.f / (l0 * a0 + l1 * a1);
    long o0 = zn * 64 + c2;
    float2 v0 = *(const float2*)(OP + o0);
    float2 v1 = *(const float2*)(OP + (long)8 * NP * 64 + o0);
    float x = (v0.x * a0 + v1.x * a1) * inv;
    float y = (v0.y * a0 + v1.y * a1) * inv;
    uint32_t lo;
    uint32_t hi = packsplit(x, y, lo);
    int b = z >> 2, h = z & 3;
    long od = ((long)b * NP + n) * 256 + h * 64 + c2;
    *(uint32_t*)(OH + od) = hi;
    *(uint32_t*)(OL + od) = lo;
}

// ======================= fp32 -> bf16 hi/lo =======================
__global__ void k_cvt(const float* __restrict__ src, long ldi, int cols, long total,
                      bf* __restrict__ H, bf* __restrict__ L, long ldo)
{
    long i = ((long)blockIdx.x * blockDim.x + threadIdx.x) * 4;
    if (i >= total) return;
    long r = i / cols; int c = (int)(i - r * cols);
    float4 v = *(const float4*)(src + r * ldi + c);
    uint32_t lo0, lo1;
    uint32_t hi0 = packsplit(v.x, v.y, lo0);
    uint32_t hi1 = packsplit(v.z, v.w, lo1);
    *(uint2*)(H + r * ldo + c) = make_uint2(hi0, hi1);
    *(uint2*)(L + r * ldo + c) = make_uint2(lo0, lo1);
}

__global__ void k_prepw_b(const float* __restrict__ W, bf* __restrict__ H,
                          bf* __restrict__ L, int O, int Ci)
{
    long i = blockIdx.x * (long)blockDim.x + threadIdx.x;
    if (i >= (long)O * Ci) return;
    int o = (int)(i / Ci), c = (int)(i % Ci);
    float a  = W[(long)o * 2 * Ci + c];
    float bq = W[(long)o * 2 * Ci + Ci + c];
    bf h, l;
    split2(a - bq, h, l);
    H[(long)o * Ci + c] = h; L[(long)o * Ci + c] = l;
    split2(bq, h, l);
    H[((long)O + o) * Ci + c] = h; L[((long)O + o) * Ci + c] = l;
}

__global__ void k_prepw_perm(const float* __restrict__ W, float scale,
                             bf* __restrict__ H, bf* __restrict__ L, int roff,
                             const float* __restrict__ bin, float* __restrict__ bout)
{
    int i = blockIdx.x * blockDim.x + threadIdx.x;
    if (i >= 256 * 256) return;
    int o = i >> 8, c = i & 255;
    int op = (o & 3) * 64 + (o >> 2);
    bf h, l;
    split2(W[i] * scale, h, l);
    H[(long)(roff + op) * 256 + c] = h;
    L[(long)(roff + op) * 256 + c] = l;
    if (c == 0) bout[op] = bin[o] * scale;
}

__global__ void k_prepw_colperm(const float* __restrict__ W,
                                bf* __restrict__ H, bf* __restrict__ L)
{
    int i = blockIdx.x * blockDim.x + threadIdx.x;
    if (i >= 256 * 256) return;
    int o = i >> 8, oc = i & 255;
    int c = (oc & 63) * 4 + (oc >> 6);
    bf h, l;
    split2(W[o * 256 + c], h, l);
    H[i] = h; L[i] = l;
}

__global__ void k_vtrans(const bf* __restrict__ SH, const bf* __restrict__ SL,
                         bf* __restrict__ DH, bf* __restrict__ DL)
{
    __shared__ uint16_t th[32][34], tl[32][34];
    int b = blockIdx.z;
    int hc0 = blockIdx.x * 32;
    int n0  = blockIdx.y * 32;
    int tx = threadIdx.x, ty = threadIdx.y;
    for (int i = ty; i < 32; i += 8) {
        long src = ((long)b * NP + n0 + i) * 512 + 256 + hc0 + tx;
        th[i][tx] = ((const uint16_t*)SH)[src];
        tl[i][tx] = ((const uint16_t*)SL)[src];
    }
    __syncthreads();
    for (int i = ty; i < 32; i += 8) {
        int hc = hc0 + i;
        int h = hc >> 6, dd = hc & 63;
        long dst = (((long)b * 4 + h) * 64 + dd) * NP + n0 + tx;
        ((uint16_t*)DH)[dst] = th[tx][i];
        ((uint16_t*)DL)[dst] = tl[tx][i];
    }
}

// ======================= edge gather: max + stats =======================
__global__ void __launch_bounds__(256) k_edge(const float* __restrict__ PQ,
                                              const int* __restrict__ knn,
                                              float* __restrict__ mx,
                                              float* __restrict__ ssum,
                                              float* __restrict__ sssq,
                                              int Co)
{
    __shared__ long nbb[KNB];
    long bn = blockIdx.x;
    int  inst = (int)(bn / NP);
    if (threadIdx.x < KNB) {
        int nb = knn[bn * KNB + threadIdx.x];
        nbb[threadIdx.x] = ((long)inst * NP + nb) * (2 * Co) + Co;
    }
    __syncthreads();
    const float* Prow = PQ + bn * (2 * Co);
    for (int o = threadIdx.x; o < Co; o += 256) {
        float p = Prow[o];
        float mv = -3.4e38f, s = 0.f, ss = 0.f;
        #pragma unroll
        for (int k2 = 0; k2 < KNB; k2++) {
            float v = p + PQ[nbb[k2] + o];
            mv = fmaxf(mv, v); s += v; ss += v * v;
        }
        mx[bn * Co + o] = mv;
        atomicAdd(&ssum[inst * 1024 + o], s);
        atomicAdd(&sssq[inst * 1024 + o], ss);
    }
}

// ======================= normalize + act -> fp32 (+ optional split) ==========
__global__ void k_norm_act_both(const float* __restrict__ X, int ldx,
                                float* __restrict__ Y, int ldy,
                                bf* __restrict__ H, bf* __restrict__ L,
                                const float* __restrict__ ssum,
                                const float* __restrict__ sssq,
                                int Co, long rows, float invcnt, int act)
{
    long i = blockIdx.x * (long)blockDim.x + threadIdx.x;
    if (i >= rows * Co) return;
    int  o  = (int)(i % Co);
    long rn = i / Co;
    int  inst = (int)(rn / NP);
    float mu  = ssum[inst * 1024 + o] * invcnt;
    float var = sssq[inst * 1024 + o] * invcnt - mu * mu;
    float v = (X[rn * ldx + o] - mu) * rsqrtf(var + EPSI);
    if (act == 1) v = (v >= 0.f) ? v : 0.2f * v;
    else          v = (v > 0.f)  ? v : 0.f;
    Y[rn * ldy + o] = v;
    bf h, l;
    split2(v, h, l);
    H[rn * (long)Co + o] = h;
    L[rn * (long)Co + o] = l;
}

// ======================= normalize + act -> bf16 hi/lo =======================
__global__ void k_norm_act_split(const float* __restrict__ X, int ldx,
                                 bf* __restrict__ H, bf* __restrict__ L,
                                 int ldy, int offy,
                                 const float* __restrict__ ssum,
                                 const float* __restrict__ sssq,
                                 int Co, long rows, float invcnt, int act)
{
    long i = blockIdx.x * (long)blockDim.x + threadIdx.x;
    if (i >= rows * Co) return;
    int  o  = (int)(i % Co);
    long rn = i / Co;
    int  inst = (int)(rn / NP);
    float mu  = ssum[inst * 1024 + o] * invcnt;
    float var = sssq[inst * 1024 + o] * invcnt - mu * mu;
    float v = (X[rn * ldx + o] - mu) * rsqrtf(var + EPSI);
    if (act == 1) v = (v >= 0.f) ? v : 0.2f * v;
    else          v = (v > 0.f)  ? v : 0.f;
    bf h, l;
    split2(v, h, l);
    H[rn * ldy + offy + o] = h;
    L[rn * ldy + offy + o] = l;
}

// ======================= host =======================
template <int EPI>
static void gemm_any(const bf* AH, const bf* AL,
                     const bf* A2H, const bf* A2L, int K1, long lda,
                     const bf* WH, const bf* WL, long ldw,
                     const float* bias, const float* bias2,
                     float* C, bf* OH, bf* OL,
                     float* gsum, float* gsq, int ldc,
                     int M, int Nout, int K)
{
    long ctas = (long)(M / 128) * (Nout / 128);
    if (ctas >= 200) {
        dim3 g(Nout / 128, M / 128);
        mma_gemm<EPI, 128, 128><<<g, 256, SM_128_128>>>(AH, AL, A2H, A2L, K1, lda,
            WH, WL, ldw, bias, bias2, C, OH, OL, gsum, gsq, ldc, K);
    } else if (ctas * 2 >= 200) {
        dim3 g(Nout / 128, M / 64);
        mma_gemm<EPI, 64, 128><<<g, 256, SM_64_128>>>(AH, AL, A2H, A2L, K1, lda,
            WH, WL, ldw, bias, bias2, C, OH, OL, gsum, gsq, ldc, K);
    } else {
        dim3 g(Nout / 64, M / 64);
        mma_gemm<EPI, 64, 64><<<g, 256, SM_64_64>>>(AH, AL, A2H, A2L, K1, lda,
            WH, WL, ldw, bias, bias2, C, OH, OL, gsum, gsq, ldc, K);
    }
}
static void gemm_f(const bf* AH, const bf* AL, long lda,
                   const bf* WH, const bf* WL, long ldw,
                   const float* bias, float* C, int ldc, int M, int Nout, int K)
{
    gemm_any<0>(AH, AL, nullptr, nullptr, 1 << 30, lda, WH, WL, ldw, bias, nullptr,
                C, nullptr, nullptr, nullptr, nullptr, ldc, M, Nout, K);
}
static void gemm_fs(const bf* AH, const bf* AL, long lda,
                    const bf* WH, const bf* WL, long ldw,
                    const float* bias, float* C, float* gsum, float* gsq,
                    int ldc, int M, int Nout, int K)
{
    gemm_any<2>(AH, AL, nullptr, nullptr, 1 << 30, lda, WH, WL, ldw, bias, nullptr,
                C, nullptr, nullptr, gsum, gsq, ldc, M, Nout, K);
}
static void gemm_dual_fs(const bf* AH, const bf* AL,
                         const bf* A2H, const bf* A2L, int K1, long lda,
                         const bf* WH, const bf* WL, long ldw,
                         const float* bias, float* C, float* gsum, float* gsq,
                         int ldc, int M, int Nout, int K)
{
    gemm_any<2>(AH, AL, A2H, A2L, K1, lda, WH, WL, ldw, bias, nullptr,
                C, nullptr, nullptr, gsum, gsq, ldc, M, Nout, K);
}
static void gemm_s(const bf* AH, const bf* AL, long lda,
                   const bf* WH, const bf* WL, long ldw,
                   const float* bias, const float* bias2,
                   bf* OH, bf* OL, int ldc, int M, int Nout, int K)
{
    gemm_any<1>(AH, AL, nullptr, nullptr, 1 << 30, lda, WH, WL, ldw, bias, bias2,
                nullptr, OH, OL, nullptr, nullptr, ldc, M, Nout, K);
}
static void gemm_b(const bf* AH, const bf* AL, long lda,
                   const bf* WH, const bf* WL, long ldw,
                   const float* bias, float* C, bf* OH, bf* OL,
                   int ldc, int M, int Nout, int K)
{
    gemm_any<3>(AH, AL, nullptr, nullptr, 1 << 30, lda, WH, WL, ldw, bias, nullptr,
                C, OH, OL, nullptr, nullptr, ldc, M, Nout, K);
}

#define GSA(sym, var, type) cudaGetSymbolAddress(&pv, sym); type* var = (type*)pv
#define CVTS(st, src, ldi, cols, total, H, L, ldo) \
    k_cvt<<<(int)(((total) / 4 + 255) / 256), 256, 0, st>>>(src, ldi, cols, total, H, L, ldo)
#define CVT(src, ldi, cols, total, H, L, ldo) CVTS(0, src, ldi, cols, total, H, L, ldo)

extern "C" void kernel_launch(void* const* d_in, const int* in_sizes, int n_in,
                              void* d_out, int out_size)
{
    const float* coords1 = (const float*)d_in[0];
    const float* coords2 = (const float*)d_in[2];
    const float* feats1  = (const float*)d_in[1];
    const float* feats2  = (const float*)d_in[3];
    const float* gW1 = (const float*)d_in[4];
    const float* gW2 = (const float*)d_in[5];
    const float* gW3 = (const float*)d_in[6];
    const float* Wq  = (const float*)d_in[7];  const float* bq  = (const float*)d_in[8];
    const float* Wk  = (const float*)d_in[9];  const float* bk  = (const float*)d_in[10];
    const float* Wv  = (const float*)d_in[11]; const float* bv  = (const float*)d_in[12];
    const float* Wo  = (const float*)d_in[13]; const float* bo  = (const float*)d_in[14];
    const float* Wm1 = (const float*)d_in[15]; const float* bm1 = (const float*)d_in[16];
    const float* Wm2 = (const float*)d_in[17]; const float* bm2 = (const float*)d_in[18];
    float* out = (float*)d_out;

    static int attr_set = 0;
    static cudaStream_t s2 = 0, s3 = 0, s4 = 0;
    static cudaEvent_t evf = 0, evk2 = 0, evk3 = 0, evG[2] = {0,0}, evA[2] = {0,0};
    if (!attr_set) {
        cudaFuncSetAttribute(mma_gemm<0,128,128>, cudaFuncAttributeMaxDynamicSharedMemorySize, SM_128_128);
        cudaFuncSetAttribute(mma_gemm<1,128,128>, cudaFuncAttributeMaxDynamicSharedMemorySize, SM_128_128);
        cudaFuncSetAttribute(mma_gemm<2,128,128>, cudaFuncAttributeMaxDynamicSharedMemorySize, SM_128_128);
        cudaFuncSetAttribute(mma_gemm<3,128,128>, cudaFuncAttributeMaxDynamicSharedMemorySize, SM_128_128);
        cudaFuncSetAttribute(mma_gemm<0,64,128>,  cudaFuncAttributeMaxDynamicSharedMemorySize, SM_64_128);
        cudaFuncSetAttribute(mma_gemm<1,64,128>,  cudaFuncAttributeMaxDynamicSharedMemorySize, SM_64_128);
        cudaFuncSetAttribute(mma_gemm<2,64,128>,  cudaFuncAttributeMaxDynamicSharedMemorySize, SM_64_128);
        cudaFuncSetAttribute(mma_gemm<3,64,128>,  cudaFuncAttributeMaxDynamicSharedMemorySize, SM_64_128);
        cudaFuncSetAttribute(mma_gemm<0,64,64>,   cudaFuncAttributeMaxDynamicSharedMemorySize, SM_64_64);
        cudaFuncSetAttribute(mma_gemm<1,64,64>,   cudaFuncAttributeMaxDynamicSharedMemorySize, SM_64_64);
        cudaFuncSetAttribute(mma_gemm<2,64,64>,   cudaFuncAttributeMaxDynamicSharedMemorySize, SM_64_64);
        cudaFuncSetAttribute(mma_gemm<3,64,64>,   cudaFuncAttributeMaxDynamicSharedMemorySize, SM_64_64);
        cudaFuncSetAttribute(k_flash, cudaFuncAttributeMaxDynamicSharedMemorySize, FA_SMEM);
        cudaStreamCreateWithFlags(&s2, cudaStreamNonBlocking);
        cudaStreamCreateWithFlags(&s3, cudaStreamNonBlocking);
        cudaStreamCreateWithFlags(&s4, cudaStreamNonBlocking);
        cudaEventCreateWithFlags(&evf, cudaEventDisableTiming);
        cudaEventCreateWithFlags(&evk2, cudaEventDisableTiming);
        cudaEventCreateWithFlags(&evk3, cudaEventDisableTiming);
        cudaEventCreateWithFlags(&evG[0], cudaEventDisableTiming);
        cudaEventCreateWithFlags(&evG[1], cudaEventDisableTiming);
        cudaEventCreateWithFlags(&evA[0], cudaEventDisableTiming);
        cudaEventCreateWithFlags(&evA[1], cudaEventDisableTiming);
        attr_set = 1;
    }

    void* pv;
    GSA(d_FE,  FEb, float);
    GSA(d_KN,  KNb, int);
    GSA(d_PQ,  PQp, float);
    GSA(d_MX,  MXp, float);
    GSA(d_STT, STp, float);
    GSA(d_BIAS, BP, float);
    GSA(d_OP,  OPp, float);
    GSA(d_ML,  MLp, float);
    GSA(d_AH,  AH, bf);    GSA(d_AL,  AL, bf);
    GSA(d_FSH, FSH, bf);   GSA(d_FSL, FSL, bf);
    GSA(d_W1H, W1H, bf);   GSA(d_W1L, W1L, bf);
    GSA(d_W2H, W2H, bf);   GSA(d_W2L, W2L, bf);
    GSA(d_W3H, W3H, bf);   GSA(d_W3L, W3L, bf);
    GSA(d_WQH, WQH, bf);   GSA(d_WQL, WQL, bf);
    GSA(d_WKVH, WKVH, bf); GSA(d_WKVL, WKVL, bf);
    GSA(d_WOH, WOH, bf);   GSA(d_WOL, WOL, bf);
    GSA(d_WM1H, WM1H, bf); GSA(d_WM1L, WM1L, bf);
    GSA(d_WM2H, WM2H, bf); GSA(d_WM2L, WM2L, bf);
    GSA(d_QHH, QHH, bf);   GSA(d_QHL, QHL, bf);
    GSA(d_KVH, KVH, bf);   GSA(d_KVL, KVL, bf);
    GSA(d_VTH, VTH, bf);   GSA(d_VTL, VTL, bf);
    GSA(d_OHH, OHH, bf);   GSA(d_OHL, OHL, bf);
    float* SUM = STp;
    float* SSQ = STp + 4 * 1024;
    float* FE[2] = { FEb, FEb + (long)M4 * 256 };
    // attention scratch within d_AH/d_AL
    bf* AOH = AH;                   bf* AOL = AL;               // Wo out (M4 x 256)
    bf* HH  = AH + (long)M4 * 256;  bf* HL  = AL + (long)M4 * 256; // MLP hidden (M4 x 512)

    const int EWB = 256;
    dim3 tb(32, 8);

    cudaEventRecord(evf, 0);
    cudaStreamWaitEvent(s2, evf, 0);
    cudaStreamWaitEvent(s3, evf, 0);
    cudaStreamWaitEvent(s4, evf, 0);
    k_knn<<<BB * NP, 256, 0, s3>>>(coords1, KNb);
    k_knn<<<BB * NP, 256, 0, s4>>>(coords2, KNb + (long)M4 * KNB);
    cudaEventRecord(evk2, s3);
    cudaEventRecord(evk3, s4);

    for (int i = 0; i < 2; i++) {
        long o1 = (long)i * 512 * 256, o2 = (long)i * 1024 * 256, o3 = (long)i * 256 * 1024;
        k_prepw_b<<<(256 * 256 + 255) / 256, 256, 0, s2>>>(gW1 + (long)i * 256 * 512,
                                                           W1H + o1, W1L + o1, 256, 256);
        k_prepw_b<<<(512 * 256 + 255) / 256, 256, 0, s2>>>(gW2 + (long)i * 512 * 512,
                                                           W2H + o2, W2L + o2, 512, 256);
        CVTS(s2, gW3 + (long)i * 256 * 1024, 1024, 1024, (long)256 * 1024,
             W3H + o3, W3L + o3, 1024);
        cudaEventRecord(evG[i], s2);
    }
    for (int i = 0; i < 2; i++) {
        long oq = (long)i * 65536, okv = (long)i * 512 * 256;
        long om1 = (long)i * 262144, om2 = (long)i * 131072;
        float* BQP = BP + i * 768;
        float* BKP = BQP + 256;
        float* BVP = BQP + 512;
        k_prepw_perm<<<256, 256, 0, s2>>>(Wq + oq, 0.125f, WQH + oq, WQL + oq, 0,
                                          bq + (long)i * 256, BQP);
        k_prepw_perm<<<256, 256, 0, s2>>>(Wk + oq, 1.f, WKVH + okv, WKVL + okv, 0,
                                          bk + (long)i * 256, BKP);
        k_prepw_perm<<<256, 256, 0, s2>>>(Wv + oq, 1.f, WKVH + okv, WKVL + okv, 256,
                                          bv + (long)i * 256, BVP);
        k_prepw_colperm<<<256, 256, 0, s2>>>(Wo + oq, WOH + oq, WOL + oq);
        CVTS(s2, Wm1 + om1, 512, 512, (long)262144, WM1H + om1, WM1L + om1, 512);
        CVTS(s2, Wm2 + om2, 512, 512, (long)131072, WM2H + om2, WM2L + om2, 512);
        cudaEventRecord(evA[i], s2);
    }

    k_transpose<<<dim3(NP / 32, 256 / 32, BB), tb>>>(feats1, FE[0], 256, NP);
    k_transpose<<<dim3(NP / 32, 256 / 32, BB), tb>>>(feats2, FE[1], 256, NP);

    const long R8 = M8, R4 = M4;
    int joined = 0;

    for (int li = 0; li < 4; li++) {
        int i = li / 2;
        if ((li & 1) == 0) {
            // ---------------- GCN layer i (both clouds batched) ----------------
            long o1 = (long)i * 512 * 256, o2 = (long)i * 1024 * 256, o3 = (long)i * 256 * 1024;
            cudaStreamWaitEvent(0, evG[i], 0);
            CVT(FEb, 256, 256, R8 * 256, AH, AL, 1024);
            gemm_f(AH, AL, 1024, W1H + o1, W1L + o1, 256, nullptr, PQp, 512, (int)R8, 512, 256);
            cudaMemsetAsync(STp, 0, sizeof(float) * 2 * 4 * 1024, 0);
            if (!joined) {
                cudaStreamWaitEvent(0, evk2, 0);
                cudaStreamWaitEvent(0, evk3, 0);
                joined = 1;
            }
            k_edge<<<(int)R8, 256>>>(PQp, KNb, MXp, SUM, SSQ, 256);
            k_norm_act_split<<<(int)((R8 * 256 + EWB - 1) / EWB), EWB>>>(
                MXp, 256, AH, AL, 1024, 256, SUM, SSQ, 256, R8, 1.f / 32768.f, 1);
            gemm_f(AH + 256, AL + 256, 1024, W2H + o2, W2L + o2, 256, nullptr,
                   PQp, 1024, (int)R8, 1024, 256);
            cudaMemsetAsync(STp, 0, sizeof(float) * 2 * 4 * 1024, 0);
            k_edge<<<(int)R8, 256>>>(PQp, KNb, MXp, SUM, SSQ, 512);
            k_norm_act_split<<<(int)((R8 * 512 + EWB - 1) / EWB), EWB>>>(
                MXp, 512, AH, AL, 1024, 512, SUM, SSQ, 512, R8, 1.f / 32768.f, 1);
            cudaMemsetAsync(STp, 0, sizeof(float) * 2 * 4 * 1024, 0);
            gemm_fs(AH, AL, 1024, W3H + o3, W3L + o3, 1024, nullptr,
                    MXp, SUM, SSQ, 256, (int)R8, 256, 1024);
            k_norm_act_both<<<(int)((R8 * 256 + EWB - 1) / EWB), EWB>>>(
                MXp, 256, FEb, 256, FSH, FSL, SUM, SSQ, 256, R8, 1.f / (float)NP, 1);
        } else {
            // ---------------- cross-attention layer i ----------------
            long oq = (long)i * 65536, okv = (long)i * 512 * 256;
            long om1 = (long)i * 262144, om2 = (long)i * 131072;
            float* BQP = BP + i * 768;
            float* BKP = BQP + 256;
            float* BVP = BQP + 512;
            cudaStreamWaitEvent(0, evA[i], 0);
            for (int a = 0; a < 2; a++) {
                bf* F1SH = FSH + (long)a * M4 * 256;
                bf* F1SL = FSL + (long)a * M4 * 256;
                bf* F2SH = FSH + (long)(1 - a) * M4 * 256;
                bf* F2SL = FSL + (long)(1 - a) * M4 * 256;
                gemm_s(F1SH, F1SL, 256, WQH + oq, WQL + oq, 256, BQP, nullptr,
                       QHH, QHL, 256, (int)R4, 256, 256);
                gemm_s(F2SH, F2SL, 256, WKVH + okv, WKVL + okv, 256, BKP, BVP,
                       KVH, KVL, 512, (int)R4, 512, 256);
                k_vtrans<<<dim3(8, NP / 32, BB), tb>>>(KVH, KVL, VTH, VTL);
                k_flash<<<dim3(16, 8, 2), 256, FA_SMEM>>>(QHH, QHL, KVH, KVL, VTH, VTL, OPp, MLp);
                k_fmerge<<<(int)((8L * NP * 32 + 255) / 256), 256>>>(OPp, MLp, OHH, OHL);
                gemm_s(OHH, OHL, 256, WOH + oq, WOL + oq, 256, bo + (long)i * 256, nullptr,
                       AOH, AOL, 256, (int)R4, 256, 256);
                cudaMemsetAsync(STp, 0, sizeof(float) * 2 * 4 * 1024, 0);
                gemm_dual_fs(F1SH, F1SL, AOH, AOL, 256, 256,
                             WM1H + om1, WM1L + om1, 512, bm1 + (long)i * 512,
                             PQp, SUM, SSQ, 512, (int)R4, 512, 512);
                k_norm_act_split<<<(int)((R4 * 512 + EWB - 1) / EWB), EWB>>>(
                    PQp, 512, HH, HL, 512, 0, SUM, SSQ, 512, R4, 1.f / (float)NP, 2);
                gemm_b(HH, HL, 512, WM2H + om2, WM2L + om2, 512, bm2 + (long)i * 256,
                       FE[a], F1SH, F1SL, 256, (int)R4, 256, 512);
            }
        }
    }

    k_transpose<<<dim3(256 / 32, NP / 32, BB), tb>>>(FE[0], out, NP, 256);
    k_transpose<<<dim3(256 / 32, NP / 32, BB), tb>>>(FE[1], out + (long)M4 * 256, NP, 256);
}

// round 17
// speedup vs baseline: 1.0997x; 1.0232x over previous
#include <cuda_runtime.h>
#include <cuda_bf16.h>
#include <cstdint>

#define BB   2
#define NP   2048
#define KNB  16
#define EPSI 1e-5f
#define M4   (BB*NP)        // 4096
#define M8   (2*BB*NP)      // 8192

typedef __nv_bfloat16 bf;

// ======================= helpers =======================
__device__ __forceinline__ void split2(float x, bf& h, bf& l){
    h = __float2bfloat16(x);
    l = __float2bfloat16(x - __bfloat162float(h));
}
__device__ __forceinline__ uint32_t packbf(bf a, bf b){
    return ((uint32_t)__bfloat16_as_ushort(b) << 16) | (uint32_t)__bfloat16_as_ushort(a);
}
__device__ __forceinline__ uint32_t packsplit(float a, float b, uint32_t& lo){
    bf ha, la, hb, lb;
    split2(a, ha, la); split2(b, hb, lb);
    lo = packbf(la, lb);
    return packbf(ha, hb);
}

#define MMA16816(d, a, b) \
    asm volatile("mma.sync.aligned.m16n8k16.row.col.f32.bf16.bf16.f32 " \
        "{%0,%1,%2,%3}, {%4,%5,%6,%7}, {%8,%9}, {%0,%1,%2,%3};" \
        : "+f"((d)[0]), "+f"((d)[1]), "+f"((d)[2]), "+f"((d)[3]) \
        : "r"((a)[0]), "r"((a)[1]), "r"((a)[2]), "r"((a)[3]), \
          "r"((b)[0]), "r"((b)[1]))

#define LDSM4(r0, r1, r2, r3, a) \
    asm volatile("ldmatrix.sync.aligned.m8n8.x4.shared.b16 {%0,%1,%2,%3}, [%4];" \
        : "=r"(r0), "=r"(r1), "=r"(r2), "=r"(r3) : "r"(a))

#define CPA16(dst, src) \
    asm volatile("cp.async.cg.shared.global [%0], [%1], 16;" :: "r"(dst), "l"(src))
#define CP_COMMIT() asm volatile("cp.async.commit_group;" ::: "memory")
#define CP_WAIT1()  asm volatile("cp.async.wait_group 1;" ::: "memory")
#define CP_WAIT0()  asm volatile("cp.async.wait_group 0;" ::: "memory")

// ======================= device scratch =======================
__device__ __align__(16) float d_FE [M8*256];
__device__ int   d_KN [M8*KNB];
__device__ __align__(16) float d_PQ [M8*1024];
__device__ __align__(16) float d_MX [M8*512];
__device__ __align__(16) float d_STT[10*8*1024];     // 10 stat slots (SUM[4][1024], SSQ[4][1024])
__device__ float d_BIAS[2*3*256];
__device__ __align__(16) bf d_AH [M8*1024];
__device__ __align__(16) bf d_AL [M8*1024];
__device__ __align__(16) bf d_FSH[M8*256], d_FSL[M8*256];    // split copy of FE
__device__ __align__(16) bf d_W1H[2*512*256],  d_W1L[2*512*256];
__device__ __align__(16) bf d_W2H[2*1024*256], d_W2L[2*1024*256];
__device__ __align__(16) bf d_W3H[2*256*1024], d_W3L[2*256*1024];
__device__ __align__(16) bf d_WQH[2*256*256],  d_WQL[2*256*256];
__device__ __align__(16) bf d_WKVH[2*512*256], d_WKVL[2*512*256];
__device__ __align__(16) bf d_WOH[2*256*256],  d_WOL[2*256*256];
__device__ __align__(16) bf d_WM1H[2*512*512], d_WM1L[2*512*512];
__device__ __align__(16) bf d_WM2H[2*256*512], d_WM2L[2*256*512];
__device__ __align__(16) bf d_QHH[M4*256], d_QHL[M4*256];
__device__ __align__(16) bf d_KVH[M4*512], d_KVL[M4*512];
__device__ __align__(16) bf d_VTH[M4*256], d_VTL[M4*256];
__device__ __align__(16) bf d_OHH[M4*256], d_OHL[M4*256];
__device__ __align__(16) float d_OP[2L*8*NP*64];   // split-KV partial O
__device__ __align__(16) float d_ML[2L*8*NP*2];    // split-KV partial (m,l)

// ======================= transpose (fp32, optional split emit) ================
__global__ void k_transpose(const float* __restrict__ in, float* __restrict__ out,
                            int R, int Cc, bf* __restrict__ H, bf* __restrict__ L)
{
    __shared__ float t[32][33];
    int b  = blockIdx.z;
    const float* ip = in  + (long)b * R * Cc;
    long obase = (long)b * R * Cc;
    int c0 = blockIdx.x * 32, r0 = blockIdx.y * 32;
    for (int i = threadIdx.y; i < 32; i += 8)
        t[i][threadIdx.x] = ip[(long)(r0 + i) * Cc + c0 + threadIdx.x];
    __syncthreads();
    for (int i = threadIdx.y; i < 32; i += 8) {
        long idx = obase + (long)(c0 + i) * R + r0 + threadIdx.x;
        float v = t[threadIdx.x][i];
        out[idx] = v;
        if (H) {
            bf h, l;
            split2(v, h, l);
            H[idx] = h; L[idx] = l;
        }
    }
}

// ======================= kNN =======================
__global__ void __launch_bounds__(256) k_knn(const float* __restrict__ coords,
                                             int* __restrict__ knn)
{
    __shared__ float sx[NP], sy[NP], sz[NP], sd[NP];
    __shared__ float wv[8];
    __shared__ int   wi[8];
    int b = blockIdx.x / NP;
    int n = blockIdx.x % NP;
    const float* cb = coords + (long)b * 3 * NP;
    for (int j = threadIdx.x; j < NP; j += 256) {
        sx[j] = cb[j]; sy[j] = cb[NP + j]; sz[j] = cb[2 * NP + j];
    }
    __syncthreads();
    float xn = sx[n], yn = sy[n], zn = sz[n];
    float sqn = xn*xn + yn*yn + zn*zn;
    for (int j = threadIdx.x; j < NP; j += 256) {
        float x = sx[j], y = sy[j], z = sz[j];
        float d = sqn + (x*x + y*y + z*z) - 2.f * (xn*x + yn*y + zn*z);
        sd[j] = (j == n) ? 3.4e38f : d;
    }
    __syncthreads();
    int lane = threadIdx.x & 31, warp = threadIdx.x >> 5;
    for (int r = 0; r < KNB; r++) {
        float best = 3.0e38f; int bi = NP;
        for (int j = threadIdx.x; j < NP; j += 256) {
            float v = sd[j];
            if (v < best) { best = v; bi = j; }
        }
        #pragma unroll
        for (int off = 16; off; off >>= 1) {
            float ov = __shfl_down_sync(0xffffffffu, best, off);
            int   oi = __shfl_down_sync(0xffffffffu, bi,   off);
            if (ov < best || (ov == best && oi < bi)) { best = ov; bi = oi; }
        }
        if (lane == 0) { wv[warp] = best; wi[warp] = bi; }
        __syncthreads();
        if (threadIdx.x == 0) {
            float fb = wv[0]; int fi = wi[0];
            for (int w = 1; w < 8; w++)
                if (wv[w] < fb || (wv[w] == fb && wi[w] < fi)) { fb = wv[w]; fi = wi[w]; }
            knn[((long)b * NP + n) * KNB + r] = fi;
            sd[fi] = 3.4e38f;
        }
        __syncthreads();
    }
}

// ======================= HMMA GEMM (cp.async 2-stage + ldmatrix) ==============
// EPI 0: fp32 C. EPI 1: split bf16 hi/lo. EPI 2: fp32 C + column stats.
// EPI 3: fp32 C + split bf16 hi/lo.
// Dual-A: chunks with k0 >= K1 read from A2 (lda2).
template <int EPI, int MR, int NR>
__global__ void __launch_bounds__(256) mma_gemm(
    const bf* __restrict__ AH, const bf* __restrict__ AL,
    const bf* __restrict__ A2H, const bf* __restrict__ A2L, int K1,
    long lda, long lda2,
    const bf* __restrict__ WH, const bf* __restrict__ WL, long ldw,
    const float* __restrict__ bias, const float* __restrict__ bias2,
    float* __restrict__ C, bf* __restrict__ OH, bf* __restrict__ OL,
    float* __restrict__ gsum, float* __restrict__ gsq,
    int ldc, int K)
{
    constexpr int MT    = MR / 32;
    constexpr int NW    = NR / 4;
    constexpr int NT    = NW / 8;
    constexpr int NBL   = NW / 16;
    constexpr int ATILE = MR * 80;
    constexpr int WTILE = NR * 80;
    constexpr int STAGE = 2 * (ATILE + WTILE);

    extern __shared__ __align__(16) char smem[];
    uint32_t sbase = (uint32_t)__cvta_generic_to_shared(smem);

    int tid = threadIdx.x, wid = tid >> 5, lane = tid & 31;
    int g = lane >> 2, tg = lane & 3;
    int wm = (wid >> 2) * (MR / 2);
    int wn = (wid & 3) * NW;
    int lr = tid >> 2;
    int lq = tid & 3;

    uint32_t aoff = (uint32_t)((wm + (lane & 7) + ((lane >> 3) & 1) * 8) * 80 + (lane >> 4) * 16);
    uint32_t boff = (uint32_t)((wn + (lane >> 4) * 8 + (lane & 7)) * 80 + ((lane >> 3) & 1) * 16);

    long m0 = (long)blockIdx.y * MR;
    int  n0 = blockIdx.x * NR;
    const bf* pAH  = AH + m0 * lda;
    const bf* pAL  = AL + m0 * lda;
    const bf* pA2H = A2H ? A2H + m0 * lda2 : nullptr;
    const bf* pA2L = A2L ? A2L + m0 * lda2 : nullptr;
    const bf* pWH  = WH + (long)n0 * ldw;
    const bf* pWL  = WL + (long)n0 * ldw;

    float acc[MT][NT][4];
    #pragma unroll
    for (int mt = 0; mt < MT; mt++)
        #pragma unroll
        for (int nt = 0; nt < NT; nt++)
            #pragma unroll
            for (int q = 0; q < 4; q++) acc[mt][nt][q] = 0.f;

    int nch = K >> 5;

    {
        const bf* sH = pAH; const bf* sL = pAL; long kk0 = 0; long ld = lda;
        if (0 >= K1) { sH = pA2H; sL = pA2L; ld = lda2; }
        uint32_t st = sbase;
        #pragma unroll
        for (int it = 0; it < MR / 64; it++) {
            int r = lr + it * 64;
            uint32_t d = st + r * 80 + lq * 16;
            CPA16(d,         sH + (long)r * ld + kk0 + lq * 8);
            CPA16(d + ATILE, sL + (long)r * ld + kk0 + lq * 8);
        }
        #pragma unroll
        for (int it = 0; it < NR / 64; it++) {
            int r = lr + it * 64;
            uint32_t d = st + 2 * ATILE + r * 80 + lq * 16;
            CPA16(d,         pWH + (long)r * ldw + lq * 8);
            CPA16(d + WTILE, pWL + (long)r * ldw + lq * 8);
        }
        CP_COMMIT();
    }

    for (int c = 0; c < nch; c++) {
        if (c + 1 < nch) {
            long k0 = (long)(c + 1) << 5;
            const bf* sH = pAH; const bf* sL = pAL; long kk0 = k0; long ld = lda;
            if (k0 >= K1) { sH = pA2H; sL = pA2L; kk0 = k0 - K1; ld = lda2; }
            uint32_t st = sbase + ((c + 1) & 1) * STAGE;
            #pragma unroll
            for (int it = 0; it < MR / 64; it++) {
                int r = lr + it * 64;
                uint32_t d = st + r * 80 + lq * 16;
                CPA16(d,         sH + (long)r * ld + kk0 + lq * 8);
                CPA16(d + ATILE, sL + (long)r * ld + kk0 + lq * 8);
            }
            #pragma unroll
            for (int it = 0; it < NR / 64; it++) {
                int r = lr + it * 64;
                uint32_t d = st + 2 * ATILE + r * 80 + lq * 16;
                CPA16(d,         pWH + (long)r * ldw + k0 + lq * 8);
                CPA16(d + WTILE, pWL + (long)r * ldw + k0 + lq * 8);
            }
            CP_COMMIT();
            CP_WAIT1();
        } else {
            CP_WAIT0();
        }
        __syncthreads();

        uint32_t stA = sbase + (c & 1) * STAGE;
        uint32_t aA = stA + aoff;
        uint32_t bA = stA + 2 * ATILE + boff;

        #pragma unroll
        for (int ks = 0; ks < 2; ks++) {
            int kbB = ks * 32;
            uint32_t ah[MT][4], al[MT][4];
            #pragma unroll
            for (int mt = 0; mt < MT; mt++) {
                uint32_t a0 = aA + mt * (16 * 80) + kbB;
                LDSM4(ah[mt][0], ah[mt][1], ah[mt][2], ah[mt][3], a0);
                LDSM4(al[mt][0], al[mt][1], al[mt][2], al[mt][3], a0 + ATILE);
            }
            uint32_t bh[NT][2], bl[NT][2];
            #pragma unroll
            for (int np2 = 0; np2 < NBL; np2++) {
                uint32_t b0 = bA + np2 * (16 * 80) + kbB;
                LDSM4(bh[np2*2][0], bh[np2*2][1], bh[np2*2+1][0], bh[np2*2+1][1], b0);
                LDSM4(bl[np2*2][0], bl[np2*2][1], bl[np2*2+1][0], bl[np2*2+1][1], b0 + WTILE);
            }
            #pragma unroll
            for (int mt = 0; mt < MT; mt++)
                #pragma unroll
                for (int nt = 0; nt < NT; nt++) {
                    MMA16816(acc[mt][nt], ah[mt], bh[nt]);
                    MMA16816(acc[mt][nt], ah[mt], bl[nt]);
                    MMA16816(acc[mt][nt], al[mt], bh[nt]);
                }
        }
        __syncthreads();
    }

    float csum[NT][2], csq[NT][2];
    if (EPI == 2) {
        #pragma unroll
        for (int nt = 0; nt < NT; nt++) {
            csum[nt][0] = 0.f; csum[nt][1] = 0.f;
            csq[nt][0] = 0.f;  csq[nt][1] = 0.f;
        }
    }

    #pragma unroll
    for (int mt = 0; mt < MT; mt++) {
        long row = m0 + wm + mt * 16 + g;
        #pragma unroll
        for (int nt = 0; nt < NT; nt++) {
            int col = n0 + wn + nt * 8 + tg * 2;
            float b0 = 0.f, b1 = 0.f;
            if (bias) {
                const float* bp = (bias2 && col >= 256) ? (bias2 - 256) : bias;
                b0 = __ldg(&bp[col]); b1 = __ldg(&bp[col + 1]);
            }
            float v0 = acc[mt][nt][0] + b0;
            float v1 = acc[mt][nt][1] + b1;
            float v2 = acc[mt][nt][2] + b0;
            float v3 = acc[mt][nt][3] + b1;
            if (EPI == 1 || EPI == 3) {
                uint32_t lo0, lo1;
                uint32_t hi0 = packsplit(v0, v1, lo0);
                uint32_t hi1 = packsplit(v2, v3, lo1);
                *(uint32_t*)(OH + row * (long)ldc + col)       = hi0;
                *(uint32_t*)(OL + row * (long)ldc + col)       = lo0;
                *(uint32_t*)(OH + (row + 8) * (long)ldc + col) = hi1;
                *(uint32_t*)(OL + (row + 8) * (long)ldc + col) = lo1;
            }
            if (EPI != 1) {
                *(float2*)(C + row * (long)ldc + col)       = make_float2(v0, v1);
                *(float2*)(C + (row + 8) * (long)ldc + col) = make_float2(v2, v3);
                if (EPI == 2) {
                    csum[nt][0] += v0 + v2; csq[nt][0] += v0 * v0 + v2 * v2;
                    csum[nt][1] += v1 + v3; csq[nt][1] += v1 * v1 + v3 * v3;
                }
            }
        }
    }

    if (EPI == 2) {
        int inst = (int)(m0 / NP);
        float* sb = gsum + inst * 1024;
        float* qb = gsq  + inst * 1024;
        #pragma unroll
        for (int nt = 0; nt < NT; nt++) {
            #pragma unroll
            for (int j = 0; j < 2; j++) {
                float s = csum[nt][j], q = csq[nt][j];
                s += __shfl_xor_sync(0xffffffffu, s, 4);
                s += __shfl_xor_sync(0xffffffffu, s, 8);
                s += __shfl_xor_sync(0xffffffffu, s, 16);
                q += __shfl_xor_sync(0xffffffffu, q, 4);
                q += __shfl_xor_sync(0xffffffffu, q, 8);
                q += __shfl_xor_sync(0xffffffffu, q, 16);
                if (g == 0) {
                    int col = n0 + wn + nt * 8 + tg * 2 + j;
                    atomicAdd(&sb[col], s);
                    atomicAdd(&qb[col], q);
                }
            }
        }
    }
}

#define SM_128_128 (2 * 2 * (128*80 + 128*80))
#define SM_64_128  (2 * 2 * (64*80  + 128*80))
#define SM_64_64   (2 * 2 * (64*80  + 64*80))

// ======================= fused flash attention (split-KV) =======================
#define FQ_B (128*144)
#define FK_B (64*144)
#define FA_SMEM (2*FQ_B + 4*FK_B)
__global__ void __launch_bounds__(256) k_flash(
    const bf* __restrict__ QH, const bf* __restrict__ QL,
    const bf* __restrict__ KVH, const bf* __restrict__ KVL,
    const bf* __restrict__ VH, const bf* __restrict__ VL,
    float* __restrict__ OP, float* __restrict__ ML)
{
    extern __shared__ __align__(16) char smem[];
    char* sQh = smem;
    char* sQl = smem + FQ_B;
    char* sKh = smem + 2 * FQ_B;
    char* sVh = sKh + 2 * FK_B;
    uint32_t sbase = (uint32_t)__cvta_generic_to_shared(smem);

    int tid = threadIdx.x, wid = tid >> 5, lane = tid & 31;
    int g = lane >> 2, tg = lane & 3;
    int z = blockIdx.y;
    int b = z >> 2, h = z & 3;
    long q0 = (long)blockIdx.x * 128;
    int wm = wid * 16;
    int part = blockIdx.z;
    int c0 = part * (NP / 128);
    int c1 = c0 + (NP / 128);

    uint32_t aoff = (uint32_t)((wm + (lane & 7) + ((lane >> 3) & 1) * 8) * 144 + (lane >> 4) * 16);
    uint32_t boff = (uint32_t)(((lane >> 4) * 8 + (lane & 7)) * 144 + ((lane >> 3) & 1) * 16);
    uint32_t qA = sbase + aoff;
    uint32_t kA = sbase + 2 * FQ_B + boff;
    uint32_t vA = kA + 2 * FK_B;

    const bf* pQH = QH + ((long)b * NP + q0) * 256 + h * 64;
    const bf* pQL = QL + ((long)b * NP + q0) * 256 + h * 64;

    #pragma unroll
    for (int it = 0; it < 4; it++) {
        int i = tid + it * 256;
        int r = i >> 3, q = i & 7;
        *(uint4*)(sQh + r * 144 + q * 16) = *(const uint4*)(pQH + (long)r * 256 + q * 8);
        *(uint4*)(sQl + r * 144 + q * 16) = *(const uint4*)(pQL + (long)r * 256 + q * 8);
    }

    float m0 = -3.4e38f, m1 = -3.4e38f, l0 = 0.f, l1 = 0.f;
    float acc[8][4];
    #pragma unroll
    for (int nt = 0; nt < 8; nt++)
        #pragma unroll
        for (int q = 0; q < 4; q++) acc[nt][q] = 0.f;

    for (int c = c0; c < c1; c++) {
        const bf* pKH = KVH + ((long)b * NP + c * 64) * 512 + h * 64;
        const bf* pKL = KVL + ((long)b * NP + c * 64) * 512 + h * 64;
        const bf* pVH = VH + (long)z * 64 * NP + c * 64;
        const bf* pVL = VL + (long)z * 64 * NP + c * 64;
        #pragma unroll
        for (int it = 0; it < 2; it++) {
            int i = tid + it * 256;
            int r = i >> 3, q = i & 7;
            *(uint4*)(sKh + r * 144 + q * 16)        = *(const uint4*)(pKH + (long)r * 512 + q * 8);
            *(uint4*)(sKh + FK_B + r * 144 + q * 16) = *(const uint4*)(pKL + (long)r * 512 + q * 8);
            *(uint4*)(sVh + r * 144 + q * 16)        = *(const uint4*)(pVH + (long)r * NP + q * 8);
            *(uint4*)(sVh + FK_B + r * 144 + q * 16) = *(const uint4*)(pVL + (long)r * NP + q * 8);
        }
        __syncthreads();

        float sacc[8][4];
        #pragma unroll
        for (int nt = 0; nt < 8; nt++)
            #pragma unroll
            for (int q = 0; q < 4; q++) sacc[nt][q] = 0.f;
        #pragma unroll
        for (int kk = 0; kk < 4; kk++) {
            int kbB = kk * 32;
            uint32_t aqh[4], aql[4];
            LDSM4(aqh[0], aqh[1], aqh[2], aqh[3], qA + kbB);
            LDSM4(aql[0], aql[1], aql[2], aql[3], qA + FQ_B + kbB);
            #pragma unroll
            for (int np2 = 0; np2 < 4; np2++) {
                uint32_t bh[2][2], bl[2][2];
                uint32_t b0 = kA + np2 * (16 * 144) + kbB;
                LDSM4(bh[0][0], bh[0][1], bh[1][0], bh[1][1], b0);
                LDSM4(bl[0][0], bl[0][1], bl[1][0], bl[1][1], b0 + FK_B);
                #pragma unroll
                for (int j = 0; j < 2; j++) {
                    MMA16816(sacc[np2*2+j], aqh, bh[j]);
                    MMA16816(sacc[np2*2+j], aqh, bl[j]);
                    MMA16816(sacc[np2*2+j], aql, bh[j]);
                }
            }
        }

        float rmax0 = -3.4e38f, rmax1 = -3.4e38f;
        #pragma unroll
        for (int nt = 0; nt < 8; nt++) {
            rmax0 = fmaxf(rmax0, fmaxf(sacc[nt][0], sacc[nt][1]));
            rmax1 = fmaxf(rmax1, fmaxf(sacc[nt][2], sacc[nt][3]));
        }
        rmax0 = fmaxf(rmax0, __shfl_xor_sync(0xffffffffu, rmax0, 1));
        rmax0 = fmaxf(rmax0, __shfl_xor_sync(0xffffffffu, rmax0, 2));
        rmax1 = fmaxf(rmax1, __shfl_xor_sync(0xffffffffu, rmax1, 1));
        rmax1 = fmaxf(rmax1, __shfl_xor_sync(0xffffffffu, rmax1, 2));
        float mn0 = fmaxf(m0, rmax0), mn1 = fmaxf(m1, rmax1);
        float al0 = __expf(m0 - mn0), al1 = __expf(m1 - mn1);
        m0 = mn0; m1 = mn1;

        float rs0 = 0.f, rs1 = 0.f;
        uint32_t pfh[4][4], pfl[4][4];
        #pragma unroll
        for (int nt = 0; nt < 8; nt++) {
            float p0 = __expf(sacc[nt][0] - mn0);
            float p1 = __expf(sacc[nt][1] - mn0);
            float p2 = __expf(sacc[nt][2] - mn1);
            float p3 = __expf(sacc[nt][3] - mn1);
            rs0 += p0 + p1; rs1 += p2 + p3;
            int kk = nt >> 1, base = (nt & 1) * 2;
            pfh[kk][base]     = packsplit(p0, p1, pfl[kk][base]);
            pfh[kk][base + 1] = packsplit(p2, p3, pfl[kk][base + 1]);
        }
        rs0 += __shfl_xor_sync(0xffffffffu, rs0, 1);
        rs0 += __shfl_xor_sync(0xffffffffu, rs0, 2);
        rs1 += __shfl_xor_sync(0xffffffffu, rs1, 1);
        rs1 += __shfl_xor_sync(0xffffffffu, rs1, 2);
        l0 = l0 * al0 + rs0; l1 = l1 * al1 + rs1;
        #pragma unroll
        for (int nt = 0; nt < 8; nt++) {
            acc[nt][0] *= al0; acc[nt][1] *= al0;
            acc[nt][2] *= al1; acc[nt][3] *= al1;
        }

        #pragma unroll
        for (int kk = 0; kk < 4; kk++) {
            int kbB = kk * 32;
            #pragma unroll
            for (int np2 = 0; np2 < 4; np2++) {
                uint32_t bh[2][2], bl[2][2];
                uint32_t b0 = vA + np2 * (16 * 144) + kbB;
                LDSM4(bh[0][0], bh[0][1], bh[1][0], bh[1][1], b0);
                LDSM4(bl[0][0], bl[0][1], bl[1][0], bl[1][1], b0 + FK_B);
                #pragma unroll
                for (int j = 0; j < 2; j++) {
                    MMA16816(acc[np2*2+j], pfh[kk], bh[j]);
                    MMA16816(acc[np2*2+j], pfh[kk], bl[j]);
                    MMA16816(acc[np2*2+j], pfl[kk], bh[j]);
                }
            }
        }
        __syncthreads();
    }

    long rbase = ((long)part * 8 + z) * NP + q0 + wm;
    float* pO = OP + rbase * 64;
    #pragma unroll
    for (int nt = 0; nt < 8; nt++) {
        int col = nt * 8 + tg * 2;
        *(float2*)(pO + (long)g * 64 + col)       = make_float2(acc[nt][0], acc[nt][1]);
        *(float2*)(pO + (long)(g + 8) * 64 + col) = make_float2(acc[nt][2], acc[nt][3]);
    }
    if (tg == 0) {
        ML[(rbase + g) * 2]         = m0;
        ML[(rbase + g) * 2 + 1]     = l0;
        ML[(rbase + g + 8) * 2]     = m1;
        ML[(rbase + g + 8) * 2 + 1] = l1;
    }
}

// merge two KV-half partials -> bf16 hi/lo (Wo-input layout)
__global__ void __launch_bounds__(256) k_fmerge(
    const float* __restrict__ OP, const float* __restrict__ ML,
    bf* __restrict__ OH, bf* __restrict__ OL)
{
    long i = (long)blockIdx.x * blockDim.x + threadIdx.x;
    if (i >= (long)8 * NP * 32) return;
    int  c2 = (int)(i & 31) * 2;
    long zn = i >> 5;
    int  n  = (int)(zn & (NP - 1));
    int  z  = (int)(zn >> 11);
    float m0 = ML[zn * 2],                     l0 = ML[zn * 2 + 1];
    float m1 = ML[((long)8 * NP + zn) * 2],    l1 = ML[((long)8 * NP + zn) * 2 + 1];
    float m  = fmaxf(m0, m1);
    float a0 = __expf(m0 - m), a1 = __expf(m1 - m);
    float inv = 1.f / (l0 * a0 + l1 * a1);
    long o0 = zn * 64 + c2;
    float2 v0 = *(const float2*)(OP + o0);
    float2 v1 = *(const float2*)(OP + (long)8 * NP * 64 + o0);
    float x = (v0.x * a0 + v1.x * a1) * inv;
    float y = (v0.y * a0 + v1.y * a1) * inv;
    uint32_t lo;
    uint32_t hi = packsplit(x, y, lo);
    int b = z >> 2, h = z & 3;
    long od = ((long)b * NP + n) * 256 + h * 64 + c2;
    *(uint32_t*)(OH + od) = hi;
    *(uint32_t*)(OL + od) = lo;
}

// ======================= fp32 -> bf16 hi/lo =======================
__global__ void k_cvt(const float* __restrict__ src, long ldi, int cols, long total,
                      bf* __restrict__ H, bf* __restrict__ L, long ldo)
{
    long i = ((long)blockIdx.x * blockDim.x + threadIdx.x) * 4;
    if (i >= total) return;
    long r = i / cols; int c = (int)(i - r * cols);
    float4 v = *(const float4*)(src + r * ldi + c);
    uint32_t lo0, lo1;
    uint32_t hi0 = packsplit(v.x, v.y, lo0);
    uint32_t hi1 = packsplit(v.z, v.w, lo1);
    *(uint2*)(H + r * ldo + c) = make_uint2(hi0, hi1);
    *(uint2*)(L + r * ldo + c) = make_uint2(lo0, lo1);
}

__global__ void k_prepw_b(const float* __restrict__ W, bf* __restrict__ H,
                          bf* __restrict__ L, int O, int Ci)
{
    long i = blockIdx.x * (long)blockDim.x + threadIdx.x;
    if (i >= (long)O * Ci) return;
    int o = (int)(i / Ci), c = (int)(i % Ci);
    float a  = W[(long)o * 2 * Ci + c];
    float bq = W[(long)o * 2 * Ci + Ci + c];
    bf h, l;
    split2(a - bq, h, l);
    H[(long)o * Ci + c] = h; L[(long)o * Ci + c] = l;
    split2(bq, h, l);
    H[((long)O + o) * Ci + c] = h; L[((long)O + o) * Ci + c] = l;
}

__global__ void k_prepw_perm(const float* __restrict__ W, float scale,
                             bf* __restrict__ H, bf* __restrict__ L, int roff,
                             const float* __restrict__ bin, float* __restrict__ bout)
{
    int i = blockIdx.x * blockDim.x + threadIdx.x;
    if (i >= 256 * 256) return;
    int o = i >> 8, c = i & 255;
    int op = (o & 3) * 64 + (o >> 2);
    bf h, l;
    split2(W[i] * scale, h, l);
    H[(long)(roff + op) * 256 + c] = h;
    L[(long)(roff + op) * 256 + c] = l;
    if (c == 0) bout[op] = bin[o] * scale;
}

__global__ void k_prepw_colperm(const float* __restrict__ W,
                                bf* __restrict__ H, bf* __restrict__ L)
{
    int i = blockIdx.x * blockDim.x + threadIdx.x;
    if (i >= 256 * 256) return;
    int o = i >> 8, oc = i & 255;
    int c = (oc & 63) * 4 + (oc >> 6);
    bf h, l;
    split2(W[o * 256 + c], h, l);
    H[i] = h; L[i] = l;
}

__global__ void k_vtrans(const bf* __restrict__ SH, const bf* __restrict__ SL,
                         bf* __restrict__ DH, bf* __restrict__ DL)
{
    __shared__ uint16_t th[32][34], tl[32][34];
    int b = blockIdx.z;
    int hc0 = blockIdx.x * 32;
    int n0  = blockIdx.y * 32;
    int tx = threadIdx.x, ty = threadIdx.y;
    for (int i = ty; i < 32; i += 8) {
        long src = ((long)b * NP + n0 + i) * 512 + 256 + hc0 + tx;
        th[i][tx] = ((const uint16_t*)SH)[src];
        tl[i][tx] = ((const uint16_t*)SL)[src];
    }
    __syncthreads();
    for (int i = ty; i < 32; i += 8) {
        int hc = hc0 + i;
        int h = hc >> 6, dd = hc & 63;
        long dst = (((long)b * 4 + h) * 64 + dd) * NP + n0 + tx;
        ((uint16_t*)DH)[dst] = th[tx][i];
        ((uint16_t*)DL)[dst] = tl[tx][i];
    }
}

// ======================= edge gather: max + stats =======================
__global__ void __launch_bounds__(256) k_edge(const float* __restrict__ PQ,
                                              const int* __restrict__ knn,
                                              float* __restrict__ mx,
                                              float* __restrict__ ssum,
                                              float* __restrict__ sssq,
                                              int Co)
{
    __shared__ long nbb[KNB];
    long bn = blockIdx.x;
    int  inst = (int)(bn / NP);
    if (threadIdx.x < KNB) {
        int nb = knn[bn * KNB + threadIdx.x];
        nbb[threadIdx.x] = ((long)inst * NP + nb) * (2 * Co) + Co;
    }
    __syncthreads();
    const float* Prow = PQ + bn * (2 * Co);
    for (int o = threadIdx.x; o < Co; o += 256) {
        float p = Prow[o];
        float mv = -3.4e38f, s = 0.f, ss = 0.f;
        #pragma unroll
        for (int k2 = 0; k2 < KNB; k2++) {
            float v = p + PQ[nbb[k2] + o];
            mv = fmaxf(mv, v); s += v; ss += v * v;
        }
        mx[bn * Co + o] = mv;
        atomicAdd(&ssum[inst * 1024 + o], s);
        atomicAdd(&sssq[inst * 1024 + o], ss);
    }
}

// ======================= normalize + act -> fp32 + split ==========
__global__ void k_norm_act_both(const float* __restrict__ X, int ldx,
                                float* __restrict__ Y, int ldy,
                                bf* __restrict__ H, bf* __restrict__ L,
                                const float* __restrict__ ssum,
                                const float* __restrict__ sssq,
                                int Co, long rows, float invcnt, int act)
{
    long i = blockIdx.x * (long)blockDim.x + threadIdx.x;
    if (i >= rows * Co) return;
    int  o  = (int)(i % Co);
    long rn = i / Co;
    int  inst = (int)(rn / NP);
    float mu  = ssum[inst * 1024 + o] * invcnt;
    float var = sssq[inst * 1024 + o] * invcnt - mu * mu;
    float v = (X[rn * ldx + o] - mu) * rsqrtf(var + EPSI);
    if (act == 1) v = (v >= 0.f) ? v : 0.2f * v;
    else          v = (v > 0.f)  ? v : 0.f;
    Y[rn * ldy + o] = v;
    bf h, l;
    split2(v, h, l);
    H[rn * (long)Co + o] = h;
    L[rn * (long)Co + o] = l;
}

// ======================= normalize + act -> bf16 hi/lo =======================
__global__ void k_norm_act_split(const float* __restrict__ X, int ldx,
                                 bf* __restrict__ H, bf* __restrict__ L,
                                 int ldy, int offy,
                                 const float* __restrict__ ssum,
                                 const float* __restrict__ sssq,
                                 int Co, long rows, float invcnt, int act)
{
    long i = blockIdx.x * (long)blockDim.x + threadIdx.x;
    if (i >= rows * Co) return;
    int  o  = (int)(i % Co);
    long rn = i / Co;
    int  inst = (int)(rn / NP);
    float mu  = ssum[inst * 1024 + o] * invcnt;
    float var = sssq[inst * 1024 + o] * invcnt - mu * mu;
    float v = (X[rn * ldx + o] - mu) * rsqrtf(var + EPSI);
    if (act == 1) v = (v >= 0.f) ? v : 0.2f * v;
    else          v = (v > 0.f)  ? v : 0.f;
    bf h, l;
    split2(v, h, l);
    H[rn * ldy + offy + o] = h;
    L[rn * ldy + offy + o] = l;
}

// ======================= host =======================
template <int EPI>
static void gemm_any(const bf* AH, const bf* AL,
                     const bf* A2H, const bf* A2L, int K1, long lda, long lda2,
                     const bf* WH, const bf* WL, long ldw,
                     const float* bias, const float* bias2,
                     float* C, bf* OH, bf* OL,
                     float* gsum, float* gsq, int ldc,
                     int M, int Nout, int K)
{
    long ctas = (long)(M / 128) * (Nout / 128);
    if (ctas >= 200) {
        dim3 g(Nout / 128, M / 128);
        mma_gemm<EPI, 128, 128><<<g, 256, SM_128_128>>>(AH, AL, A2H, A2L, K1, lda, lda2,
            WH, WL, ldw, bias, bias2, C, OH, OL, gsum, gsq, ldc, K);
    } else if (ctas * 2 >= 200) {
        dim3 g(Nout / 128, M / 64);
        mma_gemm<EPI, 64, 128><<<g, 256, SM_64_128>>>(AH, AL, A2H, A2L, K1, lda, lda2,
            WH, WL, ldw, bias, bias2, C, OH, OL, gsum, gsq, ldc, K);
    } else {
        dim3 g(Nout / 64, M / 64);
        mma_gemm<EPI, 64, 64><<<g, 256, SM_64_64>>>(AH, AL, A2H, A2L, K1, lda, lda2,
            WH, WL, ldw, bias, bias2, C, OH, OL, gsum, gsq, ldc, K);
    }
}
static void gemm_f(const bf* AH, const bf* AL, long lda,
                   const bf* WH, const bf* WL, long ldw,
                   const float* bias, float* C, int ldc, int M, int Nout, int K)
{
    gemm_any<0>(AH, AL, nullptr, nullptr, 1 << 30, lda, lda, WH, WL, ldw, bias, nullptr,
                C, nullptr, nullptr, nullptr, nullptr, ldc, M, Nout, K);
}
static void gemm_dual_fs(const bf* AH, const bf* AL,
                         const bf* A2H, const bf* A2L, int K1, long lda, long lda2,
                         const bf* WH, const bf* WL, long ldw,
                         const float* bias, float* C, float* gsum, float* gsq,
                         int ldc, int M, int Nout, int K)
{
    gemm_any<2>(AH, AL, A2H, A2L, K1, lda, lda2, WH, WL, ldw, bias, nullptr,
                C, nullptr, nullptr, gsum, gsq, ldc, M, Nout, K);
}
static void gemm_s(const bf* AH, const bf* AL, long lda,
                   const bf* WH, const bf* WL, long ldw,
                   const float* bias, const float* bias2,
                   bf* OH, bf* OL, int ldc, int M, int Nout, int K)
{
    gemm_any<1>(AH, AL, nullptr, nullptr, 1 << 30, lda, lda, WH, WL, ldw, bias, bias2,
                nullptr, OH, OL, nullptr, nullptr, ldc, M, Nout, K);
}
static void gemm_b(const bf* AH, const bf* AL, long lda,
                   const bf* WH, const bf* WL, long ldw,
                   const float* bias, float* C, bf* OH, bf* OL,
                   int ldc, int M, int Nout, int K)
{
    gemm_any<3>(AH, AL, nullptr, nullptr, 1 << 30, lda, lda, WH, WL, ldw, bias, nullptr,
                C, OH, OL, nullptr, nullptr, ldc, M, Nout, K);
}

#define GSA(sym, var, type) cudaGetSymbolAddress(&pv, sym); type* var = (type*)pv
#define CVTS(st, src, ldi, cols, total, H, L, ldo) \
    k_cvt<<<(int)(((total) / 4 + 255) / 256), 256, 0, st>>>(src, ldi, cols, total, H, L, ldo)

extern "C" void kernel_launch(void* const* d_in, const int* in_sizes, int n_in,
                              void* d_out, int out_size)
{
    const float* coords1 = (const float*)d_in[0];
    const float* coords2 = (const float*)d_in[2];
    const float* feats1  = (const float*)d_in[1];
    const float* feats2  = (const float*)d_in[3];
    const float* gW1 = (const float*)d_in[4];
    const float* gW2 = (const float*)d_in[5];
    const float* gW3 = (const float*)d_in[6];
    const float* Wq  = (const float*)d_in[7];  const float* bq  = (const float*)d_in[8];
    const float* Wk  = (const float*)d_in[9];  const float* bk  = (const float*)d_in[10];
    const float* Wv  = (const float*)d_in[11]; const float* bv  = (const float*)d_in[12];
    const float* Wo  = (const float*)d_in[13]; const float* bo  = (const float*)d_in[14];
    const float* Wm1 = (const float*)d_in[15]; const float* bm1 = (const float*)d_in[16];
    const float* Wm2 = (const float*)d_in[17]; const float* bm2 = (const float*)d_in[18];
    float* out = (float*)d_out;

    static int attr_set = 0;
    static cudaStream_t s2 = 0, s3 = 0, s4 = 0;
    static cudaEvent_t evf = 0, evk2 = 0, evk3 = 0, evG[2] = {0,0}, evA[2] = {0,0};
    if (!attr_set) {
        cudaFuncSetAttribute(mma_gemm<0,128,128>, cudaFuncAttributeMaxDynamicSharedMemorySize, SM_128_128);
        cudaFuncSetAttribute(mma_gemm<1,128,128>, cudaFuncAttributeMaxDynamicSharedMemorySize, SM_128_128);
        cudaFuncSetAttribute(mma_gemm<2,128,128>, cudaFuncAttributeMaxDynamicSharedMemorySize, SM_128_128);
        cudaFuncSetAttribute(mma_gemm<3,128,128>, cudaFuncAttributeMaxDynamicSharedMemorySize, SM_128_128);
        cudaFuncSetAttribute(mma_gemm<0,64,128>,  cudaFuncAttributeMaxDynamicSharedMemorySize, SM_64_128);
        cudaFuncSetAttribute(mma_gemm<1,64,128>,  cudaFuncAttributeMaxDynamicSharedMemorySize, SM_64_128);
        cudaFuncSetAttribute(mma_gemm<2,64,128>,  cudaFuncAttributeMaxDynamicSharedMemorySize, SM_64_128);
        cudaFuncSetAttribute(mma_gemm<3,64,128>,  cudaFuncAttributeMaxDynamicSharedMemorySize, SM_64_128);
        cudaFuncSetAttribute(mma_gemm<0,64,64>,   cudaFuncAttributeMaxDynamicSharedMemorySize, SM_64_64);
        cudaFuncSetAttribute(mma_gemm<1,64,64>,   cudaFuncAttributeMaxDynamicSharedMemorySize, SM_64_64);
        cudaFuncSetAttribute(mma_gemm<2,64,64>,   cudaFuncAttributeMaxDynamicSharedMemorySize, SM_64_64);
        cudaFuncSetAttribute(mma_gemm<3,64,64>,   cudaFuncAttributeMaxDynamicSharedMemorySize, SM_64_64);
        cudaFuncSetAttribute(k_flash, cudaFuncAttributeMaxDynamicSharedMemorySize, FA_SMEM);
        cudaStreamCreateWithFlags(&s2, cudaStreamNonBlocking);
        cudaStreamCreateWithFlags(&s3, cudaStreamNonBlocking);
        cudaStreamCreateWithFlags(&s4, cudaStreamNonBlocking);
        cudaEventCreateWithFlags(&evf, cudaEventDisableTiming);
        cudaEventCreateWithFlags(&evk2, cudaEventDisableTiming);
        cudaEventCreateWithFlags(&evk3, cudaEventDisableTiming);
        cudaEventCreateWithFlags(&evG[0], cudaEventDisableTiming);
        cudaEventCreateWithFlags(&evG[1], cudaEventDisableTiming);
        cudaEventCreateWithFlags(&evA[0], cudaEventDisableTiming);
        cudaEventCreateWithFlags(&evA[1], cudaEventDisableTiming);
        attr_set = 1;
    }

    void* pv;
    GSA(d_FE,  FEb, float);
    GSA(d_KN,  KNb, int);
    GSA(d_PQ,  PQp, float);
    GSA(d_MX,  MXp, float);
    GSA(d_STT, STp, float);
    GSA(d_BIAS, BP, float);
    GSA(d_OP,  OPp, float);
    GSA(d_ML,  MLp, float);
    GSA(d_AH,  AH, bf);    GSA(d_AL,  AL, bf);
    GSA(d_FSH, FSH, bf);   GSA(d_FSL, FSL, bf);
    GSA(d_W1H, W1H, bf);   GSA(d_W1L, W1L, bf);
    GSA(d_W2H, W2H, bf);   GSA(d_W2L, W2L, bf);
    GSA(d_W3H, W3H, bf);   GSA(d_W3L, W3L, bf);
    GSA(d_WQH, WQH, bf);   GSA(d_WQL, WQL, bf);
    GSA(d_WKVH, WKVH, bf); GSA(d_WKVL, WKVL, bf);
    GSA(d_WOH, WOH, bf);   GSA(d_WOL, WOL, bf);
    GSA(d_WM1H, WM1H, bf); GSA(d_WM1L, WM1L, bf);
    GSA(d_WM2H, WM2H, bf); GSA(d_WM2L, WM2L, bf);
    GSA(d_QHH, QHH, bf);   GSA(d_QHL, QHL, bf);
    GSA(d_KVH, KVH, bf);   GSA(d_KVL, KVL, bf);
    GSA(d_VTH, VTH, bf);   GSA(d_VTL, VTL, bf);
    GSA(d_OHH, OHH, bf);   GSA(d_OHL, OHL, bf);
    float* FE[2] = { FEb, FEb + (long)M4 * 256 };
    bf* AOH = AH;                   bf* AOL = AL;
    bf* HH  = AH + (long)M4 * 256;  bf* HL  = AL + (long)M4 * 256;

    #define SUMS(k) (STp + (k) * 8192)
    #define SSQS(k) (STp + (k) * 8192 + 4096)

    const int EWB = 256;
    dim3 tb(32, 8);

    // one upfront memset of all 10 stat slots (replay-safe: inside the graph)
    cudaMemsetAsync(STp, 0, sizeof(float) * 10 * 8 * 1024, 0);

    cudaEventRecord(evf, 0);
    cudaStreamWaitEvent(s2, evf, 0);
    cudaStreamWaitEvent(s3, evf, 0);
    cudaStreamWaitEvent(s4, evf, 0);
    k_knn<<<BB * NP, 256, 0, s3>>>(coords1, KNb);
    k_knn<<<BB * NP, 256, 0, s4>>>(coords2, KNb + (long)M4 * KNB);
    cudaEventRecord(evk2, s3);
    cudaEventRecord(evk3, s4);

    for (int i = 0; i < 2; i++) {
        long o1 = (long)i * 512 * 256, o2 = (long)i * 1024 * 256, o3 = (long)i * 256 * 1024;
        k_prepw_b<<<(256 * 256 + 255) / 256, 256, 0, s2>>>(gW1 + (long)i * 256 * 512,
                                                           W1H + o1, W1L + o1, 256, 256);
        k_prepw_b<<<(512 * 256 + 255) / 256, 256, 0, s2>>>(gW2 + (long)i * 512 * 512,
                                                           W2H + o2, W2L + o2, 512, 256);
        CVTS(s2, gW3 + (long)i * 256 * 1024, 1024, 1024, (long)256 * 1024,
             W3H + o3, W3L + o3, 1024);
        cudaEventRecord(evG[i], s2);
    }
    for (int i = 0; i < 2; i++) {
        long oq = (long)i * 65536, okv = (long)i * 512 * 256;
        long om1 = (long)i * 262144, om2 = (long)i * 131072;
        float* BQP = BP + i * 768;
        float* BKP = BQP + 256;
        float* BVP = BQP + 512;
        k_prepw_perm<<<256, 256, 0, s2>>>(Wq + oq, 0.125f, WQH + oq, WQL + oq, 0,
                                          bq + (long)i * 256, BQP);
        k_prepw_perm<<<256, 256, 0, s2>>>(Wk + oq, 1.f, WKVH + okv, WKVL + okv, 0,
                                          bk + (long)i * 256, BKP);
        k_prepw_perm<<<256, 256, 0, s2>>>(Wv + oq, 1.f, WKVH + okv, WKVL + okv, 256,
                                          bv + (long)i * 256, BVP);
        k_prepw_colperm<<<256, 256, 0, s2>>>(Wo + oq, WOH + oq, WOL + oq);
        CVTS(s2, Wm1 + om1, 512, 512, (long)262144, WM1H + om1, WM1L + om1, 512);
        CVTS(s2, Wm2 + om2, 512, 512, (long)131072, WM2H + om2, WM2L + om2, 512);
        cudaEventRecord(evA[i], s2);
    }

    // input transposes emit fp32 FE + split FSH/FSL
    k_transpose<<<dim3(NP / 32, 256 / 32, BB), tb>>>(feats1, FE[0], 256, NP, FSH, FSL);
    k_transpose<<<dim3(NP / 32, 256 / 32, BB), tb>>>(feats2, FE[1], 256, NP,
                                                     FSH + (long)M4 * 256, FSL + (long)M4 * 256);

    const long R8 = M8, R4 = M4;
    int joined = 0;

    for (int li = 0; li < 4; li++) {
        int i = li / 2;
        if ((li & 1) == 0) {
            // ---------------- GCN layer i (both clouds batched) ----------------
            long o1 = (long)i * 512 * 256, o2 = (long)i * 1024 * 256, o3 = (long)i * 256 * 1024;
            int s0 = i * 3;
            cudaStreamWaitEvent(0, evG[i], 0);
            gemm_f(FSH, FSL, 256, W1H + o1, W1L + o1, 256, nullptr, PQp, 512, (int)R8, 512, 256);
            if (!joined) {
                cudaStreamWaitEvent(0, evk2, 0);
                cudaStreamWaitEvent(0, evk3, 0);
                joined = 1;
            }
            k_edge<<<(int)R8, 256>>>(PQp, KNb, MXp, SUMS(s0), SSQS(s0), 256);
            k_norm_act_split<<<(int)((R8 * 256 + EWB - 1) / EWB), EWB>>>(
                MXp, 256, AH, AL, 1024, 256, SUMS(s0), SSQS(s0), 256, R8, 1.f / 32768.f, 1);
            gemm_f(AH + 256, AL + 256, 1024, W2H + o2, W2L + o2, 256, nullptr,
                   PQp, 1024, (int)R8, 1024, 256);
            k_edge<<<(int)R8, 256>>>(PQp, KNb, MXp, SUMS(s0 + 1), SSQS(s0 + 1), 512);
            k_norm_act_split<<<(int)((R8 * 512 + EWB - 1) / EWB), EWB>>>(
                MXp, 512, AH, AL, 1024, 512, SUMS(s0 + 1), SSQS(s0 + 1), 512, R8, 1.f / 32768.f, 1);
            gemm_dual_fs(FSH, FSL, AH + 256, AL + 256, 256, 256, 1024,
                         W3H + o3, W3L + o3, 1024, nullptr,
                         MXp, SUMS(s0 + 2), SSQS(s0 + 2), 256, (int)R8, 256, 1024);
            k_norm_act_both<<<(int)((R8 * 256 + EWB - 1) / EWB), EWB>>>(
                MXp, 256, FEb, 256, FSH, FSL, SUMS(s0 + 2), SSQS(s0 + 2), 256, R8, 1.f / (float)NP, 1);
        } else {
            // ---------------- cross-attention layer i ----------------
            long oq = (long)i * 65536, okv = (long)i * 512 * 256;
            long om1 = (long)i * 262144, om2 = (long)i * 131072;
            float* BQP = BP + i * 768;
            float* BKP = BQP + 256;
            float* BVP = BQP + 512;
            cudaStreamWaitEvent(0, evA[i], 0);
            for (int a = 0; a < 2; a++) {
                int sl = 6 + i * 2 + a;
                bf* F1SH = FSH + (long)a * M4 * 256;
                bf* F1SL = FSL + (long)a * M4 * 256;
                bf* F2SH = FSH + (long)(1 - a) * M4 * 256;
                bf* F2SL = FSL + (long)(1 - a) * M4 * 256;
                gemm_s(F1SH, F1SL, 256, WQH + oq, WQL + oq, 256, BQP, nullptr,
                       QHH, QHL, 256, (int)R4, 256, 256);
                gemm_s(F2SH, F2SL, 256, WKVH + okv, WKVL + okv, 256, BKP, BVP,
                       KVH, KVL, 512, (int)R4, 512, 256);
                k_vtrans<<<dim3(8, NP / 32, BB), tb>>>(KVH, KVL, VTH, VTL);
                k_flash<<<dim3(16, 8, 2), 256, FA_SMEM>>>(QHH, QHL, KVH, KVL, VTH, VTL, OPp, MLp);
                k_fmerge<<<(int)((8L * NP * 32 + 255) / 256), 256>>>(OPp, MLp, OHH, OHL);
                gemm_s(OHH, OHL, 256, WOH + oq, WOL + oq, 256, bo + (long)i * 256, nullptr,
                       AOH, AOL, 256, (int)R4, 256, 256);
                gemm_dual_fs(F1SH, F1SL, AOH, AOL, 256, 256, 256,
                             WM1H + om1, WM1L + om1, 512, bm1 + (long)i * 512,
                             PQp, SUMS(sl), SSQS(sl), 512, (int)R4, 512, 512);
                k_norm_act_split<<<(int)((R4 * 512 + EWB - 1) / EWB), EWB>>>(
                    PQp, 512, HH, HL, 512, 0, SUMS(sl), SSQS(sl), 512, R4, 1.f / (float)NP, 2);
                gemm_b(HH, HL, 512, WM2H + om2, WM2L + om2, 512, bm2 + (long)i * 256,
                       FE[a], F1SH, F1SL, 256, (int)R4, 256, 512);
            }
        }
    }

    k_transpose<<<dim3(256 / 32, NP / 32, BB), tb>>>(FE[0], out, NP, 256, nullptr, nullptr);
    k_transpose<<<dim3(256 / 32, NP / 32, BB), tb>>>(FE[1], out + (long)M4 * 256, NP, 256,
                                                     nullptr, nullptr);
}